// round 3
// baseline (speedup 1.0000x reference)
#include <cuda_runtime.h>
#include <math.h>

#define BB 64
#define VV 197
#define LL 64
#define DD 768
#define EE 256

// Scratch for projected+normalized tokens (allocation-free rule: __device__ globals)
__device__ __align__(16) float g_vtok[(size_t)BB * VV * EE]; // 12.9 MB
__device__ __align__(16) float g_ttok[(size_t)BB * LL * EE]; //  4.0 MB

// ---------------------------------------------------------------------------
// Generic GEMM: C[M x 256] = A[M x 768] @ W[768 x 256] + bias
// grid = (M/64, 4), block = 256 (16x16), 4x4 per thread, k-chunk 64.
// sA row-major [m][k] (scalar a-reads, only 2 distinct addrs/warp -> broadcast)
// sW k-major   [k][n] (natural layout of W -> conflict-free float4 r/w)
// ---------------------------------------------------------------------------
__global__ __launch_bounds__(256) void gemm_bias_kernel(
    const float* __restrict__ A, const float* __restrict__ W,
    const float* __restrict__ bias, float* __restrict__ C)
{
    __shared__ float sA[64][68];
    __shared__ float sW[64][68];

    const int tid = threadIdx.x;
    const int tx = tid & 15, ty = tid >> 4;
    const int m0 = blockIdx.x * 64, n0 = blockIdx.y * 64;

    float acc[4][4] = {};

    for (int k0 = 0; k0 < DD; k0 += 64) {
        #pragma unroll
        for (int it = 0; it < 4; it++) {
            int idx = tid + it * 256;        // 0..1023
            int rr = idx >> 4;               // row within tile (m or k)
            int cv = idx & 15;               // float4 index within 64
            float4 va = *(const float4*)(A + (size_t)(m0 + rr) * DD + k0 + cv * 4);
            *(float4*)&sA[rr][cv * 4] = va;
            float4 vw = *(const float4*)(W + (size_t)(k0 + rr) * EE + n0 + cv * 4);
            *(float4*)&sW[rr][cv * 4] = vw;
        }
        __syncthreads();

        #pragma unroll 8
        for (int kk = 0; kk < 64; kk++) {
            float4 b4 = *(const float4*)&sW[kk][tx * 4];
            float bvals[4] = {b4.x, b4.y, b4.z, b4.w};
            float avals[4];
            #pragma unroll
            for (int i = 0; i < 4; i++) avals[i] = sA[ty * 4 + i][kk];
            #pragma unroll
            for (int i = 0; i < 4; i++)
                #pragma unroll
                for (int j = 0; j < 4; j++)
                    acc[i][j] = fmaf(avals[i], bvals[j], acc[i][j]);
        }
        __syncthreads();
    }

    float4 bb = *(const float4*)(bias + n0 + tx * 4);
    #pragma unroll
    for (int i = 0; i < 4; i++) {
        float4 o;
        o.x = acc[i][0] + bb.x;
        o.y = acc[i][1] + bb.y;
        o.z = acc[i][2] + bb.z;
        o.w = acc[i][3] + bb.w;
        *(float4*)(C + (size_t)(m0 + ty * 4 + i) * EE + n0 + tx * 4) = o;
    }
}

// ---------------------------------------------------------------------------
// Row L2 normalize, in place. One warp per 256-element row.
// ---------------------------------------------------------------------------
__global__ __launch_bounds__(256) void l2norm_kernel(float* __restrict__ X, int rows)
{
    int gw = (blockIdx.x * blockDim.x + threadIdx.x) >> 5;
    int lane = threadIdx.x & 31;
    if (gw >= rows) return;
    float* row = X + (size_t)gw * EE;

    float4 a = *(float4*)(row + lane * 4);
    float4 c = *(float4*)(row + 128 + lane * 4);
    float s = a.x * a.x + a.y * a.y + a.z * a.z + a.w * a.w
            + c.x * c.x + c.y * c.y + c.z * c.z + c.w * c.w;
    #pragma unroll
    for (int off = 16; off > 0; off >>= 1)
        s += __shfl_xor_sync(0xffffffffu, s, off);

    float inv = 1.0f / fmaxf(sqrtf(s), 1e-12f);
    a.x *= inv; a.y *= inv; a.z *= inv; a.w *= inv;
    c.x *= inv; c.y *= inv; c.z *= inv; c.w *= inv;
    *(float4*)(row + lane * 4) = a;
    *(float4*)(row + 128 + lane * 4) = c;
}

// ---------------------------------------------------------------------------
// Fused sim kernel: one block per (b, q) pair. grid = (q=64, b=64), 256 thr.
//   sim[v][t] = dot(v_tok[b,v,:], t_tok[q,t,:])   (never materialized)
//   i2t[b][q] = (1/V) * sum_v max_t sim
//   t2i[b][q] = (1/len[b]) * sum_{t<len[b]} max_v sim      (mask uses b!)
// sT: k-major [256][64] with XOR-4 swizzle (float4 compute reads; 4-way-
//     conflict scalar writes, one-time). sV: row-major [64][260] streamed.
// ---------------------------------------------------------------------------
__global__ __launch_bounds__(256) void fused_sim_kernel(
    const float* __restrict__ vtok, const float* __restrict__ ttok,
    const int* __restrict__ text_length, float* __restrict__ out)
{
    extern __shared__ float smem[];
    float* sT = smem;               // 256*64 floats, swizzled k-major
    float* sV = smem + 256 * 64;    // 64 rows * 260 stride

    __shared__ float red[16][65];
    __shared__ float t2i_run[64];
    __shared__ float redsc[16];

    const int tid = threadIdx.x;
    const int tx = tid & 15, ty = tid >> 4;
    const int q = blockIdx.x, b = blockIdx.y;

    if (tid < 64) t2i_run[tid] = -1e30f;

    // Load t_tok[q] into swizzled k-major smem: elem (k, t) -> sT[k*64 + (t ^ swz(k))]
    // swz(k) = ((k>>2)&7)<<2  (multiple of 4: preserves float4 blocks)
    const float* tq = ttok + (size_t)q * LL * EE;
    #pragma unroll
    for (int it = 0; it < 16; it++) {
        int idx = tid + it * 256;        // 0..4095
        int r = idx >> 6;                // t row
        int kv = idx & 63;               // float4 index along k
        float4 v = *(const float4*)(tq + (size_t)r * EE + kv * 4);
        int c = r ^ ((kv & 7) << 2);     // k>>2 == kv for all 4 components
        sT[(4 * kv + 0) * 64 + c] = v.x;
        sT[(4 * kv + 1) * 64 + c] = v.y;
        sT[(4 * kv + 2) * 64 + c] = v.z;
        sT[(4 * kv + 3) * 64 + c] = v.w;
    }

    float i2t_acc = 0.0f;
    const float* vb = vtok + (size_t)b * VV * EE;

    for (int v0 = 0; v0 < VV; v0 += 64) {
        // Load v tile (zero-padded past V)
        #pragma unroll
        for (int it = 0; it < 16; it++) {
            int idx = tid + it * 256;
            int r = idx >> 6;
            int kv = idx & 63;
            float4 v;
            if (v0 + r < VV) v = *(const float4*)(vb + (size_t)(v0 + r) * EE + kv * 4);
            else             v = make_float4(0.f, 0.f, 0.f, 0.f);
            *(float4*)&sV[r * 260 + kv * 4] = v;
        }
        __syncthreads();   // also covers sT load / t2i_run init on first iter

        float acc[4][4] = {};
        #pragma unroll 8
        for (int k = 0; k < 256; k++) {
            int s = ((k >> 2) & 7) << 2;
            float4 b4 = *(const float4*)&sT[k * 64 + ((tx * 4) ^ s)];
            float bvals[4] = {b4.x, b4.y, b4.z, b4.w};
            float avals[4];
            #pragma unroll
            for (int i = 0; i < 4; i++) avals[i] = sV[(ty * 4 + i) * 260 + k];
            #pragma unroll
            for (int i = 0; i < 4; i++)
                #pragma unroll
                for (int j = 0; j < 4; j++)
                    acc[i][j] = fmaf(avals[i], bvals[j], acc[i][j]);
        }

        // image->text: per-v-row max over all 64 t (t tile == full L)
        #pragma unroll
        for (int i = 0; i < 4; i++) {
            float m = fmaxf(fmaxf(acc[i][0], acc[i][1]), fmaxf(acc[i][2], acc[i][3]));
            #pragma unroll
            for (int off = 1; off < 16; off <<= 1)
                m = fmaxf(m, __shfl_xor_sync(0xffffffffu, m, off));
            if (tx == 0 && (v0 + ty * 4 + i) < VV) i2t_acc += m;
        }

        // text->image: per-t running max over v (mask invalid v rows)
        #pragma unroll
        for (int j = 0; j < 4; j++) {
            float m = -1e30f;
            #pragma unroll
            for (int i = 0; i < 4; i++)
                if (v0 + ty * 4 + i < VV) m = fmaxf(m, acc[i][j]);
            red[ty][tx * 4 + j] = m;
        }
        __syncthreads();
        if (tid < 64) {
            float m = t2i_run[tid];
            #pragma unroll
            for (int r = 0; r < 16; r++) m = fmaxf(m, red[r][tid]);
            t2i_run[tid] = m;
        }
        __syncthreads();   // red + sV reuse on next iter
    }

    if (tx == 0) redsc[ty] = i2t_acc;
    __syncthreads();
    if (tid == 0) {
        float s = 0.0f;
        #pragma unroll
        for (int r = 0; r < 16; r++) s += redsc[r];
        out[32768 + b * 64 + q] = s / (float)VV;

        int len = text_length[b];           // reference quirk: indexed by b
        float s2 = 0.0f;
        for (int t = 0; t < len && t < LL; t++) s2 += t2i_run[t];
        out[36864 + b * 64 + q] = s2 / fmaxf((float)len, 1e-6f);
    }
}

// ---------------------------------------------------------------------------
extern "C" void kernel_launch(void* const* d_in, const int* in_sizes, int n_in,
                              void* d_out, int out_size)
{
    const float* visual_cls     = (const float*)d_in[0];
    const float* textual_cls    = (const float*)d_in[1];
    const float* visual_tokens  = (const float*)d_in[2];
    const float* textual_tokens = (const float*)d_in[3];
    const int*   text_length    = (const int*)  d_in[4];
    const float* Wv  = (const float*)d_in[5];
    const float* bv  = (const float*)d_in[6];
    const float* Wt  = (const float*)d_in[7];
    const float* bt  = (const float*)d_in[8];
    const float* Wvt = (const float*)d_in[9];
    const float* bvt = (const float*)d_in[10];
    const float* Wtt = (const float*)d_in[11];
    const float* btt = (const float*)d_in[12];
    float* out = (float*)d_out;

    float *vtok = nullptr, *ttok = nullptr;
    cudaGetSymbolAddress((void**)&vtok, g_vtok);
    cudaGetSymbolAddress((void**)&ttok, g_ttok);

    // cls projections -> straight into output
    gemm_bias_kernel<<<dim3(1, 4), 256>>>(visual_cls,  Wv, bv, out);
    gemm_bias_kernel<<<dim3(1, 4), 256>>>(textual_cls, Wt, bt, out + 64 * 256);

    // token projections -> scratch, then l2norm in place
    gemm_bias_kernel<<<dim3(197, 4), 256>>>(visual_tokens,  Wvt, bvt, vtok);
    gemm_bias_kernel<<<dim3(64, 4),  256>>>(textual_tokens, Wtt, btt, ttok);
    l2norm_kernel<<<(BB * VV + 7) / 8, 256>>>(vtok, BB * VV);
    l2norm_kernel<<<(BB * LL + 7) / 8, 256>>>(ttok, BB * LL);

    // fused similarity + reductions
    const size_t smem_bytes = (size_t)(256 * 64 + 64 * 260) * sizeof(float); // 132096
    cudaFuncSetAttribute(fused_sim_kernel,
                         cudaFuncAttributeMaxDynamicSharedMemorySize, (int)smem_bytes);
    fused_sim_kernel<<<dim3(64, 64), 256, smem_bytes>>>(vtok, ttok, text_length, out);
}

// round 4
// speedup vs baseline: 3.5988x; 3.5988x over previous
#include <cuda_runtime.h>
#include <math.h>

#define BB 64
#define VV 197
#define LL 64
#define DD 768
#define EE 256

// Scratch for projected+normalized tokens
__device__ __align__(16) float g_vtok[(size_t)BB * VV * EE]; // 12.9 MB
__device__ __align__(16) float g_ttok[(size_t)BB * LL * EE]; //  4.0 MB

// ---------------------------------------------------------------------------
// helpers
// ---------------------------------------------------------------------------
__device__ __forceinline__ float tf32r(float x) {
    unsigned u;
    asm("cvt.rna.tf32.f32 %0, %1;" : "=r"(u) : "f"(x));
    return __uint_as_float(u);
}

__device__ __forceinline__ void mma8(float* c, float a0, float a1, float a2, float a3,
                                     float b0, float b1) {
    asm volatile(
        "mma.sync.aligned.m16n8k8.row.col.f32.tf32.tf32.f32 "
        "{%0,%1,%2,%3},{%4,%5,%6,%7},{%8,%9},{%0,%1,%2,%3};\n"
        : "+f"(c[0]), "+f"(c[1]), "+f"(c[2]), "+f"(c[3])
        : "r"(__float_as_uint(a0)), "r"(__float_as_uint(a1)),
          "r"(__float_as_uint(a2)), "r"(__float_as_uint(a3)),
          "r"(__float_as_uint(b0)), "r"(__float_as_uint(b1)));
}

// ---------------------------------------------------------------------------
// Exact fp32 FFMA path for the 64-row cls projections (outputs compared
// directly -> keep full precision). 4 blocks per cls tensor (64x64 cols each).
// Uses sA [64][68] and sWf (= first 64*68 of sW region) [64][68].
// ---------------------------------------------------------------------------
__device__ void ffma_cls_block(const float* __restrict__ A, const float* __restrict__ W,
                               const float* __restrict__ bias, float* __restrict__ C,
                               int n0, float* sA, float* sWf) {
    const int tid = threadIdx.x;
    const int tx = tid & 15, ty = tid >> 4;
    float acc[4][4] = {};

    for (int k0 = 0; k0 < DD; k0 += 64) {
        #pragma unroll
        for (int it = 0; it < 4; it++) {
            int idx = tid + it * 256;
            int rr = idx >> 4;
            int cv = idx & 15;
            *(float4*)&sA[rr * 68 + cv * 4] =
                *(const float4*)(A + (size_t)rr * DD + k0 + cv * 4);
            *(float4*)&sWf[rr * 68 + cv * 4] =
                *(const float4*)(W + (size_t)(k0 + rr) * EE + n0 + cv * 4);
        }
        __syncthreads();
        #pragma unroll 8
        for (int kk = 0; kk < 64; kk++) {
            float4 b4 = *(const float4*)&sWf[kk * 68 + tx * 4];
            float bvals[4] = {b4.x, b4.y, b4.z, b4.w};
            float avals[4];
            #pragma unroll
            for (int i = 0; i < 4; i++) avals[i] = sA[(ty * 4 + i) * 68 + kk];
            #pragma unroll
            for (int i = 0; i < 4; i++)
                #pragma unroll
                for (int j = 0; j < 4; j++)
                    acc[i][j] = fmaf(avals[i], bvals[j], acc[i][j]);
        }
        __syncthreads();
    }

    float4 bb = *(const float4*)(bias + n0 + tx * 4);
    #pragma unroll
    for (int i = 0; i < 4; i++) {
        float4 o;
        o.x = acc[i][0] + bb.x;
        o.y = acc[i][1] + bb.y;
        o.z = acc[i][2] + bb.z;
        o.w = acc[i][3] + bb.w;
        *(float4*)(C + (size_t)(ty * 4 + i) * EE + n0 + tx * 4) = o;
    }
}

// ---------------------------------------------------------------------------
// Token projection kernel (tf32 MMA) with fused bias + l2norm.
// One block = 64 rows x 256 cols, k = 768 in chunks of 64.
// 8 warps: 2 row-groups x 4 col-groups, each warp tile 32x64.
// Grid (1-D): [0,197) vtok, [197,261) ttok, [261,265) vcls (ffma), [265,269) tcls.
// smem: sA [64][68] (row-major, stride==4 mod 32 -> conflict-free A-frag LDS),
//       sW [64][264] (k-major, stride==8 mod 32 -> conflict-free B-frag LDS).
// ---------------------------------------------------------------------------
__global__ __launch_bounds__(256) void proj_kernel(
    const float* __restrict__ visual_cls, const float* __restrict__ textual_cls,
    const float* __restrict__ vtokA, const float* __restrict__ ttokA,
    const float* __restrict__ Wv, const float* __restrict__ bv,
    const float* __restrict__ Wt, const float* __restrict__ bt,
    const float* __restrict__ Wvt, const float* __restrict__ bvt,
    const float* __restrict__ Wtt, const float* __restrict__ btt,
    float* __restrict__ out, float* __restrict__ vtokC, float* __restrict__ ttokC)
{
    extern __shared__ float sm[];
    float* sA = sm;              // 64*68
    float* sW = sm + 64 * 68;    // 64*264
    __shared__ float sbias[256];
    __shared__ float rowsq[64 * 5];
    __shared__ float sinv[64];

    const int bid = blockIdx.x;

    if (bid >= 261) {
        if (bid < 265)
            ffma_cls_block(visual_cls, Wv, bv, out, (bid - 261) * 64, sA, sW);
        else
            ffma_cls_block(textual_cls, Wt, bt, out + 16384, (bid - 265) * 64, sA, sW);
        return;
    }

    const float *A, *W, *bias;
    float* C;
    int mbase;
    if (bid < 197) { A = vtokA; W = Wvt; bias = bvt; C = vtokC; mbase = bid * 64; }
    else           { A = ttokA; W = Wtt; bias = btt; C = ttokC; mbase = (bid - 197) * 64; }

    const int tid = threadIdx.x;
    const int lane = tid & 31, w = tid >> 5;
    const int lq = lane >> 2, lr = lane & 3;
    const int vg = w >> 2, nw = w & 3;
    const int rbase = vg * 32;
    const int nb = nw * 64;

    sbias[tid] = bias[tid];

    float acc[2][8][4] = {};

    for (int k0 = 0; k0 < DD; k0 += 64) {
        // fill sA [64 rows][64 k] (tf32-rounded)
        #pragma unroll
        for (int it = 0; it < 4; it++) {
            int idx = tid + it * 256;
            int rr = idx >> 4;
            int cv = idx & 15;
            float4 v = *(const float4*)(A + (size_t)(mbase + rr) * DD + k0 + cv * 4);
            v.x = tf32r(v.x); v.y = tf32r(v.y); v.z = tf32r(v.z); v.w = tf32r(v.w);
            *(float4*)&sA[rr * 68 + cv * 4] = v;
        }
        // fill sW [64 k][256 n]
        #pragma unroll
        for (int it = 0; it < 16; it++) {
            int idx = tid + it * 256;
            int rr = idx >> 6;
            int cv = idx & 63;
            float4 v = *(const float4*)(W + (size_t)(k0 + rr) * EE + cv * 4);
            v.x = tf32r(v.x); v.y = tf32r(v.y); v.z = tf32r(v.z); v.w = tf32r(v.w);
            *(float4*)&sW[rr * 264 + cv * 4] = v;
        }
        __syncthreads();

        #pragma unroll
        for (int ks = 0; ks < 8; ks++) {
            float b0[8], b1[8];
            #pragma unroll
            for (int ng = 0; ng < 8; ng++) {
                int ba = (ks * 8 + lr) * 264 + nb + 8 * ng + lq;
                b0[ng] = sW[ba];
                b1[ng] = sW[ba + 4 * 264];
            }
            #pragma unroll
            for (int rg = 0; rg < 2; rg++) {
                int aa = (rbase + 16 * rg + lq) * 68 + ks * 8 + lr;
                float a0 = sA[aa], a1 = sA[aa + 8 * 68];
                float a2 = sA[aa + 4], a3 = sA[aa + 8 * 68 + 4];
                #pragma unroll
                for (int ng = 0; ng < 8; ng++)
                    mma8(acc[rg][ng], a0, a1, a2, a3, b0[ng], b1[ng]);
            }
        }
        __syncthreads();
    }

    // bias
    #pragma unroll
    for (int rg = 0; rg < 2; rg++)
        #pragma unroll
        for (int ng = 0; ng < 8; ng++) {
            int col = nb + 8 * ng + 2 * lr;
            float c0 = sbias[col], c1 = sbias[col + 1];
            acc[rg][ng][0] += c0; acc[rg][ng][1] += c1;
            acc[rg][ng][2] += c0; acc[rg][ng][3] += c1;
        }

    // l2norm: per-row sum of squares
    #pragma unroll
    for (int rg = 0; rg < 2; rg++) {
        float s0 = 0.f, s1 = 0.f;
        #pragma unroll
        for (int ng = 0; ng < 8; ng++) {
            s0 += acc[rg][ng][0] * acc[rg][ng][0] + acc[rg][ng][1] * acc[rg][ng][1];
            s1 += acc[rg][ng][2] * acc[rg][ng][2] + acc[rg][ng][3] * acc[rg][ng][3];
        }
        s0 += __shfl_xor_sync(0xffffffffu, s0, 1);
        s0 += __shfl_xor_sync(0xffffffffu, s0, 2);
        s1 += __shfl_xor_sync(0xffffffffu, s1, 1);
        s1 += __shfl_xor_sync(0xffffffffu, s1, 2);
        if (lr == 0) {
            rowsq[(rbase + 16 * rg + lq) * 5 + nw] = s0;
            rowsq[(rbase + 16 * rg + lq + 8) * 5 + nw] = s1;
        }
    }
    __syncthreads();
    if (tid < 64) {
        float s = rowsq[tid * 5] + rowsq[tid * 5 + 1] + rowsq[tid * 5 + 2] + rowsq[tid * 5 + 3];
        sinv[tid] = 1.0f / fmaxf(sqrtf(s), 1e-12f);
    }
    __syncthreads();

    #pragma unroll
    for (int rg = 0; rg < 2; rg++) {
        int r0 = rbase + 16 * rg + lq;
        float inv0 = sinv[r0], inv1 = sinv[r0 + 8];
        #pragma unroll
        for (int ng = 0; ng < 8; ng++) {
            int col = nb + 8 * ng + 2 * lr;
            float2 o0 = make_float2(acc[rg][ng][0] * inv0, acc[rg][ng][1] * inv0);
            float2 o1 = make_float2(acc[rg][ng][2] * inv1, acc[rg][ng][3] * inv1);
            *(float2*)(C + (size_t)(mbase + r0) * EE + col) = o0;
            *(float2*)(C + (size_t)(mbase + r0 + 8) * EE + col) = o1;
        }
    }
}

// ---------------------------------------------------------------------------
// Fused sim kernel (tf32 MMA). grid = (qpair=32, b=64), 256 threads (8 warps).
// Block tile: 128 v-rows x 128 t-cols (t-cols = q0's 64 + q1's 64, contiguous).
// 8 warps = 4 v-groups x 2 t-groups; warp tile 32v x 64t (one full q per warp).
// k = 256 in 2 chunks of 128. smem tiles [128][132] (stride 132 == 4 mod 32
// -> conflict-free fragment LDS for both operands).
//   i2t[b][q] = (1/V) sum_v max_t sim
//   t2i[b][q] = (1/len[b]) sum_{t<len[b]} max_v sim
// ---------------------------------------------------------------------------
__global__ __launch_bounds__(256) void sim_kernel(
    const float* __restrict__ vtok, const float* __restrict__ ttok,
    const int* __restrict__ text_length, float* __restrict__ out)
{
    extern __shared__ float smem[];
    float* sV = smem;              // 128*132
    float* sT = smem + 128 * 132;  // 128*132

    __shared__ float t2i_part[4][128];
    __shared__ float t2i_run[128];
    __shared__ float wsum[8];

    const int tid = threadIdx.x;
    const int lane = tid & 31, w = tid >> 5;
    const int lq = lane >> 2, lr = lane & 3;
    const int vb = (w >> 1) * 32;        // warp's v base within 128-row tile
    const int tb = (w & 1) * 64;         // warp's t base (selects q0 / q1)
    const int qp = blockIdx.x;           // q pair index
    const int b = blockIdx.y;

    const float* vbase = vtok + (size_t)b * VV * EE;
    const float* tbase = ttok + (size_t)(qp * 2) * LL * EE;  // 128 contiguous t rows

    float i2t_wsum = 0.0f;   // this warp's running i2t contribution (its q)

    for (int v0 = 0; v0 < 256; v0 += 128) {
        float acc[2][8][4] = {};

        for (int kc = 0; kc < 2; kc++) {
            // fill sV (zero-padded past V) and sT, tf32-rounded
            #pragma unroll
            for (int it = 0; it < 16; it++) {
                int idx = tid + it * 256;
                int r = idx >> 5;
                int c = idx & 31;
                float4 v;
                if (v0 + r < VV)
                    v = *(const float4*)(vbase + (size_t)(v0 + r) * EE + kc * 128 + 4 * c);
                else
                    v = make_float4(0.f, 0.f, 0.f, 0.f);
                v.x = tf32r(v.x); v.y = tf32r(v.y); v.z = tf32r(v.z); v.w = tf32r(v.w);
                *(float4*)&sV[r * 132 + 4 * c] = v;

                float4 t = *(const float4*)(tbase + (size_t)r * EE + kc * 128 + 4 * c);
                t.x = tf32r(t.x); t.y = tf32r(t.y); t.z = tf32r(t.z); t.w = tf32r(t.w);
                *(float4*)&sT[r * 132 + 4 * c] = t;
            }
            __syncthreads();

            #pragma unroll
            for (int ks = 0; ks < 16; ks++) {
                float b0[8], b1[8];
                #pragma unroll
                for (int ng = 0; ng < 8; ng++) {
                    int ba = (tb + 8 * ng + lq) * 132 + ks * 8 + lr;
                    b0[ng] = sT[ba];
                    b1[ng] = sT[ba + 4];
                }
                #pragma unroll
                for (int rg = 0; rg < 2; rg++) {
                    int aa = (vb + 16 * rg + lq) * 132 + ks * 8 + lr;
                    float a0 = sV[aa], a1 = sV[aa + 8 * 132];
                    float a2 = sV[aa + 4], a3 = sV[aa + 8 * 132 + 4];
                    #pragma unroll
                    for (int ng = 0; ng < 8; ng++)
                        mma8(acc[rg][ng], a0, a1, a2, a3, b0[ng], b1[ng]);
                }
            }
            __syncthreads();
        }

        // ---- i2t: per-v-row max over this warp's 64 t cols (= its full q) ----
        float rsum = 0.0f;
        #pragma unroll
        for (int rg = 0; rg < 2; rg++) {
            float m0 = -1e30f, m1 = -1e30f;
            #pragma unroll
            for (int ng = 0; ng < 8; ng++) {
                m0 = fmaxf(m0, fmaxf(acc[rg][ng][0], acc[rg][ng][1]));
                m1 = fmaxf(m1, fmaxf(acc[rg][ng][2], acc[rg][ng][3]));
            }
            m0 = fmaxf(m0, __shfl_xor_sync(0xffffffffu, m0, 1));
            m0 = fmaxf(m0, __shfl_xor_sync(0xffffffffu, m0, 2));
            m1 = fmaxf(m1, __shfl_xor_sync(0xffffffffu, m1, 1));
            m1 = fmaxf(m1, __shfl_xor_sync(0xffffffffu, m1, 2));
            int r0 = v0 + vb + 16 * rg + lq;
            if (lr == 0) {
                if (r0 < VV) rsum += m0;
                if (r0 + 8 < VV) rsum += m1;
            }
        }
        #pragma unroll
        for (int off = 16; off > 0; off >>= 1)
            rsum += __shfl_xor_sync(0xffffffffu, rsum, off);
        i2t_wsum += rsum;

        // ---- t2i: per-t-col max over this warp's 32 v rows (masked) ----
        #pragma unroll
        for (int ng = 0; ng < 8; ng++) {
            float m0 = -1e30f, m1 = -1e30f;
            #pragma unroll
            for (int rg = 0; rg < 2; rg++) {
                int r0 = v0 + vb + 16 * rg + lq;
                if (r0 < VV) {
                    m0 = fmaxf(m0, acc[rg][ng][0]);
                    m1 = fmaxf(m1, acc[rg][ng][1]);
                }
                if (r0 + 8 < VV) {
                    m0 = fmaxf(m0, acc[rg][ng][2]);
                    m1 = fmaxf(m1, acc[rg][ng][3]);
                }
            }
            m0 = fmaxf(m0, __shfl_xor_sync(0xffffffffu, m0, 4));
            m0 = fmaxf(m0, __shfl_xor_sync(0xffffffffu, m0, 8));
            m0 = fmaxf(m0, __shfl_xor_sync(0xffffffffu, m0, 16));
            m1 = fmaxf(m1, __shfl_xor_sync(0xffffffffu, m1, 4));
            m1 = fmaxf(m1, __shfl_xor_sync(0xffffffffu, m1, 8));
            m1 = fmaxf(m1, __shfl_xor_sync(0xffffffffu, m1, 16));
            if (lane < 4) {
                t2i_part[w >> 1][tb + 8 * ng + 2 * lane] = m0;
                t2i_part[w >> 1][tb + 8 * ng + 2 * lane + 1] = m1;
            }
        }
        __syncthreads();
        if (tid < 128) {
            float m = fmaxf(fmaxf(t2i_part[0][tid], t2i_part[1][tid]),
                            fmaxf(t2i_part[2][tid], t2i_part[3][tid]));
            t2i_run[tid] = (v0 == 0) ? m : fmaxf(t2i_run[tid], m);
        }
        __syncthreads();
    }

    if (lane == 0) wsum[w] = i2t_wsum;
    __syncthreads();

    // t2i outputs: warp 0 -> q0, warp 1 -> q1
    if (tid < 64) {
        int w2 = tid >> 5;
        int l2 = tid & 31;
        int len = text_length[b];   // reference quirk: indexed by b
        float s = 0.0f;
        if (l2 < len) s += t2i_run[w2 * 64 + l2];
        if (l2 + 32 < len) s += t2i_run[w2 * 64 + l2 + 32];
        #pragma unroll
        for (int off = 16; off > 0; off >>= 1)
            s += __shfl_xor_sync(0xffffffffu, s, off);
        if (l2 == 0)
            out[36864 + b * 64 + qp * 2 + w2] = s / fmaxf((float)len, 1e-6f);
    }
    // i2t outputs
    if (tid == 128 || tid == 129) {
        int j = tid - 128;
        float s = wsum[j] + wsum[j + 2] + wsum[j + 4] + wsum[j + 6];
        out[32768 + b * 64 + qp * 2 + j] = s / (float)VV;
    }
}

// ---------------------------------------------------------------------------
extern "C" void kernel_launch(void* const* d_in, const int* in_sizes, int n_in,
                              void* d_out, int out_size)
{
    const float* visual_cls     = (const float*)d_in[0];
    const float* textual_cls    = (const float*)d_in[1];
    const float* visual_tokens  = (const float*)d_in[2];
    const float* textual_tokens = (const float*)d_in[3];
    const int*   text_length    = (const int*)  d_in[4];
    const float* Wv  = (const float*)d_in[5];
    const float* bv  = (const float*)d_in[6];
    const float* Wt  = (const float*)d_in[7];
    const float* bt  = (const float*)d_in[8];
    const float* Wvt = (const float*)d_in[9];
    const float* bvt = (const float*)d_in[10];
    const float* Wtt = (const float*)d_in[11];
    const float* btt = (const float*)d_in[12];
    float* out = (float*)d_out;

    float *vtok = nullptr, *ttok = nullptr;
    cudaGetSymbolAddress((void**)&vtok, g_vtok);
    cudaGetSymbolAddress((void**)&ttok, g_ttok);

    const int proj_smem = (64 * 68 + 64 * 264) * sizeof(float);   // 84992
    const int sim_smem  = (2 * 128 * 132) * sizeof(float);        // 135168
    cudaFuncSetAttribute(proj_kernel, cudaFuncAttributeMaxDynamicSharedMemorySize, proj_smem);
    cudaFuncSetAttribute(sim_kernel,  cudaFuncAttributeMaxDynamicSharedMemorySize, sim_smem);

    // 269 blocks: 197 vtok + 64 ttok (tf32 MMA, fused bias+l2norm)
    //             + 4 vcls + 4 tcls (exact fp32 FFMA, hidden under MMA blocks)
    proj_kernel<<<269, 256, proj_smem>>>(
        visual_cls, textual_cls, visual_tokens, textual_tokens,
        Wv, bv, Wt, bt, Wvt, bvt, Wtt, btt,
        out, vtok, ttok);

    sim_kernel<<<dim3(32, 64), 256, sim_smem>>>(vtok, ttok, text_length, out);
}

// round 5
// speedup vs baseline: 7.0877x; 1.9695x over previous
#include <cuda_runtime.h>
#include <cuda_fp16.h>
#include <math.h>

#define BB 64
#define VV 197
#define LL 64
#define DD 768
#define EE 256

// Scratch: projected + normalized tokens in fp16
__device__ __align__(16) __half g_vtok[(size_t)BB * VV * EE]; // 6.45 MB
__device__ __align__(16) __half g_ttok[(size_t)BB * LL * EE]; // 2.1 MB

// ---------------------------------------------------------------------------
// helpers
// ---------------------------------------------------------------------------
__device__ __forceinline__ float tf32r(float x) {
    unsigned u;
    asm("cvt.rna.tf32.f32 %0, %1;" : "=r"(u) : "f"(x));
    return __uint_as_float(u);
}

__device__ __forceinline__ void mma8(float* c, float a0, float a1, float a2, float a3,
                                     float b0, float b1) {
    asm volatile(
        "mma.sync.aligned.m16n8k8.row.col.f32.tf32.tf32.f32 "
        "{%0,%1,%2,%3},{%4,%5,%6,%7},{%8,%9},{%0,%1,%2,%3};\n"
        : "+f"(c[0]), "+f"(c[1]), "+f"(c[2]), "+f"(c[3])
        : "r"(__float_as_uint(a0)), "r"(__float_as_uint(a1)),
          "r"(__float_as_uint(a2)), "r"(__float_as_uint(a3)),
          "r"(__float_as_uint(b0)), "r"(__float_as_uint(b1)));
}

__device__ __forceinline__ void mma16(float* c, unsigned a0, unsigned a1, unsigned a2,
                                      unsigned a3, unsigned b0, unsigned b1) {
    asm volatile(
        "mma.sync.aligned.m16n8k16.row.col.f32.f16.f16.f32 "
        "{%0,%1,%2,%3},{%4,%5,%6,%7},{%8,%9},{%0,%1,%2,%3};\n"
        : "+f"(c[0]), "+f"(c[1]), "+f"(c[2]), "+f"(c[3])
        : "r"(a0), "r"(a1), "r"(a2), "r"(a3), "r"(b0), "r"(b1));
}

__device__ __forceinline__ void cpa16(unsigned s, const void* g) {
    asm volatile("cp.async.cg.shared.global [%0], [%1], 16;" :: "r"(s), "l"(g) : "memory");
}
__device__ __forceinline__ void cpa_commit() {
    asm volatile("cp.async.commit_group;" ::: "memory");
}
__device__ __forceinline__ void cpa_wait0() {
    asm volatile("cp.async.wait_group 0;" ::: "memory");
}

// ---------------------------------------------------------------------------
// Exact fp32 FFMA path for the 64-row cls projections (outputs compared
// directly -> keep full precision). 4 blocks per cls tensor (64x64 cols each).
// ---------------------------------------------------------------------------
__device__ void ffma_cls_block(const float* __restrict__ A, const float* __restrict__ W,
                               const float* __restrict__ bias, float* __restrict__ C,
                               int n0, float* sA, float* sWf) {
    const int tid = threadIdx.x;
    const int tx = tid & 15, ty = tid >> 4;
    float acc[4][4] = {};

    for (int k0 = 0; k0 < DD; k0 += 64) {
        #pragma unroll
        for (int it = 0; it < 4; it++) {
            int idx = tid + it * 256;
            int rr = idx >> 4;
            int cv = idx & 15;
            *(float4*)&sA[rr * 68 + cv * 4] =
                *(const float4*)(A + (size_t)rr * DD + k0 + cv * 4);
            *(float4*)&sWf[rr * 68 + cv * 4] =
                *(const float4*)(W + (size_t)(k0 + rr) * EE + n0 + cv * 4);
        }
        __syncthreads();
        #pragma unroll 8
        for (int kk = 0; kk < 64; kk++) {
            float4 b4 = *(const float4*)&sWf[kk * 68 + tx * 4];
            float bvals[4] = {b4.x, b4.y, b4.z, b4.w};
            float avals[4];
            #pragma unroll
            for (int i = 0; i < 4; i++) avals[i] = sA[(ty * 4 + i) * 68 + kk];
            #pragma unroll
            for (int i = 0; i < 4; i++)
                #pragma unroll
                for (int j = 0; j < 4; j++)
                    acc[i][j] = fmaf(avals[i], bvals[j], acc[i][j]);
        }
        __syncthreads();
    }

    float4 bb = *(const float4*)(bias + n0 + tx * 4);
    #pragma unroll
    for (int i = 0; i < 4; i++) {
        float4 o;
        o.x = acc[i][0] + bb.x;
        o.y = acc[i][1] + bb.y;
        o.z = acc[i][2] + bb.z;
        o.w = acc[i][3] + bb.w;
        *(float4*)(C + (size_t)(ty * 4 + i) * EE + n0 + tx * 4) = o;
    }
}

// ---------------------------------------------------------------------------
// Token projection (tf32 MMA) with fused bias + l2norm; fp16 output.
// Grid: [0,197) vtok, [197,261) ttok, [261,265) vcls (ffma), [265,269) tcls.
// ---------------------------------------------------------------------------
__global__ __launch_bounds__(256) void proj_kernel(
    const float* __restrict__ visual_cls, const float* __restrict__ textual_cls,
    const float* __restrict__ vtokA, const float* __restrict__ ttokA,
    const float* __restrict__ Wv, const float* __restrict__ bv,
    const float* __restrict__ Wt, const float* __restrict__ bt,
    const float* __restrict__ Wvt, const float* __restrict__ bvt,
    const float* __restrict__ Wtt, const float* __restrict__ btt,
    float* __restrict__ out, __half* __restrict__ vtokC, __half* __restrict__ ttokC)
{
    extern __shared__ float sm[];
    float* sA = sm;              // 64*68
    float* sW = sm + 64 * 68;    // 64*264
    __shared__ float sbias[256];
    __shared__ float rowsq[64 * 5];
    __shared__ float sinv[64];

    const int bid = blockIdx.x;

    if (bid >= 261) {
        if (bid < 265)
            ffma_cls_block(visual_cls, Wv, bv, out, (bid - 261) * 64, sA, sW);
        else
            ffma_cls_block(textual_cls, Wt, bt, out + 16384, (bid - 265) * 64, sA, sW);
        return;
    }

    const float *A, *W, *bias;
    __half* C;
    int mbase;
    if (bid < 197) { A = vtokA; W = Wvt; bias = bvt; C = vtokC; mbase = bid * 64; }
    else           { A = ttokA; W = Wtt; bias = btt; C = ttokC; mbase = (bid - 197) * 64; }

    const int tid = threadIdx.x;
    const int lane = tid & 31, w = tid >> 5;
    const int lq = lane >> 2, lr = lane & 3;
    const int vg = w >> 2, nw = w & 3;
    const int rbase = vg * 32;
    const int nb = nw * 64;

    sbias[tid] = bias[tid];

    float acc[2][8][4] = {};

    for (int k0 = 0; k0 < DD; k0 += 64) {
        #pragma unroll
        for (int it = 0; it < 4; it++) {
            int idx = tid + it * 256;
            int rr = idx >> 4;
            int cv = idx & 15;
            float4 v = *(const float4*)(A + (size_t)(mbase + rr) * DD + k0 + cv * 4);
            v.x = tf32r(v.x); v.y = tf32r(v.y); v.z = tf32r(v.z); v.w = tf32r(v.w);
            *(float4*)&sA[rr * 68 + cv * 4] = v;
        }
        #pragma unroll
        for (int it = 0; it < 16; it++) {
            int idx = tid + it * 256;
            int rr = idx >> 6;
            int cv = idx & 63;
            float4 v = *(const float4*)(W + (size_t)(k0 + rr) * EE + cv * 4);
            v.x = tf32r(v.x); v.y = tf32r(v.y); v.z = tf32r(v.z); v.w = tf32r(v.w);
            *(float4*)&sW[rr * 264 + cv * 4] = v;
        }
        __syncthreads();

        #pragma unroll
        for (int ks = 0; ks < 8; ks++) {
            float b0[8], b1[8];
            #pragma unroll
            for (int ng = 0; ng < 8; ng++) {
                int ba = (ks * 8 + lr) * 264 + nb + 8 * ng + lq;
                b0[ng] = sW[ba];
                b1[ng] = sW[ba + 4 * 264];
            }
            #pragma unroll
            for (int rg = 0; rg < 2; rg++) {
                int aa = (rbase + 16 * rg + lq) * 68 + ks * 8 + lr;
                float a0 = sA[aa], a1 = sA[aa + 8 * 68];
                float a2 = sA[aa + 4], a3 = sA[aa + 8 * 68 + 4];
                #pragma unroll
                for (int ng = 0; ng < 8; ng++)
                    mma8(acc[rg][ng], a0, a1, a2, a3, b0[ng], b1[ng]);
            }
        }
        __syncthreads();
    }

    // bias
    #pragma unroll
    for (int rg = 0; rg < 2; rg++)
        #pragma unroll
        for (int ng = 0; ng < 8; ng++) {
            int col = nb + 8 * ng + 2 * lr;
            float c0 = sbias[col], c1 = sbias[col + 1];
            acc[rg][ng][0] += c0; acc[rg][ng][1] += c1;
            acc[rg][ng][2] += c0; acc[rg][ng][3] += c1;
        }

    // l2norm: per-row sum of squares
    #pragma unroll
    for (int rg = 0; rg < 2; rg++) {
        float s0 = 0.f, s1 = 0.f;
        #pragma unroll
        for (int ng = 0; ng < 8; ng++) {
            s0 += acc[rg][ng][0] * acc[rg][ng][0] + acc[rg][ng][1] * acc[rg][ng][1];
            s1 += acc[rg][ng][2] * acc[rg][ng][2] + acc[rg][ng][3] * acc[rg][ng][3];
        }
        s0 += __shfl_xor_sync(0xffffffffu, s0, 1);
        s0 += __shfl_xor_sync(0xffffffffu, s0, 2);
        s1 += __shfl_xor_sync(0xffffffffu, s1, 1);
        s1 += __shfl_xor_sync(0xffffffffu, s1, 2);
        if (lr == 0) {
            rowsq[(rbase + 16 * rg + lq) * 5 + nw] = s0;
            rowsq[(rbase + 16 * rg + lq + 8) * 5 + nw] = s1;
        }
    }
    __syncthreads();
    if (tid < 64) {
        float s = rowsq[tid * 5] + rowsq[tid * 5 + 1] + rowsq[tid * 5 + 2] + rowsq[tid * 5 + 3];
        sinv[tid] = 1.0f / fmaxf(sqrtf(s), 1e-12f);
    }
    __syncthreads();

    #pragma unroll
    for (int rg = 0; rg < 2; rg++) {
        int r0 = rbase + 16 * rg + lq;
        float inv0 = sinv[r0], inv1 = sinv[r0 + 8];
        #pragma unroll
        for (int ng = 0; ng < 8; ng++) {
            int col = nb + 8 * ng + 2 * lr;
            __half2 h0 = __floats2half2_rn(acc[rg][ng][0] * inv0, acc[rg][ng][1] * inv0);
            __half2 h1 = __floats2half2_rn(acc[rg][ng][2] * inv1, acc[rg][ng][3] * inv1);
            *(__half2*)(C + (size_t)(mbase + r0) * EE + col) = h0;
            *(__half2*)(C + (size_t)(mbase + r0 + 8) * EE + col) = h1;
        }
    }
}

// ---------------------------------------------------------------------------
// Fused sim kernel (fp16 MMA m16n8k16, f32 accum).
// grid = (qpair=32, b=64), 256 threads (8 warps = 4 v-groups x 2 t-groups).
// Block tile 128v x 128t. sT resident for full K=256 (loaded once per block);
// sV streamed per (v-tile, k-chunk=128) via cp.async. 2 blocks/SM.
//   i2t[b][q] = (1/V) sum_v max_t sim
//   t2i[b][q] = (1/len[b]) sum_{t<len[b]} max_v sim   (len indexed by b!)
// ---------------------------------------------------------------------------
#define SVS 136   // sV stride in halves (272B: bank-bijective for fragments)
#define STS 264   // sT stride in halves (528B: same property)

__global__ __launch_bounds__(256, 2) void sim_kernel(
    const __half* __restrict__ vtok, const __half* __restrict__ ttok,
    const int* __restrict__ text_length, float* __restrict__ out)
{
    extern __shared__ __half smh[];
    __half* sV = smh;                  // 128 x SVS
    __half* sT = smh + 128 * SVS;      // 128 x STS (full K)

    __shared__ float t2i_part[4][128];
    __shared__ float t2i_run[128];
    __shared__ float wsum[8];

    const int tid = threadIdx.x;
    const int lane = tid & 31, w = tid >> 5;
    const int lq = lane >> 2, lr = lane & 3;
    const int vb = (w >> 1) * 32;
    const int tb = (w & 1) * 64;
    const int qp = blockIdx.x, b = blockIdx.y;

    const __half* vbase = vtok + (size_t)b * VV * EE;
    const __half* tbase = ttok + (size_t)(qp * 2) * LL * EE;

    unsigned sVu = (unsigned)__cvta_generic_to_shared(sV);
    unsigned sTu = (unsigned)__cvta_generic_to_shared(sT);

    // sT: full 128 t-rows x 256 k (once per block)
    #pragma unroll
    for (int it = 0; it < 16; it++) {
        int idx = tid + it * 256;        // 0..4095
        int r = idx >> 5;                // 0..127
        int c8 = idx & 31;               // 8-half unit
        cpa16(sTu + (unsigned)(r * STS + c8 * 8) * 2, tbase + (size_t)r * EE + c8 * 8);
    }

    float i2t_wsum = 0.0f;

    for (int v0 = 0; v0 < 256; v0 += 128) {
        float acc[2][8][4] = {};

        for (int kc = 0; kc < 2; kc++) {
            // sV chunk: 128 rows x 128 k (source row clamped; garbage rows masked later)
            #pragma unroll
            for (int it = 0; it < 8; it++) {
                int idx = tid + it * 256;    // 0..2047
                int r = idx >> 4;            // 0..127
                int c8 = idx & 15;
                int vr = min(v0 + r, VV - 1);
                cpa16(sVu + (unsigned)(r * SVS + c8 * 8) * 2,
                      vbase + (size_t)vr * EE + kc * 128 + c8 * 8);
            }
            cpa_commit();
            cpa_wait0();
            __syncthreads();

            #pragma unroll
            for (int ks = 0; ks < 8; ks++) {
                unsigned b0[8], b1[8];
                #pragma unroll
                for (int ng = 0; ng < 8; ng++) {
                    const __half* p = sT + (tb + 8 * ng + lq) * STS + kc * 128 + ks * 16 + 2 * lr;
                    b0[ng] = *(const unsigned*)p;
                    b1[ng] = *(const unsigned*)(p + 8);
                }
                #pragma unroll
                for (int rg = 0; rg < 2; rg++) {
                    const __half* p = sV + (vb + 16 * rg + lq) * SVS + ks * 16 + 2 * lr;
                    unsigned a0 = *(const unsigned*)p;
                    unsigned a1 = *(const unsigned*)(p + 8 * SVS);
                    unsigned a2 = *(const unsigned*)(p + 8);
                    unsigned a3 = *(const unsigned*)(p + 8 * SVS + 8);
                    #pragma unroll
                    for (int ng = 0; ng < 8; ng++)
                        mma16(acc[rg][ng], a0, a1, a2, a3, b0[ng], b1[ng]);
                }
            }
            __syncthreads();
        }

        // ---- i2t: per-v-row max over this warp's 64 t cols (its full q) ----
        float rsum = 0.0f;
        #pragma unroll
        for (int rg = 0; rg < 2; rg++) {
            float m0 = -1e30f, m1 = -1e30f;
            #pragma unroll
            for (int ng = 0; ng < 8; ng++) {
                m0 = fmaxf(m0, fmaxf(acc[rg][ng][0], acc[rg][ng][1]));
                m1 = fmaxf(m1, fmaxf(acc[rg][ng][2], acc[rg][ng][3]));
            }
            m0 = fmaxf(m0, __shfl_xor_sync(0xffffffffu, m0, 1));
            m0 = fmaxf(m0, __shfl_xor_sync(0xffffffffu, m0, 2));
            m1 = fmaxf(m1, __shfl_xor_sync(0xffffffffu, m1, 1));
            m1 = fmaxf(m1, __shfl_xor_sync(0xffffffffu, m1, 2));
            int r0 = v0 + vb + 16 * rg + lq;
            if (lr == 0) {
                if (r0 < VV) rsum += m0;
                if (r0 + 8 < VV) rsum += m1;
            }
        }
        #pragma unroll
        for (int off = 16; off > 0; off >>= 1)
            rsum += __shfl_xor_sync(0xffffffffu, rsum, off);
        i2t_wsum += rsum;

        // ---- t2i: per-t-col max over this warp's 32 v rows (masked) ----
        #pragma unroll
        for (int ng = 0; ng < 8; ng++) {
            float m0 = -1e30f, m1 = -1e30f;
            #pragma unroll
            for (int rg = 0; rg < 2; rg++) {
                int r0 = v0 + vb + 16 * rg + lq;
                if (r0 < VV) {
                    m0 = fmaxf(m0, acc[rg][ng][0]);
                    m1 = fmaxf(m1, acc[rg][ng][1]);
                }
                if (r0 + 8 < VV) {
                    m0 = fmaxf(m0, acc[rg][ng][2]);
                    m1 = fmaxf(m1, acc[rg][ng][3]);
                }
            }
            m0 = fmaxf(m0, __shfl_xor_sync(0xffffffffu, m0, 4));
            m0 = fmaxf(m0, __shfl_xor_sync(0xffffffffu, m0, 8));
            m0 = fmaxf(m0, __shfl_xor_sync(0xffffffffu, m0, 16));
            m1 = fmaxf(m1, __shfl_xor_sync(0xffffffffu, m1, 4));
            m1 = fmaxf(m1, __shfl_xor_sync(0xffffffffu, m1, 8));
            m1 = fmaxf(m1, __shfl_xor_sync(0xffffffffu, m1, 16));
            if (lane < 4) {
                t2i_part[w >> 1][tb + 8 * ng + 2 * lane] = m0;
                t2i_part[w >> 1][tb + 8 * ng + 2 * lane + 1] = m1;
            }
        }
        __syncthreads();
        if (tid < 128) {
            float m = fmaxf(fmaxf(t2i_part[0][tid], t2i_part[1][tid]),
                            fmaxf(t2i_part[2][tid], t2i_part[3][tid]));
            t2i_run[tid] = (v0 == 0) ? m : fmaxf(t2i_run[tid], m);
        }
        __syncthreads();
    }

    if (lane == 0) wsum[w] = i2t_wsum;
    __syncthreads();

    // t2i outputs: warp 0 -> q0, warp 1 -> q1
    if (tid < 64) {
        int w2 = tid >> 5;
        int l2 = tid & 31;
        int len = text_length[b];   // reference quirk: indexed by b
        float s = 0.0f;
        if (l2 < len) s += t2i_run[w2 * 64 + l2];
        if (l2 + 32 < len) s += t2i_run[w2 * 64 + l2 + 32];
        #pragma unroll
        for (int off = 16; off > 0; off >>= 1)
            s += __shfl_xor_sync(0xffffffffu, s, off);
        if (l2 == 0)
            out[36864 + b * 64 + qp * 2 + w2] = s / fmaxf((float)len, 1e-6f);
    }
    // i2t outputs
    if (tid == 128 || tid == 129) {
        int j = tid - 128;
        float s = wsum[j] + wsum[j + 2] + wsum[j + 4] + wsum[j + 6];
        out[32768 + b * 64 + qp * 2 + j] = s / (float)VV;
    }
}

// ---------------------------------------------------------------------------
extern "C" void kernel_launch(void* const* d_in, const int* in_sizes, int n_in,
                              void* d_out, int out_size)
{
    const float* visual_cls     = (const float*)d_in[0];
    const float* textual_cls    = (const float*)d_in[1];
    const float* visual_tokens  = (const float*)d_in[2];
    const float* textual_tokens = (const float*)d_in[3];
    const int*   text_length    = (const int*)  d_in[4];
    const float* Wv  = (const float*)d_in[5];
    const float* bv  = (const float*)d_in[6];
    const float* Wt  = (const float*)d_in[7];
    const float* bt  = (const float*)d_in[8];
    const float* Wvt = (const float*)d_in[9];
    const float* bvt = (const float*)d_in[10];
    const float* Wtt = (const float*)d_in[11];
    const float* btt = (const float*)d_in[12];
    float* out = (float*)d_out;

    __half *vtok = nullptr, *ttok = nullptr;
    cudaGetSymbolAddress((void**)&vtok, g_vtok);
    cudaGetSymbolAddress((void**)&ttok, g_ttok);

    const int proj_smem = (64 * 68 + 64 * 264) * sizeof(float);           // 84992
    const int sim_smem  = (128 * SVS + 128 * STS) * sizeof(__half);       // 102400
    cudaFuncSetAttribute(proj_kernel, cudaFuncAttributeMaxDynamicSharedMemorySize, proj_smem);
    cudaFuncSetAttribute(sim_kernel,  cudaFuncAttributeMaxDynamicSharedMemorySize, sim_smem);

    proj_kernel<<<269, 256, proj_smem>>>(
        visual_cls, textual_cls, visual_tokens, textual_tokens,
        Wv, bv, Wt, bt, Wvt, bvt, Wtt, btt,
        out, vtok, ttok);

    sim_kernel<<<dim3(32, 64), 256, sim_smem>>>(vtok, ttok, text_length, out);
}

// round 8
// speedup vs baseline: 7.9722x; 1.1248x over previous
#include <cuda_runtime.h>
#include <cuda_fp16.h>
#include <math.h>
#include <stdint.h>

#define BB 64
#define VV 197
#define LL 64
#define DD 768
#define EE 256

// Scratch: projected + normalized tokens in fp16, transposed half weights
__device__ __align__(16) __half g_vtok[(size_t)BB * VV * EE]; // 6.45 MB
__device__ __align__(16) __half g_ttok[(size_t)BB * LL * EE]; // 2.1 MB
__device__ __align__(16) __half g_wvtT[(size_t)EE * DD];      // 0.39 MB [n][k]
__device__ __align__(16) __half g_wttT[(size_t)EE * DD];      // 0.39 MB [n][k]

// ---------------------------------------------------------------------------
// helpers
// ---------------------------------------------------------------------------
__device__ __forceinline__ void mma16(float* c, unsigned a0, unsigned a1, unsigned a2,
                                      unsigned a3, unsigned b0, unsigned b1) {
    asm volatile(
        "mma.sync.aligned.m16n8k16.row.col.f32.f16.f16.f32 "
        "{%0,%1,%2,%3},{%4,%5,%6,%7},{%8,%9},{%0,%1,%2,%3};\n"
        : "+f"(c[0]), "+f"(c[1]), "+f"(c[2]), "+f"(c[3])
        : "r"(a0), "r"(a1), "r"(a2), "r"(a3), "r"(b0), "r"(b1));
}

__device__ __forceinline__ void cpa16(unsigned s, const void* g) {
    asm volatile("cp.async.cg.shared.global [%0], [%1], 16;" :: "r"(s), "l"(g) : "memory");
}
__device__ __forceinline__ void cpa_commit() {
    asm volatile("cp.async.commit_group;" ::: "memory");
}
__device__ __forceinline__ void cpa_wait0() {
    asm volatile("cp.async.wait_group 0;" ::: "memory");
}
__device__ __forceinline__ unsigned s2u(const void* p) {
    return (unsigned)__cvta_generic_to_shared(p);
}

// ---------------------------------------------------------------------------
// W transpose + fp32->fp16 prepass: W[768][256] -> WT[256][768] half.
// grid (24, 8, 2), block (32, 8).
// ---------------------------------------------------------------------------
__global__ void wprep_kernel(const float* __restrict__ Wvt, const float* __restrict__ Wtt,
                             __half* __restrict__ WvtT, __half* __restrict__ WttT)
{
    __shared__ float t[32][33];
    const float* W = blockIdx.z ? Wtt : Wvt;
    __half* WT = blockIdx.z ? WttT : WvtT;
    int kb = blockIdx.x * 32, nb = blockIdx.y * 32;
    int tx = threadIdx.x, ty = threadIdx.y;
    #pragma unroll
    for (int j = 0; j < 4; j++)
        t[ty + 8 * j][tx] = W[(size_t)(kb + ty + 8 * j) * EE + nb + tx];
    __syncthreads();
    #pragma unroll
    for (int j = 0; j < 4; j++)
        WT[(size_t)(nb + ty + 8 * j) * DD + kb + tx] = __float2half(t[tx][ty + 8 * j]);
}

// ---------------------------------------------------------------------------
// Exact fp32 FFMA path for the 64-row cls projections (outputs compared
// directly -> keep full precision). 4 blocks per cls tensor (64x64 cols).
// ---------------------------------------------------------------------------
__device__ void ffma_cls_block(const float* __restrict__ A, const float* __restrict__ W,
                               const float* __restrict__ bias, float* __restrict__ C,
                               int n0, float* sA, float* sWf) {
    const int tid = threadIdx.x;
    const int tx = tid & 15, ty = tid >> 4;
    float acc[4][4] = {};

    for (int k0 = 0; k0 < DD; k0 += 64) {
        #pragma unroll
        for (int it = 0; it < 4; it++) {
            int idx = tid + it * 256;
            int rr = idx >> 4;
            int cv = idx & 15;
            *(float4*)&sA[rr * 68 + cv * 4] =
                *(const float4*)(A + (size_t)rr * DD + k0 + cv * 4);
            *(float4*)&sWf[rr * 68 + cv * 4] =
                *(const float4*)(W + (size_t)(k0 + rr) * EE + n0 + cv * 4);
        }
        __syncthreads();
        #pragma unroll 8
        for (int kk = 0; kk < 64; kk++) {
            float4 b4 = *(const float4*)&sWf[kk * 68 + tx * 4];
            float bvals[4] = {b4.x, b4.y, b4.z, b4.w};
            float avals[4];
            #pragma unroll
            for (int i = 0; i < 4; i++) avals[i] = sA[(ty * 4 + i) * 68 + kk];
            #pragma unroll
            for (int i = 0; i < 4; i++)
                #pragma unroll
                for (int j = 0; j < 4; j++)
                    acc[i][j] = fmaf(avals[i], bvals[j], acc[i][j]);
        }
        __syncthreads();
    }

    float4 bb = *(const float4*)(bias + n0 + tx * 4);
    #pragma unroll
    for (int i = 0; i < 4; i++) {
        float4 o;
        o.x = acc[i][0] + bb.x;
        o.y = acc[i][1] + bb.y;
        o.z = acc[i][2] + bb.z;
        o.w = acc[i][3] + bb.w;
        *(float4*)(C + (size_t)(ty * 4 + i) * EE + n0 + tx * 4) = o;
    }
}

// ---------------------------------------------------------------------------
// Token projection (fp16 MMA m16n8k16) with fused bias + l2norm; half output.
// One block = 64 rows x 256 cols, K=768 in chunks of 128.
// smem: sAh [64][136] half (A converted in-register), sWh [256][136] half
// (cp.async from transposed half W). Stride 136 halves -> bank-bijective
// fragment loads (same scheme as sim kernel).
// Grid: [0,197) vtok, [197,261) ttok, [261,265) vcls (ffma), [265,269) tcls.
// ---------------------------------------------------------------------------
__global__ __launch_bounds__(256) void proj_kernel(
    const float* __restrict__ visual_cls, const float* __restrict__ textual_cls,
    const float* __restrict__ vtokA, const float* __restrict__ ttokA,
    const float* __restrict__ Wv, const float* __restrict__ bv,
    const float* __restrict__ Wt, const float* __restrict__ bt,
    const float* __restrict__ bvt, const float* __restrict__ btt,
    const __half* __restrict__ WvtT, const __half* __restrict__ WttT,
    float* __restrict__ out, __half* __restrict__ vtokC, __half* __restrict__ ttokC)
{
    extern __shared__ float sm[];
    __shared__ float sbias[256];
    __shared__ float rowsq[64 * 5];
    __shared__ float sinv[64];

    const int bid = blockIdx.x;

    if (bid >= 261) {
        float* sA = sm;
        float* sW = sm + 64 * 68;
        if (bid < 265)
            ffma_cls_block(visual_cls, Wv, bv, out, (bid - 261) * 64, sA, sW);
        else
            ffma_cls_block(textual_cls, Wt, bt, out + 16384, (bid - 265) * 64, sA, sW);
        return;
    }

    __half* sAh = (__half*)sm;               // 64 x 136
    __half* sWh = (__half*)sm + 64 * 136;    // 256 x 136

    const float* A;
    const __half* WT;
    const float* bias;
    __half* C;
    int mbase;
    if (bid < 197) { A = vtokA; WT = WvtT; bias = bvt; C = vtokC; mbase = bid * 64; }
    else           { A = ttokA; WT = WttT; bias = btt; C = ttokC; mbase = (bid - 197) * 64; }

    const int tid = threadIdx.x;
    const int lane = tid & 31, w = tid >> 5;
    const int lq = lane >> 2, lr = lane & 3;
    const int vg = w >> 2, nw = w & 3;
    const int rbase = vg * 32;
    const int nb = nw * 64;

    sbias[tid] = bias[tid];

    const unsigned sWu = s2u(sWh);

    float acc[2][8][4] = {};

    for (int k0 = 0; k0 < DD; k0 += 128) {
        // W chunk: 256 n-rows x 128 k halves via cp.async
        // 256 rows x 16 chunks of 16B (= 8 halves) -> 4096 chunks
        #pragma unroll
        for (int it = 0; it < 16; it++) {
            int idx = tid + it * 256;        // 0..4095
            int r = idx >> 4;                // 0..255
            int c16 = idx & 15;              // 16-byte chunk (8 halves)
            cpa16(sWu + (unsigned)(r * 136 + c16 * 8) * 2,
                  WT + (size_t)r * DD + k0 + c16 * 8);
        }
        cpa_commit();
        // A chunk: 64 rows x 128 k, fp32 -> half in-register
        #pragma unroll
        for (int it = 0; it < 8; it++) {
            int idx = tid + it * 256;        // 0..2047
            int r = idx >> 5;                // 0..63
            int c4 = idx & 31;               // float4 unit along k
            float4 v = *(const float4*)(A + (size_t)(mbase + r) * DD + k0 + c4 * 4);
            __half2 h0 = __floats2half2_rn(v.x, v.y);
            __half2 h1 = __floats2half2_rn(v.z, v.w);
            uint2 pk = make_uint2(*(unsigned*)&h0, *(unsigned*)&h1);
            *(uint2*)(sAh + r * 136 + c4 * 4) = pk;
        }
        cpa_wait0();
        __syncthreads();

        #pragma unroll
        for (int ks = 0; ks < 8; ks++) {
            unsigned b0[8], b1[8];
            #pragma unroll
            for (int ng = 0; ng < 8; ng++) {
                const __half* p = sWh + (nb + 8 * ng + lq) * 136 + ks * 16 + 2 * lr;
                b0[ng] = *(const unsigned*)p;
                b1[ng] = *(const unsigned*)(p + 8);
            }
            #pragma unroll
            for (int rg = 0; rg < 2; rg++) {
                const __half* p = sAh + (rbase + 16 * rg + lq) * 136 + ks * 16 + 2 * lr;
                unsigned a0 = *(const unsigned*)p;
                unsigned a1 = *(const unsigned*)(p + 8 * 136);
                unsigned a2 = *(const unsigned*)(p + 8);
                unsigned a3 = *(const unsigned*)(p + 8 * 136 + 8);
                #pragma unroll
                for (int ng = 0; ng < 8; ng++)
                    mma16(acc[rg][ng], a0, a1, a2, a3, b0[ng], b1[ng]);
            }
        }
        __syncthreads();
    }

    // bias
    #pragma unroll
    for (int rg = 0; rg < 2; rg++)
        #pragma unroll
        for (int ng = 0; ng < 8; ng++) {
            int col = nb + 8 * ng + 2 * lr;
            float c0 = sbias[col], c1 = sbias[col + 1];
            acc[rg][ng][0] += c0; acc[rg][ng][1] += c1;
            acc[rg][ng][2] += c0; acc[rg][ng][3] += c1;
        }

    // l2norm: per-row sum of squares
    #pragma unroll
    for (int rg = 0; rg < 2; rg++) {
        float s0 = 0.f, s1 = 0.f;
        #pragma unroll
        for (int ng = 0; ng < 8; ng++) {
            s0 += acc[rg][ng][0] * acc[rg][ng][0] + acc[rg][ng][1] * acc[rg][ng][1];
            s1 += acc[rg][ng][2] * acc[rg][ng][2] + acc[rg][ng][3] * acc[rg][ng][3];
        }
        s0 += __shfl_xor_sync(0xffffffffu, s0, 1);
        s0 += __shfl_xor_sync(0xffffffffu, s0, 2);
        s1 += __shfl_xor_sync(0xffffffffu, s1, 1);
        s1 += __shfl_xor_sync(0xffffffffu, s1, 2);
        if (lr == 0) {
            rowsq[(rbase + 16 * rg + lq) * 5 + nw] = s0;
            rowsq[(rbase + 16 * rg + lq + 8) * 5 + nw] = s1;
        }
    }
    __syncthreads();
    if (tid < 64) {
        float s = rowsq[tid * 5] + rowsq[tid * 5 + 1] + rowsq[tid * 5 + 2] + rowsq[tid * 5 + 3];
        sinv[tid] = 1.0f / fmaxf(sqrtf(s), 1e-12f);
    }
    __syncthreads();

    #pragma unroll
    for (int rg = 0; rg < 2; rg++) {
        int r0 = rbase + 16 * rg + lq;
        float inv0 = sinv[r0], inv1 = sinv[r0 + 8];
        #pragma unroll
        for (int ng = 0; ng < 8; ng++) {
            int col = nb + 8 * ng + 2 * lr;
            __half2 h0 = __floats2half2_rn(acc[rg][ng][0] * inv0, acc[rg][ng][1] * inv0);
            __half2 h1 = __floats2half2_rn(acc[rg][ng][2] * inv1, acc[rg][ng][3] * inv1);
            *(__half2*)(C + (size_t)(mbase + r0) * EE + col) = h0;
            *(__half2*)(C + (size_t)(mbase + r0 + 8) * EE + col) = h1;
        }
    }
}

// ---------------------------------------------------------------------------
// Fused sim kernel (fp16 MMA m16n8k16, f32 accum).
// grid = (qpair=32, b=64), 256 threads (8 warps = 4 v-groups x 2 t-groups).
// Block tile 128v x 128t. sT resident for full K=256; sV streamed per
// (v-tile, k-chunk=128) via cp.async. Pass 2 (rows 128-255): fully-invalid
// v-group (rows 224-255, warps 6/7) skips fragment loads + MMAs; sV loads
// trimmed to rows 0-79 (valid through 196).
// ---------------------------------------------------------------------------
#define SVS 136
#define STS 264

__global__ __launch_bounds__(256, 2) void sim_kernel(
    const __half* __restrict__ vtok, const __half* __restrict__ ttok,
    const int* __restrict__ text_length, float* __restrict__ out)
{
    extern __shared__ __half smh[];
    __half* sV = smh;                  // 128 x SVS
    __half* sT = smh + 128 * SVS;      // 128 x STS (full K)

    __shared__ float t2i_part[4][128];
    __shared__ float t2i_run[128];
    __shared__ float wsum[8];

    const int tid = threadIdx.x;
    const int lane = tid & 31, w = tid >> 5;
    const int lq = lane >> 2, lr = lane & 3;
    const int vb = (w >> 1) * 32;
    const int tb = (w & 1) * 64;
    const int qp = blockIdx.x, b = blockIdx.y;

    const __half* vbase = vtok + (size_t)b * VV * EE;
    const __half* tbase = ttok + (size_t)(qp * 2) * LL * EE;

    unsigned sVu = (unsigned)__cvta_generic_to_shared(sV);
    unsigned sTu = (unsigned)__cvta_generic_to_shared(sT);

    // sT: full 128 t-rows x 256 k (once per block)
    #pragma unroll
    for (int it = 0; it < 16; it++) {
        int idx = tid + it * 256;
        int r = idx >> 5;
        int c8 = idx & 31;
        cpa16(sTu + (unsigned)(r * STS + c8 * 8) * 2, tbase + (size_t)r * EE + c8 * 8);
    }

    float i2t_wsum = 0.0f;

    for (int v0 = 0; v0 < 256; v0 += 128) {
        float acc[2][8][4] = {};
        const bool active = (v0 + vb) < VV;      // whole 32-row group in range?
        const int itmax = (v0 == 0) ? 8 : 5;     // pass 2 needs rows 0..79 only

        for (int kc = 0; kc < 2; kc++) {
            for (int it = 0; it < itmax; it++) {
                int idx = tid + it * 256;
                int r = idx >> 4;
                int c8 = idx & 15;
                int vr = min(v0 + r, VV - 1);
                cpa16(sVu + (unsigned)(r * SVS + c8 * 8) * 2,
                      vbase + (size_t)vr * EE + kc * 128 + c8 * 8);
            }
            cpa_commit();
            cpa_wait0();
            __syncthreads();

            if (active) {
                #pragma unroll
                for (int ks = 0; ks < 8; ks++) {
                    unsigned b0[8], b1[8];
                    #pragma unroll
                    for (int ng = 0; ng < 8; ng++) {
                        const __half* p = sT + (tb + 8 * ng + lq) * STS + kc * 128 + ks * 16 + 2 * lr;
                        b0[ng] = *(const unsigned*)p;
                        b1[ng] = *(const unsigned*)(p + 8);
                    }
                    #pragma unroll
                    for (int rg = 0; rg < 2; rg++) {
                        const __half* p = sV + (vb + 16 * rg + lq) * SVS + ks * 16 + 2 * lr;
                        unsigned a0 = *(const unsigned*)p;
                        unsigned a1 = *(const unsigned*)(p + 8 * SVS);
                        unsigned a2 = *(const unsigned*)(p + 8);
                        unsigned a3 = *(const unsigned*)(p + 8 * SVS + 8);
                        #pragma unroll
                        for (int ng = 0; ng < 8; ng++)
                            mma16(acc[rg][ng], a0, a1, a2, a3, b0[ng], b1[ng]);
                    }
                }
            }
            __syncthreads();
        }

        // ---- i2t: per-v-row max over this warp's 64 t cols (its full q) ----
        float rsum = 0.0f;
        #pragma unroll
        for (int rg = 0; rg < 2; rg++) {
            float m0 = -1e30f, m1 = -1e30f;
            #pragma unroll
            for (int ng = 0; ng < 8; ng++) {
                m0 = fmaxf(m0, fmaxf(acc[rg][ng][0], acc[rg][ng][1]));
                m1 = fmaxf(m1, fmaxf(acc[rg][ng][2], acc[rg][ng][3]));
            }
            m0 = fmaxf(m0, __shfl_xor_sync(0xffffffffu, m0, 1));
            m0 = fmaxf(m0, __shfl_xor_sync(0xffffffffu, m0, 2));
            m1 = fmaxf(m1, __shfl_xor_sync(0xffffffffu, m1, 1));
            m1 = fmaxf(m1, __shfl_xor_sync(0xffffffffu, m1, 2));
            int r0 = v0 + vb + 16 * rg + lq;
            if (lr == 0) {
                if (r0 < VV) rsum += m0;
                if (r0 + 8 < VV) rsum += m1;
            }
        }
        #pragma unroll
        for (int off = 16; off > 0; off >>= 1)
            rsum += __shfl_xor_sync(0xffffffffu, rsum, off);
        i2t_wsum += rsum;

        // ---- t2i: per-t-col max over this warp's 32 v rows (masked) ----
        #pragma unroll
        for (int ng = 0; ng < 8; ng++) {
            float m0 = -1e30f, m1 = -1e30f;
            #pragma unroll
            for (int rg = 0; rg < 2; rg++) {
                int r0 = v0 + vb + 16 * rg + lq;
                if (r0 < VV) {
                    m0 = fmaxf(m0, acc[rg][ng][0]);
                    m1 = fmaxf(m1, acc[rg][ng][1]);
                }
                if (r0 + 8 < VV) {
                    m0 = fmaxf(m0, acc[rg][ng][2]);
                    m1 = fmaxf(m1, acc[rg][ng][3]);
                }
            }
            m0 = fmaxf(m0, __shfl_xor_sync(0xffffffffu, m0, 4));
            m0 = fmaxf(m0, __shfl_xor_sync(0xffffffffu, m0, 8));
            m0 = fmaxf(m0, __shfl_xor_sync(0xffffffffu, m0, 16));
            m1 = fmaxf(m1, __shfl_xor_sync(0xffffffffu, m1, 4));
            m1 = fmaxf(m1, __shfl_xor_sync(0xffffffffu, m1, 8));
            m1 = fmaxf(m1, __shfl_xor_sync(0xffffffffu, m1, 16));
            if (lane < 4) {
                t2i_part[w >> 1][tb + 8 * ng + 2 * lane] = m0;
                t2i_part[w >> 1][tb + 8 * ng + 2 * lane + 1] = m1;
            }
        }
        __syncthreads();
        if (tid < 128) {
            float m = fmaxf(fmaxf(t2i_part[0][tid], t2i_part[1][tid]),
                            fmaxf(t2i_part[2][tid], t2i_part[3][tid]));
            t2i_run[tid] = (v0 == 0) ? m : fmaxf(t2i_run[tid], m);
        }
        __syncthreads();
    }

    if (lane == 0) wsum[w] = i2t_wsum;
    __syncthreads();

    // t2i outputs: warp 0 -> q0, warp 1 -> q1
    if (tid < 64) {
        int w2 = tid >> 5;
        int l2 = tid & 31;
        int len = text_length[b];   // reference quirk: indexed by b
        float s = 0.0f;
        if (l2 < len) s += t2i_run[w2 * 64 + l2];
        if (l2 + 32 < len) s += t2i_run[w2 * 64 + l2 + 32];
        #pragma unroll
        for (int off = 16; off > 0; off >>= 1)
            s += __shfl_xor_sync(0xffffffffu, s, off);
        if (l2 == 0)
            out[36864 + b * 64 + qp * 2 + w2] = s / fmaxf((float)len, 1e-6f);
    }
    // i2t outputs
    if (tid == 128 || tid == 129) {
        int j = tid - 128;
        float s = wsum[j] + wsum[j + 2] + wsum[j + 4] + wsum[j + 6];
        out[32768 + b * 64 + qp * 2 + j] = s / (float)VV;
    }
}

// ---------------------------------------------------------------------------
extern "C" void kernel_launch(void* const* d_in, const int* in_sizes, int n_in,
                              void* d_out, int out_size)
{
    const float* visual_cls     = (const float*)d_in[0];
    const float* textual_cls    = (const float*)d_in[1];
    const float* visual_tokens  = (const float*)d_in[2];
    const float* textual_tokens = (const float*)d_in[3];
    const int*   text_length    = (const int*)  d_in[4];
    const float* Wv  = (const float*)d_in[5];
    const float* bv  = (const float*)d_in[6];
    const float* Wt  = (const float*)d_in[7];
    const float* bt  = (const float*)d_in[8];
    const float* Wvt = (const float*)d_in[9];
    const float* bvt = (const float*)d_in[10];
    const float* Wtt = (const float*)d_in[11];
    const float* btt = (const float*)d_in[12];
    float* out = (float*)d_out;

    __half *vtok = nullptr, *ttok = nullptr, *wvtT = nullptr, *wttT = nullptr;
    cudaGetSymbolAddress((void**)&vtok, g_vtok);
    cudaGetSymbolAddress((void**)&ttok, g_ttok);
    cudaGetSymbolAddress((void**)&wvtT, g_wvtT);
    cudaGetSymbolAddress((void**)&wttT, g_wttT);

    const int proj_smem = (64 * 136 + 256 * 136) * sizeof(__half);        // 87040
    const int sim_smem  = (128 * SVS + 128 * STS) * sizeof(__half);       // 102400
    cudaFuncSetAttribute(proj_kernel, cudaFuncAttributeMaxDynamicSharedMemorySize, proj_smem);
    cudaFuncSetAttribute(sim_kernel,  cudaFuncAttributeMaxDynamicSharedMemorySize, sim_smem);

    wprep_kernel<<<dim3(24, 8, 2), dim3(32, 8)>>>(Wvt, Wtt, wvtT, wttT);

    proj_kernel<<<269, 256, proj_smem>>>(
        visual_cls, textual_cls, visual_tokens, textual_tokens,
        Wv, bv, Wt, bt, bvt, btt, wvtT, wttT,
        out, vtok, ttok);

    sim_kernel<<<dim3(32, 64), 256, sim_smem>>>(vtok, ttok, text_length, out);
}

// round 9
// speedup vs baseline: 8.6605x; 1.0863x over previous
#include <cuda_runtime.h>
#include <cuda_fp16.h>
#include <math.h>
#include <stdint.h>

#define BB 64
#define VV 197
#define LL 64
#define DD 768
#define EE 256

// Scratch: projected + normalized tokens in fp16, transposed half weights
__device__ __align__(16) __half g_vtok[(size_t)BB * VV * EE]; // 6.45 MB
__device__ __align__(16) __half g_ttok[(size_t)BB * LL * EE]; // 2.1 MB
__device__ __align__(16) __half g_wvtT[(size_t)EE * DD];      // [n][k]
__device__ __align__(16) __half g_wttT[(size_t)EE * DD];
__device__ __align__(16) __half g_wvT[(size_t)EE * DD];
__device__ __align__(16) __half g_wtT[(size_t)EE * DD];

// ---------------------------------------------------------------------------
// helpers
// ---------------------------------------------------------------------------
__device__ __forceinline__ void mma16(float* c, unsigned a0, unsigned a1, unsigned a2,
                                      unsigned a3, unsigned b0, unsigned b1) {
    asm volatile(
        "mma.sync.aligned.m16n8k16.row.col.f32.f16.f16.f32 "
        "{%0,%1,%2,%3},{%4,%5,%6,%7},{%8,%9},{%0,%1,%2,%3};\n"
        : "+f"(c[0]), "+f"(c[1]), "+f"(c[2]), "+f"(c[3])
        : "r"(a0), "r"(a1), "r"(a2), "r"(a3), "r"(b0), "r"(b1));
}

__device__ __forceinline__ void cpa16(unsigned s, const void* g) {
    asm volatile("cp.async.cg.shared.global [%0], [%1], 16;" :: "r"(s), "l"(g) : "memory");
}
__device__ __forceinline__ void cpa_commit() {
    asm volatile("cp.async.commit_group;" ::: "memory");
}
__device__ __forceinline__ void cpa_wait0() {
    asm volatile("cp.async.wait_group 0;" ::: "memory");
}
__device__ __forceinline__ unsigned s2u(const void* p) {
    return (unsigned)__cvta_generic_to_shared(p);
}

// ---------------------------------------------------------------------------
// W transpose + fp32->fp16 prepass: W[768][256] -> WT[256][768] half.
// grid (24, 8, 4), block (32, 8). z: 0=Wvt 1=Wtt 2=Wv 3=Wt.
// ---------------------------------------------------------------------------
__global__ void wprep_kernel(const float* __restrict__ Wvt, const float* __restrict__ Wtt,
                             const float* __restrict__ Wv, const float* __restrict__ Wt,
                             __half* __restrict__ WvtT, __half* __restrict__ WttT,
                             __half* __restrict__ WvT, __half* __restrict__ WtT)
{
    __shared__ float t[32][33];
    const float* W;
    __half* WT;
    switch (blockIdx.z) {
        case 0: W = Wvt; WT = WvtT; break;
        case 1: W = Wtt; WT = WttT; break;
        case 2: W = Wv;  WT = WvT;  break;
        default: W = Wt; WT = WtT;  break;
    }
    int kb = blockIdx.x * 32, nb = blockIdx.y * 32;
    int tx = threadIdx.x, ty = threadIdx.y;
    #pragma unroll
    for (int j = 0; j < 4; j++)
        t[ty + 8 * j][tx] = W[(size_t)(kb + ty + 8 * j) * EE + nb + tx];
    __syncthreads();
    #pragma unroll
    for (int j = 0; j < 4; j++)
        WT[(size_t)(nb + ty + 8 * j) * DD + kb + tx] = __float2half(t[tx][ty + 8 * j]);
}

// ---------------------------------------------------------------------------
// Unified projection (fp16 MMA m16n8k16, fp32 accum).
// One block = 64 rows x 256 cols, K=768 in chunks of 128.
// smem: sAh [64][136] half (A converted in-register), sWh [256][136] half
// (cp.async from transposed half W). Stride 136 halves -> bank-bijective.
// Grid: [0,197) vtok (+bias+l2norm, half out), [197,261) ttok (same),
//       261 vcls (+bias, fp32 out), 262 tcls (+bias, fp32 out).
// ---------------------------------------------------------------------------
__global__ __launch_bounds__(256) void proj_kernel(
    const float* __restrict__ visual_cls, const float* __restrict__ textual_cls,
    const float* __restrict__ vtokA, const float* __restrict__ ttokA,
    const float* __restrict__ bv, const float* __restrict__ bt,
    const float* __restrict__ bvt, const float* __restrict__ btt,
    const __half* __restrict__ WvtT, const __half* __restrict__ WttT,
    const __half* __restrict__ WvT, const __half* __restrict__ WtT,
    float* __restrict__ out, __half* __restrict__ vtokC, __half* __restrict__ ttokC)
{
    extern __shared__ float sm[];
    __shared__ float sbias[256];
    __shared__ float rowsq[64 * 5];
    __shared__ float sinv[64];

    __half* sAh = (__half*)sm;               // 64 x 136
    __half* sWh = (__half*)sm + 64 * 136;    // 256 x 136

    const int bid = blockIdx.x;

    const float* A;
    const __half* WT;
    const float* bias;
    __half* C = nullptr;
    float* Cf = nullptr;
    int mbase = 0;
    bool do_norm;
    if (bid < 197)      { A = vtokA;       WT = WvtT; bias = bvt; C = vtokC; mbase = bid * 64;        do_norm = true;  }
    else if (bid < 261) { A = ttokA;       WT = WttT; bias = btt; C = ttokC; mbase = (bid - 197) * 64; do_norm = true;  }
    else if (bid == 261){ A = visual_cls;  WT = WvT;  bias = bv;  Cf = out;              do_norm = false; }
    else                { A = textual_cls; WT = WtT;  bias = bt;  Cf = out + 16384;      do_norm = false; }

    const int tid = threadIdx.x;
    const int lane = tid & 31, w = tid >> 5;
    const int lq = lane >> 2, lr = lane & 3;
    const int vg = w >> 2, nw = w & 3;
    const int rbase = vg * 32;
    const int nb = nw * 64;

    sbias[tid] = bias[tid];

    const unsigned sWu = s2u(sWh);

    float acc[2][8][4] = {};

    for (int k0 = 0; k0 < DD; k0 += 128) {
        // W chunk: 256 n-rows x 128 k halves via cp.async (16 x 16B per row)
        #pragma unroll
        for (int it = 0; it < 16; it++) {
            int idx = tid + it * 256;        // 0..4095
            int r = idx >> 4;                // 0..255
            int c16 = idx & 15;              // 16-byte chunk (8 halves)
            cpa16(sWu + (unsigned)(r * 136 + c16 * 8) * 2,
                  WT + (size_t)r * DD + k0 + c16 * 8);
        }
        cpa_commit();
        // A chunk: 64 rows x 128 k, fp32 -> half in-register
        #pragma unroll
        for (int it = 0; it < 8; it++) {
            int idx = tid + it * 256;        // 0..2047
            int r = idx >> 5;                // 0..63
            int c4 = idx & 31;               // float4 unit along k
            float4 v = *(const float4*)(A + (size_t)(mbase + r) * DD + k0 + c4 * 4);
            __half2 h0 = __floats2half2_rn(v.x, v.y);
            __half2 h1 = __floats2half2_rn(v.z, v.w);
            uint2 pk = make_uint2(*(unsigned*)&h0, *(unsigned*)&h1);
            *(uint2*)(sAh + r * 136 + c4 * 4) = pk;
        }
        cpa_wait0();
        __syncthreads();

        #pragma unroll
        for (int ks = 0; ks < 8; ks++) {
            unsigned b0[8], b1[8];
            #pragma unroll
            for (int ng = 0; ng < 8; ng++) {
                const __half* p = sWh + (nb + 8 * ng + lq) * 136 + ks * 16 + 2 * lr;
                b0[ng] = *(const unsigned*)p;
                b1[ng] = *(const unsigned*)(p + 8);
            }
            #pragma unroll
            for (int rg = 0; rg < 2; rg++) {
                const __half* p = sAh + (rbase + 16 * rg + lq) * 136 + ks * 16 + 2 * lr;
                unsigned a0 = *(const unsigned*)p;
                unsigned a1 = *(const unsigned*)(p + 8 * 136);
                unsigned a2 = *(const unsigned*)(p + 8);
                unsigned a3 = *(const unsigned*)(p + 8 * 136 + 8);
                #pragma unroll
                for (int ng = 0; ng < 8; ng++)
                    mma16(acc[rg][ng], a0, a1, a2, a3, b0[ng], b1[ng]);
            }
        }
        __syncthreads();
    }

    // bias
    #pragma unroll
    for (int rg = 0; rg < 2; rg++)
        #pragma unroll
        for (int ng = 0; ng < 8; ng++) {
            int col = nb + 8 * ng + 2 * lr;
            float c0 = sbias[col], c1 = sbias[col + 1];
            acc[rg][ng][0] += c0; acc[rg][ng][1] += c1;
            acc[rg][ng][2] += c0; acc[rg][ng][3] += c1;
        }

    if (!do_norm) {
        // cls: fp32 store straight to output
        #pragma unroll
        for (int rg = 0; rg < 2; rg++) {
            int r0 = rbase + 16 * rg + lq;
            #pragma unroll
            for (int ng = 0; ng < 8; ng++) {
                int col = nb + 8 * ng + 2 * lr;
                *(float2*)(Cf + (size_t)r0 * EE + col) =
                    make_float2(acc[rg][ng][0], acc[rg][ng][1]);
                *(float2*)(Cf + (size_t)(r0 + 8) * EE + col) =
                    make_float2(acc[rg][ng][2], acc[rg][ng][3]);
            }
        }
        return;
    }

    // l2norm: per-row sum of squares
    #pragma unroll
    for (int rg = 0; rg < 2; rg++) {
        float s0 = 0.f, s1 = 0.f;
        #pragma unroll
        for (int ng = 0; ng < 8; ng++) {
            s0 += acc[rg][ng][0] * acc[rg][ng][0] + acc[rg][ng][1] * acc[rg][ng][1];
            s1 += acc[rg][ng][2] * acc[rg][ng][2] + acc[rg][ng][3] * acc[rg][ng][3];
        }
        s0 += __shfl_xor_sync(0xffffffffu, s0, 1);
        s0 += __shfl_xor_sync(0xffffffffu, s0, 2);
        s1 += __shfl_xor_sync(0xffffffffu, s1, 1);
        s1 += __shfl_xor_sync(0xffffffffu, s1, 2);
        if (lr == 0) {
            rowsq[(rbase + 16 * rg + lq) * 5 + nw] = s0;
            rowsq[(rbase + 16 * rg + lq + 8) * 5 + nw] = s1;
        }
    }
    __syncthreads();
    if (tid < 64) {
        float s = rowsq[tid * 5] + rowsq[tid * 5 + 1] + rowsq[tid * 5 + 2] + rowsq[tid * 5 + 3];
        sinv[tid] = 1.0f / fmaxf(sqrtf(s), 1e-12f);
    }
    __syncthreads();

    #pragma unroll
    for (int rg = 0; rg < 2; rg++) {
        int r0 = rbase + 16 * rg + lq;
        float inv0 = sinv[r0], inv1 = sinv[r0 + 8];
        #pragma unroll
        for (int ng = 0; ng < 8; ng++) {
            int col = nb + 8 * ng + 2 * lr;
            __half2 h0 = __floats2half2_rn(acc[rg][ng][0] * inv0, acc[rg][ng][1] * inv0);
            __half2 h1 = __floats2half2_rn(acc[rg][ng][2] * inv1, acc[rg][ng][3] * inv1);
            *(__half2*)(C + (size_t)(mbase + r0) * EE + col) = h0;
            *(__half2*)(C + (size_t)(mbase + r0 + 8) * EE + col) = h1;
        }
    }
}

// ---------------------------------------------------------------------------
// Fused sim kernel (fp16 MMA m16n8k16, f32 accum).
// grid = (qpair=32, b=64), 256 threads (8 warps = 4 v-groups x 2 t-groups).
// Block tile 128v x 128t. sT resident for full K=256; sV streamed per
// (v-tile, k-chunk=128) via cp.async. Pass 2: fully-invalid v-group skips
// fragment loads + MMAs; sV loads trimmed to rows 0-79.
// ---------------------------------------------------------------------------
#define SVS 136
#define STS 264

__global__ __launch_bounds__(256, 2) void sim_kernel(
    const __half* __restrict__ vtok, const __half* __restrict__ ttok,
    const int* __restrict__ text_length, float* __restrict__ out)
{
    extern __shared__ __half smh[];
    __half* sV = smh;                  // 128 x SVS
    __half* sT = smh + 128 * SVS;      // 128 x STS (full K)

    __shared__ float t2i_part[4][128];
    __shared__ float t2i_run[128];
    __shared__ float wsum[8];

    const int tid = threadIdx.x;
    const int lane = tid & 31, w = tid >> 5;
    const int lq = lane >> 2, lr = lane & 3;
    const int vb = (w >> 1) * 32;
    const int tb = (w & 1) * 64;
    const int qp = blockIdx.x, b = blockIdx.y;

    const __half* vbase = vtok + (size_t)b * VV * EE;
    const __half* tbase = ttok + (size_t)(qp * 2) * LL * EE;

    unsigned sVu = (unsigned)__cvta_generic_to_shared(sV);
    unsigned sTu = (unsigned)__cvta_generic_to_shared(sT);

    // sT: full 128 t-rows x 256 k (once per block)
    #pragma unroll
    for (int it = 0; it < 16; it++) {
        int idx = tid + it * 256;
        int r = idx >> 5;
        int c8 = idx & 31;
        cpa16(sTu + (unsigned)(r * STS + c8 * 8) * 2, tbase + (size_t)r * EE + c8 * 8);
    }

    float i2t_wsum = 0.0f;

    for (int v0 = 0; v0 < 256; v0 += 128) {
        float acc[2][8][4] = {};
        const bool active = (v0 + vb) < VV;
        const int itmax = (v0 == 0) ? 8 : 5;

        for (int kc = 0; kc < 2; kc++) {
            for (int it = 0; it < itmax; it++) {
                int idx = tid + it * 256;
                int r = idx >> 4;
                int c8 = idx & 15;
                int vr = min(v0 + r, VV - 1);
                cpa16(sVu + (unsigned)(r * SVS + c8 * 8) * 2,
                      vbase + (size_t)vr * EE + kc * 128 + c8 * 8);
            }
            cpa_commit();
            cpa_wait0();
            __syncthreads();

            if (active) {
                #pragma unroll
                for (int ks = 0; ks < 8; ks++) {
                    unsigned b0[8], b1[8];
                    #pragma unroll
                    for (int ng = 0; ng < 8; ng++) {
                        const __half* p = sT + (tb + 8 * ng + lq) * STS + kc * 128 + ks * 16 + 2 * lr;
                        b0[ng] = *(const unsigned*)p;
                        b1[ng] = *(const unsigned*)(p + 8);
                    }
                    #pragma unroll
                    for (int rg = 0; rg < 2; rg++) {
                        const __half* p = sV + (vb + 16 * rg + lq) * SVS + ks * 16 + 2 * lr;
                        unsigned a0 = *(const unsigned*)p;
                        unsigned a1 = *(const unsigned*)(p + 8 * SVS);
                        unsigned a2 = *(const unsigned*)(p + 8);
                        unsigned a3 = *(const unsigned*)(p + 8 * SVS + 8);
                        #pragma unroll
                        for (int ng = 0; ng < 8; ng++)
                            mma16(acc[rg][ng], a0, a1, a2, a3, b0[ng], b1[ng]);
                    }
                }
            }
            __syncthreads();
        }

        // ---- i2t: per-v-row max over this warp's 64 t cols (its full q) ----
        float rsum = 0.0f;
        #pragma unroll
        for (int rg = 0; rg < 2; rg++) {
            float m0 = -1e30f, m1 = -1e30f;
            #pragma unroll
            for (int ng = 0; ng < 8; ng++) {
                m0 = fmaxf(m0, fmaxf(acc[rg][ng][0], acc[rg][ng][1]));
                m1 = fmaxf(m1, fmaxf(acc[rg][ng][2], acc[rg][ng][3]));
            }
            m0 = fmaxf(m0, __shfl_xor_sync(0xffffffffu, m0, 1));
            m0 = fmaxf(m0, __shfl_xor_sync(0xffffffffu, m0, 2));
            m1 = fmaxf(m1, __shfl_xor_sync(0xffffffffu, m1, 1));
            m1 = fmaxf(m1, __shfl_xor_sync(0xffffffffu, m1, 2));
            int r0 = v0 + vb + 16 * rg + lq;
            if (lr == 0) {
                if (r0 < VV) rsum += m0;
                if (r0 + 8 < VV) rsum += m1;
            }
        }
        #pragma unroll
        for (int off = 16; off > 0; off >>= 1)
            rsum += __shfl_xor_sync(0xffffffffu, rsum, off);
        i2t_wsum += rsum;

        // ---- t2i: per-t-col max over this warp's 32 v rows (masked) ----
        #pragma unroll
        for (int ng = 0; ng < 8; ng++) {
            float m0 = -1e30f, m1 = -1e30f;
            #pragma unroll
            for (int rg = 0; rg < 2; rg++) {
                int r0 = v0 + vb + 16 * rg + lq;
                if (r0 < VV) {
                    m0 = fmaxf(m0, acc[rg][ng][0]);
                    m1 = fmaxf(m1, acc[rg][ng][1]);
                }
                if (r0 + 8 < VV) {
                    m0 = fmaxf(m0, acc[rg][ng][2]);
                    m1 = fmaxf(m1, acc[rg][ng][3]);
                }
            }
            m0 = fmaxf(m0, __shfl_xor_sync(0xffffffffu, m0, 4));
            m0 = fmaxf(m0, __shfl_xor_sync(0xffffffffu, m0, 8));
            m0 = fmaxf(m0, __shfl_xor_sync(0xffffffffu, m0, 16));
            m1 = fmaxf(m1, __shfl_xor_sync(0xffffffffu, m1, 4));
            m1 = fmaxf(m1, __shfl_xor_sync(0xffffffffu, m1, 8));
            m1 = fmaxf(m1, __shfl_xor_sync(0xffffffffu, m1, 16));
            if (lane < 4) {
                t2i_part[w >> 1][tb + 8 * ng + 2 * lane] = m0;
                t2i_part[w >> 1][tb + 8 * ng + 2 * lane + 1] = m1;
            }
        }
        __syncthreads();
        if (tid < 128) {
            float m = fmaxf(fmaxf(t2i_part[0][tid], t2i_part[1][tid]),
                            fmaxf(t2i_part[2][tid], t2i_part[3][tid]));
            t2i_run[tid] = (v0 == 0) ? m : fmaxf(t2i_run[tid], m);
        }
        __syncthreads();
    }

    if (lane == 0) wsum[w] = i2t_wsum;
    __syncthreads();

    // t2i outputs: warp 0 -> q0, warp 1 -> q1
    if (tid < 64) {
        int w2 = tid >> 5;
        int l2 = tid & 31;
        int len = text_length[b];   // reference quirk: indexed by b
        float s = 0.0f;
        if (l2 < len) s += t2i_run[w2 * 64 + l2];
        if (l2 + 32 < len) s += t2i_run[w2 * 64 + l2 + 32];
        #pragma unroll
        for (int off = 16; off > 0; off >>= 1)
            s += __shfl_xor_sync(0xffffffffu, s, off);
        if (l2 == 0)
            out[36864 + b * 64 + qp * 2 + w2] = s / fmaxf((float)len, 1e-6f);
    }
    // i2t outputs
    if (tid == 128 || tid == 129) {
        int j = tid - 128;
        float s = wsum[j] + wsum[j + 2] + wsum[j + 4] + wsum[j + 6];
        out[32768 + b * 64 + qp * 2 + j] = s / (float)VV;
    }
}

// ---------------------------------------------------------------------------
extern "C" void kernel_launch(void* const* d_in, const int* in_sizes, int n_in,
                              void* d_out, int out_size)
{
    const float* visual_cls     = (const float*)d_in[0];
    const float* textual_cls    = (const float*)d_in[1];
    const float* visual_tokens  = (const float*)d_in[2];
    const float* textual_tokens = (const float*)d_in[3];
    const int*   text_length    = (const int*)  d_in[4];
    const float* Wv  = (const float*)d_in[5];
    const float* bv  = (const float*)d_in[6];
    const float* Wt  = (const float*)d_in[7];
    const float* bt  = (const float*)d_in[8];
    const float* Wvt = (const float*)d_in[9];
    const float* bvt = (const float*)d_in[10];
    const float* Wtt = (const float*)d_in[11];
    const float* btt = (const float*)d_in[12];
    float* out = (float*)d_out;

    __half *vtok, *ttok, *wvtT, *wttT, *wvT, *wtT;
    cudaGetSymbolAddress((void**)&vtok, g_vtok);
    cudaGetSymbolAddress((void**)&ttok, g_ttok);
    cudaGetSymbolAddress((void**)&wvtT, g_wvtT);
    cudaGetSymbolAddress((void**)&wttT, g_wttT);
    cudaGetSymbolAddress((void**)&wvT, g_wvT);
    cudaGetSymbolAddress((void**)&wtT, g_wtT);

    const int proj_smem = (64 * 136 + 256 * 136) * sizeof(__half);        // 87040
    const int sim_smem  = (128 * SVS + 128 * STS) * sizeof(__half);       // 102400
    cudaFuncSetAttribute(proj_kernel, cudaFuncAttributeMaxDynamicSharedMemorySize, proj_smem);
    cudaFuncSetAttribute(sim_kernel,  cudaFuncAttributeMaxDynamicSharedMemorySize, sim_smem);

    wprep_kernel<<<dim3(24, 8, 4), dim3(32, 8)>>>(Wvt, Wtt, Wv, Wt, wvtT, wttT, wvT, wtT);

    proj_kernel<<<263, 256, proj_smem>>>(
        visual_cls, textual_cls, visual_tokens, textual_tokens,
        bv, bt, bvt, btt, wvtT, wttT, wvT, wtT,
        out, vtok, ttok);

    sim_kernel<<<dim3(32, 64), 256, sim_smem>>>(vtok, ttok, text_length, out);
}

// round 10
// speedup vs baseline: 8.9378x; 1.0320x over previous
#include <cuda_runtime.h>
#include <cuda_fp16.h>
#include <math.h>
#include <stdint.h>

#define BB 64
#define VV 197
#define LL 64
#define DD 768
#define EE 256

// Scratch: projected + normalized tokens in fp16, transposed half weights
__device__ __align__(16) __half g_vtok[(size_t)BB * VV * EE]; // 6.45 MB
__device__ __align__(16) __half g_ttok[(size_t)BB * LL * EE]; // 2.1 MB
__device__ __align__(16) __half g_wvtT[(size_t)EE * DD];      // [n][k]
__device__ __align__(16) __half g_wttT[(size_t)EE * DD];
__device__ __align__(16) __half g_wvT[(size_t)EE * DD];
__device__ __align__(16) __half g_wtT[(size_t)EE * DD];

// ---------------------------------------------------------------------------
// helpers
// ---------------------------------------------------------------------------
__device__ __forceinline__ void mma16(float* c, unsigned a0, unsigned a1, unsigned a2,
                                      unsigned a3, unsigned b0, unsigned b1) {
    asm volatile(
        "mma.sync.aligned.m16n8k16.row.col.f32.f16.f16.f32 "
        "{%0,%1,%2,%3},{%4,%5,%6,%7},{%8,%9},{%0,%1,%2,%3};\n"
        : "+f"(c[0]), "+f"(c[1]), "+f"(c[2]), "+f"(c[3])
        : "r"(a0), "r"(a1), "r"(a2), "r"(a3), "r"(b0), "r"(b1));
}

__device__ __forceinline__ void cpa16(unsigned s, const void* g) {
    asm volatile("cp.async.cg.shared.global [%0], [%1], 16;" :: "r"(s), "l"(g) : "memory");
}
__device__ __forceinline__ void cpa_commit() {
    asm volatile("cp.async.commit_group;" ::: "memory");
}
__device__ __forceinline__ void cpa_wait0() {
    asm volatile("cp.async.wait_group 0;" ::: "memory");
}
__device__ __forceinline__ unsigned s2u(const void* p) {
    return (unsigned)__cvta_generic_to_shared(p);
}

// ---------------------------------------------------------------------------
// W transpose + fp32->fp16 prepass: W[768][256] -> WT[256][768] half.
// grid (24, 8, 4), block (32, 8). z: 0=Wvt 1=Wtt 2=Wv 3=Wt.
// ---------------------------------------------------------------------------
__global__ void wprep_kernel(const float* __restrict__ Wvt, const float* __restrict__ Wtt,
                             const float* __restrict__ Wv, const float* __restrict__ Wt,
                             __half* __restrict__ WvtT, __half* __restrict__ WttT,
                             __half* __restrict__ WvT, __half* __restrict__ WtT)
{
    __shared__ float t[32][33];
    const float* W;
    __half* WT;
    switch (blockIdx.z) {
        case 0: W = Wvt; WT = WvtT; break;
        case 1: W = Wtt; WT = WttT; break;
        case 2: W = Wv;  WT = WvT;  break;
        default: W = Wt; WT = WtT;  break;
    }
    int kb = blockIdx.x * 32, nb = blockIdx.y * 32;
    int tx = threadIdx.x, ty = threadIdx.y;
    #pragma unroll
    for (int j = 0; j < 4; j++)
        t[ty + 8 * j][tx] = W[(size_t)(kb + ty + 8 * j) * EE + nb + tx];
    __syncthreads();
    #pragma unroll
    for (int j = 0; j < 4; j++)
        WT[(size_t)(nb + ty + 8 * j) * DD + kb + tx] = __float2half(t[tx][ty + 8 * j]);
}

// ---------------------------------------------------------------------------
// Unified projection (fp16 MMA m16n8k16, fp32 accum), 2 blocks/SM -> 1 wave.
// One block = 64 rows x 256 cols, K=768 in chunks of 128.
// smem: sAh [64][136] half (A converted in-register), sWh [256][136] half
// (cp.async from transposed half W). Stride 136 halves -> bank-bijective.
// Grid: [0,197) vtok (+bias+l2norm, half out), [197,261) ttok (same),
//       261 vcls (+bias, fp32 out), 262 tcls (+bias, fp32 out).
// ---------------------------------------------------------------------------
__global__ __launch_bounds__(256, 2) void proj_kernel(
    const float* __restrict__ visual_cls, const float* __restrict__ textual_cls,
    const float* __restrict__ vtokA, const float* __restrict__ ttokA,
    const float* __restrict__ bv, const float* __restrict__ bt,
    const float* __restrict__ bvt, const float* __restrict__ btt,
    const __half* __restrict__ WvtT, const __half* __restrict__ WttT,
    const __half* __restrict__ WvT, const __half* __restrict__ WtT,
    float* __restrict__ out, __half* __restrict__ vtokC, __half* __restrict__ ttokC)
{
    extern __shared__ float sm[];
    __shared__ float sbias[256];
    __shared__ float rowsq[64 * 5];
    __shared__ float sinv[64];

    __half* sAh = (__half*)sm;               // 64 x 136
    __half* sWh = (__half*)sm + 64 * 136;    // 256 x 136

    const int bid = blockIdx.x;

    const float* A;
    const __half* WT;
    const float* bias;
    __half* C = nullptr;
    float* Cf = nullptr;
    int mbase = 0;
    bool do_norm;
    if (bid < 197)      { A = vtokA;       WT = WvtT; bias = bvt; C = vtokC; mbase = bid * 64;        do_norm = true;  }
    else if (bid < 261) { A = ttokA;       WT = WttT; bias = btt; C = ttokC; mbase = (bid - 197) * 64; do_norm = true;  }
    else if (bid == 261){ A = visual_cls;  WT = WvT;  bias = bv;  Cf = out;              do_norm = false; }
    else                { A = textual_cls; WT = WtT;  bias = bt;  Cf = out + 16384;      do_norm = false; }

    const int tid = threadIdx.x;
    const int lane = tid & 31, w = tid >> 5;
    const int lq = lane >> 2, lr = lane & 3;
    const int vg = w >> 2, nw = w & 3;
    const int rbase = vg * 32;
    const int nb = nw * 64;

    sbias[tid] = bias[tid];

    const unsigned sWu = s2u(sWh);

    float acc[2][8][4] = {};

    for (int k0 = 0; k0 < DD; k0 += 128) {
        // W chunk: 256 n-rows x 128 k halves via cp.async (16 x 16B per row)
        #pragma unroll
        for (int it = 0; it < 16; it++) {
            int idx = tid + it * 256;        // 0..4095
            int r = idx >> 4;                // 0..255
            int c16 = idx & 15;              // 16-byte chunk (8 halves)
            cpa16(sWu + (unsigned)(r * 136 + c16 * 8) * 2,
                  WT + (size_t)r * DD + k0 + c16 * 8);
        }
        cpa_commit();
        // A chunk: 64 rows x 128 k, fp32 -> half in-register
        #pragma unroll
        for (int it = 0; it < 8; it++) {
            int idx = tid + it * 256;        // 0..2047
            int r = idx >> 5;                // 0..63
            int c4 = idx & 31;               // float4 unit along k
            float4 v = *(const float4*)(A + (size_t)(mbase + r) * DD + k0 + c4 * 4);
            __half2 h0 = __floats2half2_rn(v.x, v.y);
            __half2 h1 = __floats2half2_rn(v.z, v.w);
            uint2 pk = make_uint2(*(unsigned*)&h0, *(unsigned*)&h1);
            *(uint2*)(sAh + r * 136 + c4 * 4) = pk;
        }
        cpa_wait0();
        __syncthreads();

        #pragma unroll
        for (int ks = 0; ks < 8; ks++) {
            unsigned b0[8], b1[8];
            #pragma unroll
            for (int ng = 0; ng < 8; ng++) {
                const __half* p = sWh + (nb + 8 * ng + lq) * 136 + ks * 16 + 2 * lr;
                b0[ng] = *(const unsigned*)p;
                b1[ng] = *(const unsigned*)(p + 8);
            }
            #pragma unroll
            for (int rg = 0; rg < 2; rg++) {
                const __half* p = sAh + (rbase + 16 * rg + lq) * 136 + ks * 16 + 2 * lr;
                unsigned a0 = *(const unsigned*)p;
                unsigned a1 = *(const unsigned*)(p + 8 * 136);
                unsigned a2 = *(const unsigned*)(p + 8);
                unsigned a3 = *(const unsigned*)(p + 8 * 136 + 8);
                #pragma unroll
                for (int ng = 0; ng < 8; ng++)
                    mma16(acc[rg][ng], a0, a1, a2, a3, b0[ng], b1[ng]);
            }
        }
        __syncthreads();
    }

    // bias
    #pragma unroll
    for (int rg = 0; rg < 2; rg++)
        #pragma unroll
        for (int ng = 0; ng < 8; ng++) {
            int col = nb + 8 * ng + 2 * lr;
            float c0 = sbias[col], c1 = sbias[col + 1];
            acc[rg][ng][0] += c0; acc[rg][ng][1] += c1;
            acc[rg][ng][2] += c0; acc[rg][ng][3] += c1;
        }

    if (!do_norm) {
        // cls: fp32 store straight to output
        #pragma unroll
        for (int rg = 0; rg < 2; rg++) {
            int r0 = rbase + 16 * rg + lq;
            #pragma unroll
            for (int ng = 0; ng < 8; ng++) {
                int col = nb + 8 * ng + 2 * lr;
                *(float2*)(Cf + (size_t)r0 * EE + col) =
                    make_float2(acc[rg][ng][0], acc[rg][ng][1]);
                *(float2*)(Cf + (size_t)(r0 + 8) * EE + col) =
                    make_float2(acc[rg][ng][2], acc[rg][ng][3]);
            }
        }
        return;
    }

    // l2norm: per-row sum of squares
    #pragma unroll
    for (int rg = 0; rg < 2; rg++) {
        float s0 = 0.f, s1 = 0.f;
        #pragma unroll
        for (int ng = 0; ng < 8; ng++) {
            s0 += acc[rg][ng][0] * acc[rg][ng][0] + acc[rg][ng][1] * acc[rg][ng][1];
            s1 += acc[rg][ng][2] * acc[rg][ng][2] + acc[rg][ng][3] * acc[rg][ng][3];
        }
        s0 += __shfl_xor_sync(0xffffffffu, s0, 1);
        s0 += __shfl_xor_sync(0xffffffffu, s0, 2);
        s1 += __shfl_xor_sync(0xffffffffu, s1, 1);
        s1 += __shfl_xor_sync(0xffffffffu, s1, 2);
        if (lr == 0) {
            rowsq[(rbase + 16 * rg + lq) * 5 + nw] = s0;
            rowsq[(rbase + 16 * rg + lq + 8) * 5 + nw] = s1;
        }
    }
    __syncthreads();
    if (tid < 64) {
        float s = rowsq[tid * 5] + rowsq[tid * 5 + 1] + rowsq[tid * 5 + 2] + rowsq[tid * 5 + 3];
        sinv[tid] = 1.0f / fmaxf(sqrtf(s), 1e-12f);
    }
    __syncthreads();

    #pragma unroll
    for (int rg = 0; rg < 2; rg++) {
        int r0 = rbase + 16 * rg + lq;
        float inv0 = sinv[r0], inv1 = sinv[r0 + 8];
        #pragma unroll
        for (int ng = 0; ng < 8; ng++) {
            int col = nb + 8 * ng + 2 * lr;
            __half2 h0 = __floats2half2_rn(acc[rg][ng][0] * inv0, acc[rg][ng][1] * inv0);
            __half2 h1 = __floats2half2_rn(acc[rg][ng][2] * inv1, acc[rg][ng][3] * inv1);
            *(__half2*)(C + (size_t)(mbase + r0) * EE + col) = h0;
            *(__half2*)(C + (size_t)(mbase + r0 + 8) * EE + col) = h1;
        }
    }
}

// ---------------------------------------------------------------------------
// Fused sim kernel (fp16 MMA m16n8k16, f32 accum).
// grid = (qpair=32, b=64), 256 threads (8 warps = 4 v-groups x 2 t-groups).
// Block tile 128v x 128t. sT resident for full K=256; sV streamed per
// (v-tile, k-chunk=128) via cp.async. Pass 2: fully-invalid v-group skips
// fragment loads + MMAs; sV loads trimmed to rows 0-79.
// ---------------------------------------------------------------------------
#define SVS 136
#define STS 264

__global__ __launch_bounds__(256, 2) void sim_kernel(
    const __half* __restrict__ vtok, const __half* __restrict__ ttok,
    const int* __restrict__ text_length, float* __restrict__ out)
{
    extern __shared__ __half smh[];
    __half* sV = smh;                  // 128 x SVS
    __half* sT = smh + 128 * SVS;      // 128 x STS (full K)

    __shared__ float t2i_part[4][128];
    __shared__ float t2i_run[128];
    __shared__ float wsum[8];

    const int tid = threadIdx.x;
    const int lane = tid & 31, w = tid >> 5;
    const int lq = lane >> 2, lr = lane & 3;
    const int vb = (w >> 1) * 32;
    const int tb = (w & 1) * 64;
    const int qp = blockIdx.x, b = blockIdx.y;

    const __half* vbase = vtok + (size_t)b * VV * EE;
    const __half* tbase = ttok + (size_t)(qp * 2) * LL * EE;

    unsigned sVu = (unsigned)__cvta_generic_to_shared(sV);
    unsigned sTu = (unsigned)__cvta_generic_to_shared(sT);

    // sT: full 128 t-rows x 256 k (once per block)
    #pragma unroll
    for (int it = 0; it < 16; it++) {
        int idx = tid + it * 256;
        int r = idx >> 5;
        int c8 = idx & 31;
        cpa16(sTu + (unsigned)(r * STS + c8 * 8) * 2, tbase + (size_t)r * EE + c8 * 8);
    }

    float i2t_wsum = 0.0f;

    for (int v0 = 0; v0 < 256; v0 += 128) {
        float acc[2][8][4] = {};
        const bool active = (v0 + vb) < VV;
        const int itmax = (v0 == 0) ? 8 : 5;

        for (int kc = 0; kc < 2; kc++) {
            for (int it = 0; it < itmax; it++) {
                int idx = tid + it * 256;
                int r = idx >> 4;
                int c8 = idx & 15;
                int vr = min(v0 + r, VV - 1);
                cpa16(sVu + (unsigned)(r * SVS + c8 * 8) * 2,
                      vbase + (size_t)vr * EE + kc * 128 + c8 * 8);
            }
            cpa_commit();
            cpa_wait0();
            __syncthreads();

            if (active) {
                #pragma unroll
                for (int ks = 0; ks < 8; ks++) {
                    unsigned b0[8], b1[8];
                    #pragma unroll
                    for (int ng = 0; ng < 8; ng++) {
                        const __half* p = sT + (tb + 8 * ng + lq) * STS + kc * 128 + ks * 16 + 2 * lr;
                        b0[ng] = *(const unsigned*)p;
                        b1[ng] = *(const unsigned*)(p + 8);
                    }
                    #pragma unroll
                    for (int rg = 0; rg < 2; rg++) {
                        const __half* p = sV + (vb + 16 * rg + lq) * SVS + ks * 16 + 2 * lr;
                        unsigned a0 = *(const unsigned*)p;
                        unsigned a1 = *(const unsigned*)(p + 8 * SVS);
                        unsigned a2 = *(const unsigned*)(p + 8);
                        unsigned a3 = *(const unsigned*)(p + 8 * SVS + 8);
                        #pragma unroll
                        for (int ng = 0; ng < 8; ng++)
                            mma16(acc[rg][ng], a0, a1, a2, a3, b0[ng], b1[ng]);
                    }
                }
            }
            __syncthreads();
        }

        // ---- i2t: per-v-row max over this warp's 64 t cols (its full q) ----
        float rsum = 0.0f;
        #pragma unroll
        for (int rg = 0; rg < 2; rg++) {
            float m0 = -1e30f, m1 = -1e30f;
            #pragma unroll
            for (int ng = 0; ng < 8; ng++) {
                m0 = fmaxf(m0, fmaxf(acc[rg][ng][0], acc[rg][ng][1]));
                m1 = fmaxf(m1, fmaxf(acc[rg][ng][2], acc[rg][ng][3]));
            }
            m0 = fmaxf(m0, __shfl_xor_sync(0xffffffffu, m0, 1));
            m0 = fmaxf(m0, __shfl_xor_sync(0xffffffffu, m0, 2));
            m1 = fmaxf(m1, __shfl_xor_sync(0xffffffffu, m1, 1));
            m1 = fmaxf(m1, __shfl_xor_sync(0xffffffffu, m1, 2));
            int r0 = v0 + vb + 16 * rg + lq;
            if (lr == 0) {
                if (r0 < VV) rsum += m0;
                if (r0 + 8 < VV) rsum += m1;
            }
        }
        #pragma unroll
        for (int off = 16; off > 0; off >>= 1)
            rsum += __shfl_xor_sync(0xffffffffu, rsum, off);
        i2t_wsum += rsum;

        // ---- t2i: per-t-col max over this warp's 32 v rows (masked) ----
        #pragma unroll
        for (int ng = 0; ng < 8; ng++) {
            float m0 = -1e30f, m1 = -1e30f;
            #pragma unroll
            for (int rg = 0; rg < 2; rg++) {
                int r0 = v0 + vb + 16 * rg + lq;
                if (r0 < VV) {
                    m0 = fmaxf(m0, acc[rg][ng][0]);
                    m1 = fmaxf(m1, acc[rg][ng][1]);
                }
                if (r0 + 8 < VV) {
                    m0 = fmaxf(m0, acc[rg][ng][2]);
                    m1 = fmaxf(m1, acc[rg][ng][3]);
                }
            }
            m0 = fmaxf(m0, __shfl_xor_sync(0xffffffffu, m0, 4));
            m0 = fmaxf(m0, __shfl_xor_sync(0xffffffffu, m0, 8));
            m0 = fmaxf(m0, __shfl_xor_sync(0xffffffffu, m0, 16));
            m1 = fmaxf(m1, __shfl_xor_sync(0xffffffffu, m1, 4));
            m1 = fmaxf(m1, __shfl_xor_sync(0xffffffffu, m1, 8));
            m1 = fmaxf(m1, __shfl_xor_sync(0xffffffffu, m1, 16));
            if (lane < 4) {
                t2i_part[w >> 1][tb + 8 * ng + 2 * lane] = m0;
                t2i_part[w >> 1][tb + 8 * ng + 2 * lane + 1] = m1;
            }
        }
        __syncthreads();
        if (tid < 128) {
            float m = fmaxf(fmaxf(t2i_part[0][tid], t2i_part[1][tid]),
                            fmaxf(t2i_part[2][tid], t2i_part[3][tid]));
            t2i_run[tid] = (v0 == 0) ? m : fmaxf(t2i_run[tid], m);
        }
        __syncthreads();
    }

    if (lane == 0) wsum[w] = i2t_wsum;
    __syncthreads();

    // t2i outputs: warp 0 -> q0, warp 1 -> q1
    if (tid < 64) {
        int w2 = tid >> 5;
        int l2 = tid & 31;
        int len = text_length[b];   // reference quirk: indexed by b
        float s = 0.0f;
        if (l2 < len) s += t2i_run[w2 * 64 + l2];
        if (l2 + 32 < len) s += t2i_run[w2 * 64 + l2 + 32];
        #pragma unroll
        for (int off = 16; off > 0; off >>= 1)
            s += __shfl_xor_sync(0xffffffffu, s, off);
        if (l2 == 0)
            out[36864 + b * 64 + qp * 2 + w2] = s / fmaxf((float)len, 1e-6f);
    }
    // i2t outputs
    if (tid == 128 || tid == 129) {
        int j = tid - 128;
        float s = wsum[j] + wsum[j + 2] + wsum[j + 4] + wsum[j + 6];
        out[32768 + b * 64 + qp * 2 + j] = s / (float)VV;
    }
}

// ---------------------------------------------------------------------------
extern "C" void kernel_launch(void* const* d_in, const int* in_sizes, int n_in,
                              void* d_out, int out_size)
{
    const float* visual_cls     = (const float*)d_in[0];
    const float* textual_cls    = (const float*)d_in[1];
    const float* visual_tokens  = (const float*)d_in[2];
    const float* textual_tokens = (const float*)d_in[3];
    const int*   text_length    = (const int*)  d_in[4];
    const float* Wv  = (const float*)d_in[5];
    const float* bv  = (const float*)d_in[6];
    const float* Wt  = (const float*)d_in[7];
    const float* bt  = (const float*)d_in[8];
    const float* Wvt = (const float*)d_in[9];
    const float* bvt = (const float*)d_in[10];
    const float* Wtt = (const float*)d_in[11];
    const float* btt = (const float*)d_in[12];
    float* out = (float*)d_out;

    __half *vtok, *ttok, *wvtT, *wttT, *wvT, *wtT;
    cudaGetSymbolAddress((void**)&vtok, g_vtok);
    cudaGetSymbolAddress((void**)&ttok, g_ttok);
    cudaGetSymbolAddress((void**)&wvtT, g_wvtT);
    cudaGetSymbolAddress((void**)&wttT, g_wttT);
    cudaGetSymbolAddress((void**)&wvT, g_wvT);
    cudaGetSymbolAddress((void**)&wtT, g_wtT);

    const int proj_smem = (64 * 136 + 256 * 136) * sizeof(__half);        // 87040
    const int sim_smem  = (128 * SVS + 128 * STS) * sizeof(__half);       // 102400
    cudaFuncSetAttribute(proj_kernel, cudaFuncAttributeMaxDynamicSharedMemorySize, proj_smem);
    cudaFuncSetAttribute(sim_kernel,  cudaFuncAttributeMaxDynamicSharedMemorySize, sim_smem);

    wprep_kernel<<<dim3(24, 8, 4), dim3(32, 8)>>>(Wvt, Wtt, Wv, Wt, wvtT, wttT, wvT, wtT);

    proj_kernel<<<263, 256, proj_smem>>>(
        visual_cls, textual_cls, visual_tokens, textual_tokens,
        bv, bt, bvt, btt, wvtT, wttT, wvT, wtT,
        out, vtok, ttok);

    sim_kernel<<<dim3(32, 64), 256, sim_smem>>>(vtok, ttok, text_length, out);
}

// round 11
// speedup vs baseline: 9.0063x; 1.0077x over previous
#include <cuda_runtime.h>
#include <cuda_fp16.h>
#include <math.h>
#include <stdint.h>

#define BB 64
#define VV 197
#define LL 64
#define DD 768
#define EE 256

// Scratch: projected + normalized tokens in fp16, transposed half weights
__device__ __align__(16) __half g_vtok[(size_t)BB * VV * EE]; // 6.45 MB
__device__ __align__(16) __half g_ttok[(size_t)BB * LL * EE]; // 2.1 MB
__device__ __align__(16) __half g_wvtT[(size_t)EE * DD];      // [n][k]
__device__ __align__(16) __half g_wttT[(size_t)EE * DD];
__device__ __align__(16) __half g_wvT[(size_t)EE * DD];
__device__ __align__(16) __half g_wtT[(size_t)EE * DD];

// ---------------------------------------------------------------------------
// helpers
// ---------------------------------------------------------------------------
__device__ __forceinline__ void mma16(float* c, unsigned a0, unsigned a1, unsigned a2,
                                      unsigned a3, unsigned b0, unsigned b1) {
    asm volatile(
        "mma.sync.aligned.m16n8k16.row.col.f32.f16.f16.f32 "
        "{%0,%1,%2,%3},{%4,%5,%6,%7},{%8,%9},{%0,%1,%2,%3};\n"
        : "+f"(c[0]), "+f"(c[1]), "+f"(c[2]), "+f"(c[3])
        : "r"(a0), "r"(a1), "r"(a2), "r"(a3), "r"(b0), "r"(b1));
}

__device__ __forceinline__ void cpa16(unsigned s, const void* g) {
    asm volatile("cp.async.cg.shared.global [%0], [%1], 16;" :: "r"(s), "l"(g) : "memory");
}
__device__ __forceinline__ void cpa_commit() {
    asm volatile("cp.async.commit_group;" ::: "memory");
}
__device__ __forceinline__ void cpa_wait0() {
    asm volatile("cp.async.wait_group 0;" ::: "memory");
}
__device__ __forceinline__ unsigned s2u(const void* p) {
    return (unsigned)__cvta_generic_to_shared(p);
}

// ---------------------------------------------------------------------------
// W transpose + fp32->fp16 prepass: W[768][256] -> WT[256][768] half.
// grid (24, 8, 4), block (32, 8). z: 0=Wvt 1=Wtt 2=Wv 3=Wt.
// ---------------------------------------------------------------------------
__global__ void wprep_kernel(const float* __restrict__ Wvt, const float* __restrict__ Wtt,
                             const float* __restrict__ Wv, const float* __restrict__ Wt,
                             __half* __restrict__ WvtT, __half* __restrict__ WttT,
                             __half* __restrict__ WvT, __half* __restrict__ WtT)
{
    __shared__ float t[32][33];
    const float* W;
    __half* WT;
    switch (blockIdx.z) {
        case 0: W = Wvt; WT = WvtT; break;
        case 1: W = Wtt; WT = WttT; break;
        case 2: W = Wv;  WT = WvT;  break;
        default: W = Wt; WT = WtT;  break;
    }
    int kb = blockIdx.x * 32, nb = blockIdx.y * 32;
    int tx = threadIdx.x, ty = threadIdx.y;
    #pragma unroll
    for (int j = 0; j < 4; j++)
        t[ty + 8 * j][tx] = W[(size_t)(kb + ty + 8 * j) * EE + nb + tx];
    __syncthreads();
    #pragma unroll
    for (int j = 0; j < 4; j++)
        WT[(size_t)(nb + ty + 8 * j) * DD + kb + tx] = __float2half(t[tx][ty + 8 * j]);
}

// ---------------------------------------------------------------------------
// Unified projection (fp16 MMA m16n8k16, fp32 accum), 2 blocks/SM.
// One block = 64 rows x 256 cols, K=768 in chunks of 128.
// Grid: [0,197) vtok (+bias+l2norm, half out), [197,261) ttok (same),
//       261 vcls (+bias, fp32 out), 262 tcls (+bias, fp32 out).
// ---------------------------------------------------------------------------
__global__ __launch_bounds__(256, 2) void proj_kernel(
    const float* __restrict__ visual_cls, const float* __restrict__ textual_cls,
    const float* __restrict__ vtokA, const float* __restrict__ ttokA,
    const float* __restrict__ bv, const float* __restrict__ bt,
    const float* __restrict__ bvt, const float* __restrict__ btt,
    const __half* __restrict__ WvtT, const __half* __restrict__ WttT,
    const __half* __restrict__ WvT, const __half* __restrict__ WtT,
    float* __restrict__ out, __half* __restrict__ vtokC, __half* __restrict__ ttokC)
{
    extern __shared__ float sm[];
    __shared__ float sbias[256];
    __shared__ float rowsq[64 * 5];
    __shared__ float sinv[64];

    __half* sAh = (__half*)sm;               // 64 x 136
    __half* sWh = (__half*)sm + 64 * 136;    // 256 x 136

    const int bid = blockIdx.x;

    const float* A;
    const __half* WT;
    const float* bias;
    __half* C = nullptr;
    float* Cf = nullptr;
    int mbase = 0;
    bool do_norm;
    if (bid < 197)      { A = vtokA;       WT = WvtT; bias = bvt; C = vtokC; mbase = bid * 64;        do_norm = true;  }
    else if (bid < 261) { A = ttokA;       WT = WttT; bias = btt; C = ttokC; mbase = (bid - 197) * 64; do_norm = true;  }
    else if (bid == 261){ A = visual_cls;  WT = WvT;  bias = bv;  Cf = out;              do_norm = false; }
    else                { A = textual_cls; WT = WtT;  bias = bt;  Cf = out + 16384;      do_norm = false; }

    const int tid = threadIdx.x;
    const int lane = tid & 31, w = tid >> 5;
    const int lq = lane >> 2, lr = lane & 3;
    const int vg = w >> 2, nw = w & 3;
    const int rbase = vg * 32;
    const int nb = nw * 64;

    sbias[tid] = bias[tid];

    const unsigned sWu = s2u(sWh);

    float acc[2][8][4] = {};

    for (int k0 = 0; k0 < DD; k0 += 128) {
        // W chunk: 256 n-rows x 128 k halves via cp.async (16 x 16B per row)
        #pragma unroll
        for (int it = 0; it < 16; it++) {
            int idx = tid + it * 256;        // 0..4095
            int r = idx >> 4;                // 0..255
            int c16 = idx & 15;              // 16-byte chunk (8 halves)
            cpa16(sWu + (unsigned)(r * 136 + c16 * 8) * 2,
                  WT + (size_t)r * DD + k0 + c16 * 8);
        }
        cpa_commit();
        // A chunk: 64 rows x 128 k, fp32 -> half in-register
        #pragma unroll
        for (int it = 0; it < 8; it++) {
            int idx = tid + it * 256;        // 0..2047
            int r = idx >> 5;                // 0..63
            int c4 = idx & 31;               // float4 unit along k
            float4 v = *(const float4*)(A + (size_t)(mbase + r) * DD + k0 + c4 * 4);
            __half2 h0 = __floats2half2_rn(v.x, v.y);
            __half2 h1 = __floats2half2_rn(v.z, v.w);
            uint2 pk = make_uint2(*(unsigned*)&h0, *(unsigned*)&h1);
            *(uint2*)(sAh + r * 136 + c4 * 4) = pk;
        }
        cpa_wait0();
        __syncthreads();

        #pragma unroll
        for (int ks = 0; ks < 8; ks++) {
            unsigned b0[8], b1[8];
            #pragma unroll
            for (int ng = 0; ng < 8; ng++) {
                const __half* p = sWh + (nb + 8 * ng + lq) * 136 + ks * 16 + 2 * lr;
                b0[ng] = *(const unsigned*)p;
                b1[ng] = *(const unsigned*)(p + 8);
            }
            #pragma unroll
            for (int rg = 0; rg < 2; rg++) {
                const __half* p = sAh + (rbase + 16 * rg + lq) * 136 + ks * 16 + 2 * lr;
                unsigned a0 = *(const unsigned*)p;
                unsigned a1 = *(const unsigned*)(p + 8 * 136);
                unsigned a2 = *(const unsigned*)(p + 8);
                unsigned a3 = *(const unsigned*)(p + 8 * 136 + 8);
                #pragma unroll
                for (int ng = 0; ng < 8; ng++)
                    mma16(acc[rg][ng], a0, a1, a2, a3, b0[ng], b1[ng]);
            }
        }
        __syncthreads();
    }

    // bias
    #pragma unroll
    for (int rg = 0; rg < 2; rg++)
        #pragma unroll
        for (int ng = 0; ng < 8; ng++) {
            int col = nb + 8 * ng + 2 * lr;
            float c0 = sbias[col], c1 = sbias[col + 1];
            acc[rg][ng][0] += c0; acc[rg][ng][1] += c1;
            acc[rg][ng][2] += c0; acc[rg][ng][3] += c1;
        }

    if (!do_norm) {
        // cls: fp32 store straight to output
        #pragma unroll
        for (int rg = 0; rg < 2; rg++) {
            int r0 = rbase + 16 * rg + lq;
            #pragma unroll
            for (int ng = 0; ng < 8; ng++) {
                int col = nb + 8 * ng + 2 * lr;
                *(float2*)(Cf + (size_t)r0 * EE + col) =
                    make_float2(acc[rg][ng][0], acc[rg][ng][1]);
                *(float2*)(Cf + (size_t)(r0 + 8) * EE + col) =
                    make_float2(acc[rg][ng][2], acc[rg][ng][3]);
            }
        }
        return;
    }

    // l2norm: per-row sum of squares
    #pragma unroll
    for (int rg = 0; rg < 2; rg++) {
        float s0 = 0.f, s1 = 0.f;
        #pragma unroll
        for (int ng = 0; ng < 8; ng++) {
            s0 += acc[rg][ng][0] * acc[rg][ng][0] + acc[rg][ng][1] * acc[rg][ng][1];
            s1 += acc[rg][ng][2] * acc[rg][ng][2] + acc[rg][ng][3] * acc[rg][ng][3];
        }
        s0 += __shfl_xor_sync(0xffffffffu, s0, 1);
        s0 += __shfl_xor_sync(0xffffffffu, s0, 2);
        s1 += __shfl_xor_sync(0xffffffffu, s1, 1);
        s1 += __shfl_xor_sync(0xffffffffu, s1, 2);
        if (lr == 0) {
            rowsq[(rbase + 16 * rg + lq) * 5 + nw] = s0;
            rowsq[(rbase + 16 * rg + lq + 8) * 5 + nw] = s1;
        }
    }
    __syncthreads();
    if (tid < 64) {
        float s = rowsq[tid * 5] + rowsq[tid * 5 + 1] + rowsq[tid * 5 + 2] + rowsq[tid * 5 + 3];
        sinv[tid] = 1.0f / fmaxf(sqrtf(s), 1e-12f);
    }
    __syncthreads();

    #pragma unroll
    for (int rg = 0; rg < 2; rg++) {
        int r0 = rbase + 16 * rg + lq;
        float inv0 = sinv[r0], inv1 = sinv[r0 + 8];
        #pragma unroll
        for (int ng = 0; ng < 8; ng++) {
            int col = nb + 8 * ng + 2 * lr;
            __half2 h0 = __floats2half2_rn(acc[rg][ng][0] * inv0, acc[rg][ng][1] * inv0);
            __half2 h1 = __floats2half2_rn(acc[rg][ng][2] * inv1, acc[rg][ng][3] * inv1);
            *(__half2*)(C + (size_t)(mbase + r0) * EE + col) = h0;
            *(__half2*)(C + (size_t)(mbase + r0 + 8) * EE + col) = h1;
        }
    }
}

// ---------------------------------------------------------------------------
// Fused sim kernel (fp16 MMA m16n8k16, f32 accum).
// grid = (qpair=32, b=64), 256 threads (8 warps = 4 v-groups x 2 t-groups).
// Block tile 128v x 128t. sT resident for full K=256; sV streamed per
// (v-tile, k-chunk=128) via cp.async.
// Padding elision at m16 granularity: any rg whose 16-row strip starts
// beyond VV skips its A-frag loads + MMAs (acc stays 0; epilogue masks).
// Rows issued: 224 -> 208 of 197 valid.
// ---------------------------------------------------------------------------
#define SVS 136
#define STS 264

__global__ __launch_bounds__(256, 2) void sim_kernel(
    const __half* __restrict__ vtok, const __half* __restrict__ ttok,
    const int* __restrict__ text_length, float* __restrict__ out)
{
    extern __shared__ __half smh[];
    __half* sV = smh;                  // 128 x SVS
    __half* sT = smh + 128 * SVS;      // 128 x STS (full K)

    __shared__ float t2i_part[4][128];
    __shared__ float t2i_run[128];
    __shared__ float wsum[8];

    const int tid = threadIdx.x;
    const int lane = tid & 31, w = tid >> 5;
    const int lq = lane >> 2, lr = lane & 3;
    const int vb = (w >> 1) * 32;
    const int tb = (w & 1) * 64;
    const int qp = blockIdx.x, b = blockIdx.y;

    const __half* vbase = vtok + (size_t)b * VV * EE;
    const __half* tbase = ttok + (size_t)(qp * 2) * LL * EE;

    unsigned sVu = (unsigned)__cvta_generic_to_shared(sV);
    unsigned sTu = (unsigned)__cvta_generic_to_shared(sT);

    // sT: full 128 t-rows x 256 k (once per block)
    #pragma unroll
    for (int it = 0; it < 16; it++) {
        int idx = tid + it * 256;
        int r = idx >> 5;
        int c8 = idx & 31;
        cpa16(sTu + (unsigned)(r * STS + c8 * 8) * 2, tbase + (size_t)r * EE + c8 * 8);
    }

    float i2t_wsum = 0.0f;

    for (int v0 = 0; v0 < 256; v0 += 128) {
        float acc[2][8][4] = {};
        const bool active = (v0 + vb) < VV;
        // per-rg validity at m16 granularity (warp-uniform)
        const bool rgok0 = (v0 + vb) < VV;
        const bool rgok1 = (v0 + vb + 16) < VV;
        const int itmax = (v0 == 0) ? 8 : 5;

        for (int kc = 0; kc < 2; kc++) {
            for (int it = 0; it < itmax; it++) {
                int idx = tid + it * 256;
                int r = idx >> 4;
                int c8 = idx & 15;
                int vr = min(v0 + r, VV - 1);
                cpa16(sVu + (unsigned)(r * SVS + c8 * 8) * 2,
                      vbase + (size_t)vr * EE + kc * 128 + c8 * 8);
            }
            cpa_commit();
            cpa_wait0();
            __syncthreads();

            if (active) {
                #pragma unroll
                for (int ks = 0; ks < 8; ks++) {
                    unsigned b0[8], b1[8];
                    #pragma unroll
                    for (int ng = 0; ng < 8; ng++) {
                        const __half* p = sT + (tb + 8 * ng + lq) * STS + kc * 128 + ks * 16 + 2 * lr;
                        b0[ng] = *(const unsigned*)p;
                        b1[ng] = *(const unsigned*)(p + 8);
                    }
                    #pragma unroll
                    for (int rg = 0; rg < 2; rg++) {
                        if (rg == 0 ? rgok0 : rgok1) {
                            const __half* p = sV + (vb + 16 * rg + lq) * SVS + ks * 16 + 2 * lr;
                            unsigned a0 = *(const unsigned*)p;
                            unsigned a1 = *(const unsigned*)(p + 8 * SVS);
                            unsigned a2 = *(const unsigned*)(p + 8);
                            unsigned a3 = *(const unsigned*)(p + 8 * SVS + 8);
                            #pragma unroll
                            for (int ng = 0; ng < 8; ng++)
                                mma16(acc[rg][ng], a0, a1, a2, a3, b0[ng], b1[ng]);
                        }
                    }
                }
            }
            __syncthreads();
        }

        // ---- i2t: per-v-row max over this warp's 64 t cols (its full q) ----
        float rsum = 0.0f;
        #pragma unroll
        for (int rg = 0; rg < 2; rg++) {
            float m0 = -1e30f, m1 = -1e30f;
            #pragma unroll
            for (int ng = 0; ng < 8; ng++) {
                m0 = fmaxf(m0, fmaxf(acc[rg][ng][0], acc[rg][ng][1]));
                m1 = fmaxf(m1, fmaxf(acc[rg][ng][2], acc[rg][ng][3]));
            }
            m0 = fmaxf(m0, __shfl_xor_sync(0xffffffffu, m0, 1));
            m0 = fmaxf(m0, __shfl_xor_sync(0xffffffffu, m0, 2));
            m1 = fmaxf(m1, __shfl_xor_sync(0xffffffffu, m1, 1));
            m1 = fmaxf(m1, __shfl_xor_sync(0xffffffffu, m1, 2));
            int r0 = v0 + vb + 16 * rg + lq;
            if (lr == 0) {
                if (r0 < VV) rsum += m0;
                if (r0 + 8 < VV) rsum += m1;
            }
        }
        #pragma unroll
        for (int off = 16; off > 0; off >>= 1)
            rsum += __shfl_xor_sync(0xffffffffu, rsum, off);
        i2t_wsum += rsum;

        // ---- t2i: per-t-col max over this warp's 32 v rows (masked) ----
        #pragma unroll
        for (int ng = 0; ng < 8; ng++) {
            float m0 = -1e30f, m1 = -1e30f;
            #pragma unroll
            for (int rg = 0; rg < 2; rg++) {
                int r0 = v0 + vb + 16 * rg + lq;
                if (r0 < VV) {
                    m0 = fmaxf(m0, acc[rg][ng][0]);
                    m1 = fmaxf(m1, acc[rg][ng][1]);
                }
                if (r0 + 8 < VV) {
                    m0 = fmaxf(m0, acc[rg][ng][2]);
                    m1 = fmaxf(m1, acc[rg][ng][3]);
                }
            }
            m0 = fmaxf(m0, __shfl_xor_sync(0xffffffffu, m0, 4));
            m0 = fmaxf(m0, __shfl_xor_sync(0xffffffffu, m0, 8));
            m0 = fmaxf(m0, __shfl_xor_sync(0xffffffffu, m0, 16));
            m1 = fmaxf(m1, __shfl_xor_sync(0xffffffffu, m1, 4));
            m1 = fmaxf(m1, __shfl_xor_sync(0xffffffffu, m1, 8));
            m1 = fmaxf(m1, __shfl_xor_sync(0xffffffffu, m1, 16));
            if (lane < 4) {
                t2i_part[w >> 1][tb + 8 * ng + 2 * lane] = m0;
                t2i_part[w >> 1][tb + 8 * ng + 2 * lane + 1] = m1;
            }
        }
        __syncthreads();
        if (tid < 128) {
            float m = fmaxf(fmaxf(t2i_part[0][tid], t2i_part[1][tid]),
                            fmaxf(t2i_part[2][tid], t2i_part[3][tid]));
            t2i_run[tid] = (v0 == 0) ? m : fmaxf(t2i_run[tid], m);
        }
        __syncthreads();
    }

    if (lane == 0) wsum[w] = i2t_wsum;
    __syncthreads();

    // t2i outputs: warp 0 -> q0, warp 1 -> q1
    if (tid < 64) {
        int w2 = tid >> 5;
        int l2 = tid & 31;
        int len = text_length[b];   // reference quirk: indexed by b
        float s = 0.0f;
        if (l2 < len) s += t2i_run[w2 * 64 + l2];
        if (l2 + 32 < len) s += t2i_run[w2 * 64 + l2 + 32];
        #pragma unroll
        for (int off = 16; off > 0; off >>= 1)
            s += __shfl_xor_sync(0xffffffffu, s, off);
        if (l2 == 0)
            out[36864 + b * 64 + qp * 2 + w2] = s / fmaxf((float)len, 1e-6f);
    }
    // i2t outputs
    if (tid == 128 || tid == 129) {
        int j = tid - 128;
        float s = wsum[j] + wsum[j + 2] + wsum[j + 4] + wsum[j + 6];
        out[32768 + b * 64 + qp * 2 + j] = s / (float)VV;
    }
}

// ---------------------------------------------------------------------------
extern "C" void kernel_launch(void* const* d_in, const int* in_sizes, int n_in,
                              void* d_out, int out_size)
{
    const float* visual_cls     = (const float*)d_in[0];
    const float* textual_cls    = (const float*)d_in[1];
    const float* visual_tokens  = (const float*)d_in[2];
    const float* textual_tokens = (const float*)d_in[3];
    const int*   text_length    = (const int*)  d_in[4];
    const float* Wv  = (const float*)d_in[5];
    const float* bv  = (const float*)d_in[6];
    const float* Wt  = (const float*)d_in[7];
    const float* bt  = (const float*)d_in[8];
    const float* Wvt = (const float*)d_in[9];
    const float* bvt = (const float*)d_in[10];
    const float* Wtt = (const float*)d_in[11];
    const float* btt = (const float*)d_in[12];
    float* out = (float*)d_out;

    __half *vtok, *ttok, *wvtT, *wttT, *wvT, *wtT;
    cudaGetSymbolAddress((void**)&vtok, g_vtok);
    cudaGetSymbolAddress((void**)&ttok, g_ttok);
    cudaGetSymbolAddress((void**)&wvtT, g_wvtT);
    cudaGetSymbolAddress((void**)&wttT, g_wttT);
    cudaGetSymbolAddress((void**)&wvT, g_wvT);
    cudaGetSymbolAddress((void**)&wtT, g_wtT);

    const int proj_smem = (64 * 136 + 256 * 136) * sizeof(__half);        // 87040
    const int sim_smem  = (128 * SVS + 128 * STS) * sizeof(__half);       // 102400
    cudaFuncSetAttribute(proj_kernel, cudaFuncAttributeMaxDynamicSharedMemorySize, proj_smem);
    cudaFuncSetAttribute(sim_kernel,  cudaFuncAttributeMaxDynamicSharedMemorySize, sim_smem);

    wprep_kernel<<<dim3(24, 8, 4), dim3(32, 8)>>>(Wvt, Wtt, Wv, Wt, wvtT, wttT, wvT, wtT);

    proj_kernel<<<263, 256, proj_smem>>>(
        visual_cls, textual_cls, visual_tokens, textual_tokens,
        bv, bt, bvt, btt, wvtT, wttT, wvT, wtT,
        out, vtok, ttok);

    sim_kernel<<<dim3(32, 64), 256, sim_smem>>>(vtok, ttok, text_length, out);
}

// round 12
// speedup vs baseline: 9.4699x; 1.0515x over previous
#include <cuda_runtime.h>
#include <cuda_fp16.h>
#include <math.h>
#include <stdint.h>

#define BB 64
#define VV 197
#define LL 64
#define DD 768
#define EE 256

// Scratch: projected + normalized tokens in fp16, transposed half weights
__device__ __align__(16) __half g_vtok[(size_t)BB * VV * EE]; // 6.45 MB
__device__ __align__(16) __half g_ttok[(size_t)BB * LL * EE]; // 2.1 MB
__device__ __align__(16) __half g_wvtT[(size_t)EE * DD];      // [n][k]
__device__ __align__(16) __half g_wttT[(size_t)EE * DD];
__device__ __align__(16) __half g_wvT[(size_t)EE * DD];
__device__ __align__(16) __half g_wtT[(size_t)EE * DD];

// ---------------------------------------------------------------------------
// helpers
// ---------------------------------------------------------------------------
__device__ __forceinline__ void mma16(float* c, unsigned a0, unsigned a1, unsigned a2,
                                      unsigned a3, unsigned b0, unsigned b1) {
    asm volatile(
        "mma.sync.aligned.m16n8k16.row.col.f32.f16.f16.f32 "
        "{%0,%1,%2,%3},{%4,%5,%6,%7},{%8,%9},{%0,%1,%2,%3};\n"
        : "+f"(c[0]), "+f"(c[1]), "+f"(c[2]), "+f"(c[3])
        : "r"(a0), "r"(a1), "r"(a2), "r"(a3), "r"(b0), "r"(b1));
}

__device__ __forceinline__ void cpa16(unsigned s, const void* g) {
    asm volatile("cp.async.cg.shared.global [%0], [%1], 16;" :: "r"(s), "l"(g) : "memory");
}
__device__ __forceinline__ void cpa_commit() {
    asm volatile("cp.async.commit_group;" ::: "memory");
}
__device__ __forceinline__ void cpa_wait0() {
    asm volatile("cp.async.wait_group 0;" ::: "memory");
}
__device__ __forceinline__ unsigned s2u(const void* p) {
    return (unsigned)__cvta_generic_to_shared(p);
}

// ---------------------------------------------------------------------------
// W transpose + fp32->fp16 prepass: W[768][256] -> WT[256][768] half.
// grid (6, 8, 4), block 256. Tile 128k x 32n: float4-coalesced reads,
// uint4-coalesced writes. z: 0=Wvt 1=Wtt 2=Wv 3=Wt.
// ---------------------------------------------------------------------------
__global__ __launch_bounds__(256) void wprep_kernel(
    const float* __restrict__ Wvt, const float* __restrict__ Wtt,
    const float* __restrict__ Wv, const float* __restrict__ Wt,
    __half* __restrict__ WvtT, __half* __restrict__ WttT,
    __half* __restrict__ WvT, __half* __restrict__ WtT)
{
    __shared__ float t[128][33];
    const float* W;
    __half* WT;
    switch (blockIdx.z) {
        case 0: W = Wvt; WT = WvtT; break;
        case 1: W = Wtt; WT = WttT; break;
        case 2: W = Wv;  WT = WvT;  break;
        default: W = Wt; WT = WtT;  break;
    }
    const int k0 = blockIdx.x * 128, n0 = blockIdx.y * 32;
    const int tid = threadIdx.x;

    // load 128 k-rows x 32 n-cols (coalesced 128B rows)
    #pragma unroll
    for (int i = 0; i < 16; i++) {
        int idx = tid + i * 256;         // 0..4095
        int r = idx >> 5;                // k row 0..127
        int cc = idx & 31;               // n col
        t[r][cc] = W[(size_t)(k0 + r) * EE + n0 + cc];
    }
    __syncthreads();

    // write 32 n-rows x 128 k-halves (coalesced 256B rows, uint4)
    #pragma unroll
    for (int j = 0; j < 2; j++) {
        int u = tid + j * 256;           // 0..511
        int n = u >> 4;                  // n row 0..31
        int kq = u & 15;                 // uint4 index along k
        __half h[8];
        #pragma unroll
        for (int i = 0; i < 8; i++) h[i] = __float2half(t[kq * 8 + i][n]);
        *(uint4*)(WT + (size_t)(n0 + n) * DD + k0 + kq * 8) = *(uint4*)h;
    }
}

// ---------------------------------------------------------------------------
// Unified projection (fp16 MMA m16n8k16, fp32 accum), 2 blocks/SM.
// One block = 64 rows x 256 cols, K=768 in chunks of 128.
// Grid: [0,197) vtok (+bias+l2norm, half out), [197,261) ttok (same),
//       261 vcls (+bias, fp32 out), 262 tcls (+bias, fp32 out).
// ---------------------------------------------------------------------------
__global__ __launch_bounds__(256, 2) void proj_kernel(
    const float* __restrict__ visual_cls, const float* __restrict__ textual_cls,
    const float* __restrict__ vtokA, const float* __restrict__ ttokA,
    const float* __restrict__ bv, const float* __restrict__ bt,
    const float* __restrict__ bvt, const float* __restrict__ btt,
    const __half* __restrict__ WvtT, const __half* __restrict__ WttT,
    const __half* __restrict__ WvT, const __half* __restrict__ WtT,
    float* __restrict__ out, __half* __restrict__ vtokC, __half* __restrict__ ttokC)
{
    extern __shared__ float sm[];
    __shared__ float sbias[256];
    __shared__ float rowsq[64 * 5];
    __shared__ float sinv[64];

    __half* sAh = (__half*)sm;               // 64 x 136
    __half* sWh = (__half*)sm + 64 * 136;    // 256 x 136

    const int bid = blockIdx.x;

    const float* A;
    const __half* WT;
    const float* bias;
    __half* C = nullptr;
    float* Cf = nullptr;
    int mbase = 0;
    bool do_norm;
    if (bid < 197)      { A = vtokA;       WT = WvtT; bias = bvt; C = vtokC; mbase = bid * 64;        do_norm = true;  }
    else if (bid < 261) { A = ttokA;       WT = WttT; bias = btt; C = ttokC; mbase = (bid - 197) * 64; do_norm = true;  }
    else if (bid == 261){ A = visual_cls;  WT = WvT;  bias = bv;  Cf = out;              do_norm = false; }
    else                { A = textual_cls; WT = WtT;  bias = bt;  Cf = out + 16384;      do_norm = false; }

    const int tid = threadIdx.x;
    const int lane = tid & 31, w = tid >> 5;
    const int lq = lane >> 2, lr = lane & 3;
    const int vg = w >> 2, nw = w & 3;
    const int rbase = vg * 32;
    const int nb = nw * 64;

    sbias[tid] = bias[tid];

    const unsigned sWu = s2u(sWh);

    float acc[2][8][4] = {};

    for (int k0 = 0; k0 < DD; k0 += 128) {
        // W chunk: 256 n-rows x 128 k halves via cp.async (16 x 16B per row)
        #pragma unroll
        for (int it = 0; it < 16; it++) {
            int idx = tid + it * 256;        // 0..4095
            int r = idx >> 4;                // 0..255
            int c16 = idx & 15;              // 16-byte chunk (8 halves)
            cpa16(sWu + (unsigned)(r * 136 + c16 * 8) * 2,
                  WT + (size_t)r * DD + k0 + c16 * 8);
        }
        cpa_commit();
        // A chunk: 64 rows x 128 k, fp32 -> half in-register
        #pragma unroll
        for (int it = 0; it < 8; it++) {
            int idx = tid + it * 256;        // 0..2047
            int r = idx >> 5;                // 0..63
            int c4 = idx & 31;               // float4 unit along k
            float4 v = *(const float4*)(A + (size_t)(mbase + r) * DD + k0 + c4 * 4);
            __half2 h0 = __floats2half2_rn(v.x, v.y);
            __half2 h1 = __floats2half2_rn(v.z, v.w);
            uint2 pk = make_uint2(*(unsigned*)&h0, *(unsigned*)&h1);
            *(uint2*)(sAh + r * 136 + c4 * 4) = pk;
        }
        cpa_wait0();
        __syncthreads();

        #pragma unroll
        for (int ks = 0; ks < 8; ks++) {
            unsigned b0[8], b1[8];
            #pragma unroll
            for (int ng = 0; ng < 8; ng++) {
                const __half* p = sWh + (nb + 8 * ng + lq) * 136 + ks * 16 + 2 * lr;
                b0[ng] = *(const unsigned*)p;
                b1[ng] = *(const unsigned*)(p + 8);
            }
            #pragma unroll
            for (int rg = 0; rg < 2; rg++) {
                const __half* p = sAh + (rbase + 16 * rg + lq) * 136 + ks * 16 + 2 * lr;
                unsigned a0 = *(const unsigned*)p;
                unsigned a1 = *(const unsigned*)(p + 8 * 136);
                unsigned a2 = *(const unsigned*)(p + 8);
                unsigned a3 = *(const unsigned*)(p + 8 * 136 + 8);
                #pragma unroll
                for (int ng = 0; ng < 8; ng++)
                    mma16(acc[rg][ng], a0, a1, a2, a3, b0[ng], b1[ng]);
            }
        }
        __syncthreads();
    }

    // bias
    #pragma unroll
    for (int rg = 0; rg < 2; rg++)
        #pragma unroll
        for (int ng = 0; ng < 8; ng++) {
            int col = nb + 8 * ng + 2 * lr;
            float c0 = sbias[col], c1 = sbias[col + 1];
            acc[rg][ng][0] += c0; acc[rg][ng][1] += c1;
            acc[rg][ng][2] += c0; acc[rg][ng][3] += c1;
        }

    if (!do_norm) {
        #pragma unroll
        for (int rg = 0; rg < 2; rg++) {
            int r0 = rbase + 16 * rg + lq;
            #pragma unroll
            for (int ng = 0; ng < 8; ng++) {
                int col = nb + 8 * ng + 2 * lr;
                *(float2*)(Cf + (size_t)r0 * EE + col) =
                    make_float2(acc[rg][ng][0], acc[rg][ng][1]);
                *(float2*)(Cf + (size_t)(r0 + 8) * EE + col) =
                    make_float2(acc[rg][ng][2], acc[rg][ng][3]);
            }
        }
        return;
    }

    // l2norm: per-row sum of squares
    #pragma unroll
    for (int rg = 0; rg < 2; rg++) {
        float s0 = 0.f, s1 = 0.f;
        #pragma unroll
        for (int ng = 0; ng < 8; ng++) {
            s0 += acc[rg][ng][0] * acc[rg][ng][0] + acc[rg][ng][1] * acc[rg][ng][1];
            s1 += acc[rg][ng][2] * acc[rg][ng][2] + acc[rg][ng][3] * acc[rg][ng][3];
        }
        s0 += __shfl_xor_sync(0xffffffffu, s0, 1);
        s0 += __shfl_xor_sync(0xffffffffu, s0, 2);
        s1 += __shfl_xor_sync(0xffffffffu, s1, 1);
        s1 += __shfl_xor_sync(0xffffffffu, s1, 2);
        if (lr == 0) {
            rowsq[(rbase + 16 * rg + lq) * 5 + nw] = s0;
            rowsq[(rbase + 16 * rg + lq + 8) * 5 + nw] = s1;
        }
    }
    __syncthreads();
    if (tid < 64) {
        float s = rowsq[tid * 5] + rowsq[tid * 5 + 1] + rowsq[tid * 5 + 2] + rowsq[tid * 5 + 3];
        sinv[tid] = 1.0f / fmaxf(sqrtf(s), 1e-12f);
    }
    __syncthreads();

    #pragma unroll
    for (int rg = 0; rg < 2; rg++) {
        int r0 = rbase + 16 * rg + lq;
        float inv0 = sinv[r0], inv1 = sinv[r0 + 8];
        #pragma unroll
        for (int ng = 0; ng < 8; ng++) {
            int col = nb + 8 * ng + 2 * lr;
            __half2 h0 = __floats2half2_rn(acc[rg][ng][0] * inv0, acc[rg][ng][1] * inv0);
            __half2 h1 = __floats2half2_rn(acc[rg][ng][2] * inv1, acc[rg][ng][3] * inv1);
            *(__half2*)(C + (size_t)(mbase + r0) * EE + col) = h0;
            *(__half2*)(C + (size_t)(mbase + r0 + 8) * EE + col) = h1;
        }
    }
}

// ---------------------------------------------------------------------------
// Fused sim kernel (fp16 MMA m16n8k16, f32 accum).
// grid = (qpair=32, b=64), 256 threads (8 warps = 4 v-groups x 2 t-groups).
// Block tile 128v x 128t. sT resident for full K=256; sV streamed as a flat
// list of 4 chunks (pass0 kc0/kc1, pass1 kc0/kc1) with lookahead cp.async:
// chunk c+1 is issued right after chunk c's MMAs sync, so the pass-boundary
// load hides under the epilogue. m16 padding elision as before.
// ---------------------------------------------------------------------------
#define SVS 136
#define STS 264

__global__ __launch_bounds__(256, 2) void sim_kernel(
    const __half* __restrict__ vtok, const __half* __restrict__ ttok,
    const int* __restrict__ text_length, float* __restrict__ out)
{
    extern __shared__ __half smh[];
    __half* sV = smh;                  // 128 x SVS
    __half* sT = smh + 128 * SVS;      // 128 x STS (full K)

    __shared__ float t2i_part[4][128];
    __shared__ float t2i_run[128];
    __shared__ float wsum[8];

    const int tid = threadIdx.x;
    const int lane = tid & 31, w = tid >> 5;
    const int lq = lane >> 2, lr = lane & 3;
    const int vb = (w >> 1) * 32;
    const int tb = (w & 1) * 64;
    const int qp = blockIdx.x, b = blockIdx.y;

    const __half* vbase = vtok + (size_t)b * VV * EE;
    const __half* tbase = ttok + (size_t)(qp * 2) * LL * EE;

    unsigned sVu = (unsigned)__cvta_generic_to_shared(sV);
    unsigned sTu = (unsigned)__cvta_generic_to_shared(sT);

    // sT: full 128 t-rows x 256 k (once per block) + sV chunk 0
    #pragma unroll
    for (int it = 0; it < 16; it++) {
        int idx = tid + it * 256;
        int r = idx >> 5;
        int c8 = idx & 31;
        cpa16(sTu + (unsigned)(r * STS + c8 * 8) * 2, tbase + (size_t)r * EE + c8 * 8);
    }
    #pragma unroll
    for (int it = 0; it < 8; it++) {
        int idx = tid + it * 256;
        int r = idx >> 4;
        int c8 = idx & 15;
        int vr = min(r, VV - 1);
        cpa16(sVu + (unsigned)(r * SVS + c8 * 8) * 2,
              vbase + (size_t)vr * EE + c8 * 8);
    }
    cpa_commit();

    float i2t_wsum = 0.0f;
    float acc[2][8][4];

    #pragma unroll
    for (int c = 0; c < 4; ++c) {
        const int pass = c >> 1, kc = c & 1;
        const int v0 = pass * 128;
        const bool active = (v0 + vb) < VV;
        const bool rgok0 = (v0 + vb) < VV;
        const bool rgok1 = (v0 + vb + 16) < VV;

        if (kc == 0) {
            #pragma unroll
            for (int rg = 0; rg < 2; rg++)
                #pragma unroll
                for (int ng = 0; ng < 8; ng++)
                    #pragma unroll
                    for (int j = 0; j < 4; j++) acc[rg][ng][j] = 0.0f;
        }

        cpa_wait0();
        __syncthreads();

        if (active) {
            #pragma unroll
            for (int ks = 0; ks < 8; ks++) {
                unsigned b0[8], b1[8];
                #pragma unroll
                for (int ng = 0; ng < 8; ng++) {
                    const __half* p = sT + (tb + 8 * ng + lq) * STS + kc * 128 + ks * 16 + 2 * lr;
                    b0[ng] = *(const unsigned*)p;
                    b1[ng] = *(const unsigned*)(p + 8);
                }
                #pragma unroll
                for (int rg = 0; rg < 2; rg++) {
                    if (rg == 0 ? rgok0 : rgok1) {
                        const __half* p = sV + (vb + 16 * rg + lq) * SVS + ks * 16 + 2 * lr;
                        unsigned a0 = *(const unsigned*)p;
                        unsigned a1 = *(const unsigned*)(p + 8 * SVS);
                        unsigned a2 = *(const unsigned*)(p + 8);
                        unsigned a3 = *(const unsigned*)(p + 8 * SVS + 8);
                        #pragma unroll
                        for (int ng = 0; ng < 8; ng++)
                            mma16(acc[rg][ng], a0, a1, a2, a3, b0[ng], b1[ng]);
                    }
                }
            }
        }
        __syncthreads();   // MMAs done block-wide -> sV free for next chunk

        // lookahead: issue next chunk's sV loads (hidden under epilogue at
        // pass boundaries)
        if (c < 3) {
            const int nc = c + 1;
            const int np = nc >> 1, nkc = nc & 1;
            const int nv0 = np * 128;
            const int itmax = (np == 0) ? 8 : 5;
            for (int it = 0; it < itmax; it++) {
                int idx = tid + it * 256;
                int r = idx >> 4;
                int c8 = idx & 15;
                int vr = min(nv0 + r, VV - 1);
                cpa16(sVu + (unsigned)(r * SVS + c8 * 8) * 2,
                      vbase + (size_t)vr * EE + nkc * 128 + c8 * 8);
            }
            cpa_commit();
        }

        if (kc == 1) {
            // ---- i2t: per-v-row max over this warp's 64 t cols ----
            float rsum = 0.0f;
            #pragma unroll
            for (int rg = 0; rg < 2; rg++) {
                float m0 = -1e30f, m1 = -1e30f;
                #pragma unroll
                for (int ng = 0; ng < 8; ng++) {
                    m0 = fmaxf(m0, fmaxf(acc[rg][ng][0], acc[rg][ng][1]));
                    m1 = fmaxf(m1, fmaxf(acc[rg][ng][2], acc[rg][ng][3]));
                }
                m0 = fmaxf(m0, __shfl_xor_sync(0xffffffffu, m0, 1));
                m0 = fmaxf(m0, __shfl_xor_sync(0xffffffffu, m0, 2));
                m1 = fmaxf(m1, __shfl_xor_sync(0xffffffffu, m1, 1));
                m1 = fmaxf(m1, __shfl_xor_sync(0xffffffffu, m1, 2));
                int r0 = v0 + vb + 16 * rg + lq;
                if (lr == 0) {
                    if (r0 < VV) rsum += m0;
                    if (r0 + 8 < VV) rsum += m1;
                }
            }
            #pragma unroll
            for (int off = 16; off > 0; off >>= 1)
                rsum += __shfl_xor_sync(0xffffffffu, rsum, off);
            i2t_wsum += rsum;

            // ---- t2i: per-t-col max over this warp's 32 v rows (masked) ----
            #pragma unroll
            for (int ng = 0; ng < 8; ng++) {
                float m0 = -1e30f, m1 = -1e30f;
                #pragma unroll
                for (int rg = 0; rg < 2; rg++) {
                    int r0 = v0 + vb + 16 * rg + lq;
                    if (r0 < VV) {
                        m0 = fmaxf(m0, acc[rg][ng][0]);
                        m1 = fmaxf(m1, acc[rg][ng][1]);
                    }
                    if (r0 + 8 < VV) {
                        m0 = fmaxf(m0, acc[rg][ng][2]);
                        m1 = fmaxf(m1, acc[rg][ng][3]);
                    }
                }
                m0 = fmaxf(m0, __shfl_xor_sync(0xffffffffu, m0, 4));
                m0 = fmaxf(m0, __shfl_xor_sync(0xffffffffu, m0, 8));
                m0 = fmaxf(m0, __shfl_xor_sync(0xffffffffu, m0, 16));
                m1 = fmaxf(m1, __shfl_xor_sync(0xffffffffu, m1, 4));
                m1 = fmaxf(m1, __shfl_xor_sync(0xffffffffu, m1, 8));
                m1 = fmaxf(m1, __shfl_xor_sync(0xffffffffu, m1, 16));
                if (lane < 4) {
                    t2i_part[w >> 1][tb + 8 * ng + 2 * lane] = m0;
                    t2i_part[w >> 1][tb + 8 * ng + 2 * lane + 1] = m1;
                }
            }
            __syncthreads();
            if (tid < 128) {
                float m = fmaxf(fmaxf(t2i_part[0][tid], t2i_part[1][tid]),
                                fmaxf(t2i_part[2][tid], t2i_part[3][tid]));
                t2i_run[tid] = (v0 == 0) ? m : fmaxf(t2i_run[tid], m);
            }
            __syncthreads();
        }
    }

    if (lane == 0) wsum[w] = i2t_wsum;
    __syncthreads();

    // t2i outputs: warp 0 -> q0, warp 1 -> q1
    if (tid < 64) {
        int w2 = tid >> 5;
        int l2 = tid & 31;
        int len = text_length[b];   // reference quirk: indexed by b
        float s = 0.0f;
        if (l2 < len) s += t2i_run[w2 * 64 + l2];
        if (l2 + 32 < len) s += t2i_run[w2 * 64 + l2 + 32];
        #pragma unroll
        for (int off = 16; off > 0; off >>= 1)
            s += __shfl_xor_sync(0xffffffffu, s, off);
        if (l2 == 0)
            out[36864 + b * 64 + qp * 2 + w2] = s / fmaxf((float)len, 1e-6f);
    }
    // i2t outputs
    if (tid == 128 || tid == 129) {
        int j = tid - 128;
        float s = wsum[j] + wsum[j + 2] + wsum[j + 4] + wsum[j + 6];
        out[32768 + b * 64 + qp * 2 + j] = s / (float)VV;
    }
}

// ---------------------------------------------------------------------------
extern "C" void kernel_launch(void* const* d_in, const int* in_sizes, int n_in,
                              void* d_out, int out_size)
{
    const float* visual_cls     = (const float*)d_in[0];
    const float* textual_cls    = (const float*)d_in[1];
    const float* visual_tokens  = (const float*)d_in[2];
    const float* textual_tokens = (const float*)d_in[3];
    const int*   text_length    = (const int*)  d_in[4];
    const float* Wv  = (const float*)d_in[5];
    const float* bv  = (const float*)d_in[6];
    const float* Wt  = (const float*)d_in[7];
    const float* bt  = (const float*)d_in[8];
    const float* Wvt = (const float*)d_in[9];
    const float* bvt = (const float*)d_in[10];
    const float* Wtt = (const float*)d_in[11];
    const float* btt = (const float*)d_in[12];
    float* out = (float*)d_out;

    __half *vtok, *ttok, *wvtT, *wttT, *wvT, *wtT;
    cudaGetSymbolAddress((void**)&vtok, g_vtok);
    cudaGetSymbolAddress((void**)&ttok, g_ttok);
    cudaGetSymbolAddress((void**)&wvtT, g_wvtT);
    cudaGetSymbolAddress((void**)&wttT, g_wttT);
    cudaGetSymbolAddress((void**)&wvT, g_wvT);
    cudaGetSymbolAddress((void**)&wtT, g_wtT);

    const int proj_smem = (64 * 136 + 256 * 136) * sizeof(__half);        // 87040
    const int sim_smem  = (128 * SVS + 128 * STS) * sizeof(__half);       // 102400
    cudaFuncSetAttribute(proj_kernel, cudaFuncAttributeMaxDynamicSharedMemorySize, proj_smem);
    cudaFuncSetAttribute(sim_kernel,  cudaFuncAttributeMaxDynamicSharedMemorySize, sim_smem);

    wprep_kernel<<<dim3(6, 8, 4), 256>>>(Wvt, Wtt, Wv, Wt, wvtT, wttT, wvT, wtT);

    proj_kernel<<<263, 256, proj_smem>>>(
        visual_cls, textual_cls, visual_tokens, textual_tokens,
        bv, bt, bvt, btt, wvtT, wttT, wvT, wtT,
        out, vtok, ttok);

    sim_kernel<<<dim3(32, 64), 256, sim_smem>>>(vtok, ttok, text_length, out);
}

// round 13
// speedup vs baseline: 9.5423x; 1.0076x over previous
#include <cuda_runtime.h>
#include <cuda_fp16.h>
#include <math.h>
#include <stdint.h>

#define BB 64
#define VV 197
#define LL 64
#define DD 768
#define EE 256

// Scratch: projected + normalized tokens in fp16, transposed half weights
__device__ __align__(16) __half g_vtok[(size_t)BB * VV * EE]; // 6.45 MB
__device__ __align__(16) __half g_ttok[(size_t)BB * LL * EE]; // 2.1 MB
__device__ __align__(16) __half g_wvtT[(size_t)EE * DD];      // [n][k]
__device__ __align__(16) __half g_wttT[(size_t)EE * DD];
__device__ __align__(16) __half g_wvT[(size_t)EE * DD];
__device__ __align__(16) __half g_wtT[(size_t)EE * DD];

// ---------------------------------------------------------------------------
// helpers
// ---------------------------------------------------------------------------
__device__ __forceinline__ void mma16(float* c, unsigned a0, unsigned a1, unsigned a2,
                                      unsigned a3, unsigned b0, unsigned b1) {
    asm volatile(
        "mma.sync.aligned.m16n8k16.row.col.f32.f16.f16.f32 "
        "{%0,%1,%2,%3},{%4,%5,%6,%7},{%8,%9},{%0,%1,%2,%3};\n"
        : "+f"(c[0]), "+f"(c[1]), "+f"(c[2]), "+f"(c[3])
        : "r"(a0), "r"(a1), "r"(a2), "r"(a3), "r"(b0), "r"(b1));
}

__device__ __forceinline__ void cpa16(unsigned s, const void* g) {
    asm volatile("cp.async.cg.shared.global [%0], [%1], 16;" :: "r"(s), "l"(g) : "memory");
}
__device__ __forceinline__ void cpa_commit() {
    asm volatile("cp.async.commit_group;" ::: "memory");
}
__device__ __forceinline__ void cpa_wait0() {
    asm volatile("cp.async.wait_group 0;" ::: "memory");
}
__device__ __forceinline__ unsigned s2u(const void* p) {
    return (unsigned)__cvta_generic_to_shared(p);
}

// ---------------------------------------------------------------------------
// W transpose + fp32->fp16 prepass: W[768][256] -> WT[256][768] half.
// grid (24, 8, 4), block (32, 8). z: 0=Wvt 1=Wtt 2=Wv 3=Wt.
// (R10/R11 version: 768 small blocks, latency-friendly, measured ~4.8us.)
// ---------------------------------------------------------------------------
__global__ void wprep_kernel(const float* __restrict__ Wvt, const float* __restrict__ Wtt,
                             const float* __restrict__ Wv, const float* __restrict__ Wt,
                             __half* __restrict__ WvtT, __half* __restrict__ WttT,
                             __half* __restrict__ WvT, __half* __restrict__ WtT)
{
    __shared__ float t[32][33];
    const float* W;
    __half* WT;
    switch (blockIdx.z) {
        case 0: W = Wvt; WT = WvtT; break;
        case 1: W = Wtt; WT = WttT; break;
        case 2: W = Wv;  WT = WvT;  break;
        default: W = Wt; WT = WtT;  break;
    }
    int kb = blockIdx.x * 32, nb = blockIdx.y * 32;
    int tx = threadIdx.x, ty = threadIdx.y;
    #pragma unroll
    for (int j = 0; j < 4; j++)
        t[ty + 8 * j][tx] = W[(size_t)(kb + ty + 8 * j) * EE + nb + tx];
    __syncthreads();
    #pragma unroll
    for (int j = 0; j < 4; j++)
        WT[(size_t)(nb + ty + 8 * j) * DD + kb + tx] = __float2half(t[tx][ty + 8 * j]);
}

// ---------------------------------------------------------------------------
// Unified projection (fp16 MMA m16n8k16, fp32 accum), 2 blocks/SM.
// One block = 64 rows x 256 cols, K=768 in chunks of 128.
// Grid: [0,197) vtok (+bias+l2norm, half out), [197,261) ttok (same),
//       261 vcls (+bias, fp32 out), 262 tcls (+bias, fp32 out).
// ---------------------------------------------------------------------------
__global__ __launch_bounds__(256, 2) void proj_kernel(
    const float* __restrict__ visual_cls, const float* __restrict__ textual_cls,
    const float* __restrict__ vtokA, const float* __restrict__ ttokA,
    const float* __restrict__ bv, const float* __restrict__ bt,
    const float* __restrict__ bvt, const float* __restrict__ btt,
    const __half* __restrict__ WvtT, const __half* __restrict__ WttT,
    const __half* __restrict__ WvT, const __half* __restrict__ WtT,
    float* __restrict__ out, __half* __restrict__ vtokC, __half* __restrict__ ttokC)
{
    extern __shared__ float sm[];
    __shared__ float sbias[256];
    __shared__ float rowsq[64 * 5];
    __shared__ float sinv[64];

    __half* sAh = (__half*)sm;               // 64 x 136
    __half* sWh = (__half*)sm + 64 * 136;    // 256 x 136

    const int bid = blockIdx.x;

    const float* A;
    const __half* WT;
    const float* bias;
    __half* C = nullptr;
    float* Cf = nullptr;
    int mbase = 0;
    bool do_norm;
    if (bid < 197)      { A = vtokA;       WT = WvtT; bias = bvt; C = vtokC; mbase = bid * 64;        do_norm = true;  }
    else if (bid < 261) { A = ttokA;       WT = WttT; bias = btt; C = ttokC; mbase = (bid - 197) * 64; do_norm = true;  }
    else if (bid == 261){ A = visual_cls;  WT = WvT;  bias = bv;  Cf = out;              do_norm = false; }
    else                { A = textual_cls; WT = WtT;  bias = bt;  Cf = out + 16384;      do_norm = false; }

    const int tid = threadIdx.x;
    const int lane = tid & 31, w = tid >> 5;
    const int lq = lane >> 2, lr = lane & 3;
    const int vg = w >> 2, nw = w & 3;
    const int rbase = vg * 32;
    const int nb = nw * 64;

    sbias[tid] = bias[tid];

    const unsigned sWu = s2u(sWh);

    float acc[2][8][4] = {};

    for (int k0 = 0; k0 < DD; k0 += 128) {
        // W chunk: 256 n-rows x 128 k halves via cp.async (16 x 16B per row)
        #pragma unroll
        for (int it = 0; it < 16; it++) {
            int idx = tid + it * 256;        // 0..4095
            int r = idx >> 4;                // 0..255
            int c16 = idx & 15;              // 16-byte chunk (8 halves)
            cpa16(sWu + (unsigned)(r * 136 + c16 * 8) * 2,
                  WT + (size_t)r * DD + k0 + c16 * 8);
        }
        cpa_commit();
        // A chunk: 64 rows x 128 k, fp32 -> half in-register
        #pragma unroll
        for (int it = 0; it < 8; it++) {
            int idx = tid + it * 256;        // 0..2047
            int r = idx >> 5;                // 0..63
            int c4 = idx & 31;               // float4 unit along k
            float4 v = *(const float4*)(A + (size_t)(mbase + r) * DD + k0 + c4 * 4);
            __half2 h0 = __floats2half2_rn(v.x, v.y);
            __half2 h1 = __floats2half2_rn(v.z, v.w);
            uint2 pk = make_uint2(*(unsigned*)&h0, *(unsigned*)&h1);
            *(uint2*)(sAh + r * 136 + c4 * 4) = pk;
        }
        cpa_wait0();
        __syncthreads();

        #pragma unroll
        for (int ks = 0; ks < 8; ks++) {
            unsigned b0[8], b1[8];
            #pragma unroll
            for (int ng = 0; ng < 8; ng++) {
                const __half* p = sWh + (nb + 8 * ng + lq) * 136 + ks * 16 + 2 * lr;
                b0[ng] = *(const unsigned*)p;
                b1[ng] = *(const unsigned*)(p + 8);
            }
            #pragma unroll
            for (int rg = 0; rg < 2; rg++) {
                const __half* p = sAh + (rbase + 16 * rg + lq) * 136 + ks * 16 + 2 * lr;
                unsigned a0 = *(const unsigned*)p;
                unsigned a1 = *(const unsigned*)(p + 8 * 136);
                unsigned a2 = *(const unsigned*)(p + 8);
                unsigned a3 = *(const unsigned*)(p + 8 * 136 + 8);
                #pragma unroll
                for (int ng = 0; ng < 8; ng++)
                    mma16(acc[rg][ng], a0, a1, a2, a3, b0[ng], b1[ng]);
            }
        }
        __syncthreads();
    }

    // bias
    #pragma unroll
    for (int rg = 0; rg < 2; rg++)
        #pragma unroll
        for (int ng = 0; ng < 8; ng++) {
            int col = nb + 8 * ng + 2 * lr;
            float c0 = sbias[col], c1 = sbias[col + 1];
            acc[rg][ng][0] += c0; acc[rg][ng][1] += c1;
            acc[rg][ng][2] += c0; acc[rg][ng][3] += c1;
        }

    if (!do_norm) {
        #pragma unroll
        for (int rg = 0; rg < 2; rg++) {
            int r0 = rbase + 16 * rg + lq;
            #pragma unroll
            for (int ng = 0; ng < 8; ng++) {
                int col = nb + 8 * ng + 2 * lr;
                *(float2*)(Cf + (size_t)r0 * EE + col) =
                    make_float2(acc[rg][ng][0], acc[rg][ng][1]);
                *(float2*)(Cf + (size_t)(r0 + 8) * EE + col) =
                    make_float2(acc[rg][ng][2], acc[rg][ng][3]);
            }
        }
        return;
    }

    // l2norm: per-row sum of squares
    #pragma unroll
    for (int rg = 0; rg < 2; rg++) {
        float s0 = 0.f, s1 = 0.f;
        #pragma unroll
        for (int ng = 0; ng < 8; ng++) {
            s0 += acc[rg][ng][0] * acc[rg][ng][0] + acc[rg][ng][1] * acc[rg][ng][1];
            s1 += acc[rg][ng][2] * acc[rg][ng][2] + acc[rg][ng][3] * acc[rg][ng][3];
        }
        s0 += __shfl_xor_sync(0xffffffffu, s0, 1);
        s0 += __shfl_xor_sync(0xffffffffu, s0, 2);
        s1 += __shfl_xor_sync(0xffffffffu, s1, 1);
        s1 += __shfl_xor_sync(0xffffffffu, s1, 2);
        if (lr == 0) {
            rowsq[(rbase + 16 * rg + lq) * 5 + nw] = s0;
            rowsq[(rbase + 16 * rg + lq + 8) * 5 + nw] = s1;
        }
    }
    __syncthreads();
    if (tid < 64) {
        float s = rowsq[tid * 5] + rowsq[tid * 5 + 1] + rowsq[tid * 5 + 2] + rowsq[tid * 5 + 3];
        sinv[tid] = 1.0f / fmaxf(sqrtf(s), 1e-12f);
    }
    __syncthreads();

    #pragma unroll
    for (int rg = 0; rg < 2; rg++) {
        int r0 = rbase + 16 * rg + lq;
        float inv0 = sinv[r0], inv1 = sinv[r0 + 8];
        #pragma unroll
        for (int ng = 0; ng < 8; ng++) {
            int col = nb + 8 * ng + 2 * lr;
            __half2 h0 = __floats2half2_rn(acc[rg][ng][0] * inv0, acc[rg][ng][1] * inv0);
            __half2 h1 = __floats2half2_rn(acc[rg][ng][2] * inv1, acc[rg][ng][3] * inv1);
            *(__half2*)(C + (size_t)(mbase + r0) * EE + col) = h0;
            *(__half2*)(C + (size_t)(mbase + r0 + 8) * EE + col) = h1;
        }
    }
}

// ---------------------------------------------------------------------------
// Fused sim kernel (fp16 MMA m16n8k16, f32 accum).
// grid = (qpair=32, b=64), 256 threads (8 warps = 4 v-groups x 2 t-groups).
// Block tile 128v x 128t. sT resident for full K=256; sV streamed as a flat
// list of 4 chunks with lookahead cp.async (chunk c+1 issued right after
// chunk c's MMAs sync, hiding pass-boundary load latency under the
// epilogue). m16 padding elision: rows issued 224 -> 208 of 197 valid.
// ---------------------------------------------------------------------------
#define SVS 136
#define STS 264

__global__ __launch_bounds__(256, 2) void sim_kernel(
    const __half* __restrict__ vtok, const __half* __restrict__ ttok,
    const int* __restrict__ text_length, float* __restrict__ out)
{
    extern __shared__ __half smh[];
    __half* sV = smh;                  // 128 x SVS
    __half* sT = smh + 128 * SVS;      // 128 x STS (full K)

    __shared__ float t2i_part[4][128];
    __shared__ float t2i_run[128];
    __shared__ float wsum[8];

    const int tid = threadIdx.x;
    const int lane = tid & 31, w = tid >> 5;
    const int lq = lane >> 2, lr = lane & 3;
    const int vb = (w >> 1) * 32;
    const int tb = (w & 1) * 64;
    const int qp = blockIdx.x, b = blockIdx.y;

    const __half* vbase = vtok + (size_t)b * VV * EE;
    const __half* tbase = ttok + (size_t)(qp * 2) * LL * EE;

    unsigned sVu = (unsigned)__cvta_generic_to_shared(sV);
    unsigned sTu = (unsigned)__cvta_generic_to_shared(sT);

    // sT: full 128 t-rows x 256 k (once per block) + sV chunk 0
    #pragma unroll
    for (int it = 0; it < 16; it++) {
        int idx = tid + it * 256;
        int r = idx >> 5;
        int c8 = idx & 31;
        cpa16(sTu + (unsigned)(r * STS + c8 * 8) * 2, tbase + (size_t)r * EE + c8 * 8);
    }
    #pragma unroll
    for (int it = 0; it < 8; it++) {
        int idx = tid + it * 256;
        int r = idx >> 4;
        int c8 = idx & 15;
        int vr = min(r, VV - 1);
        cpa16(sVu + (unsigned)(r * SVS + c8 * 8) * 2,
              vbase + (size_t)vr * EE + c8 * 8);
    }
    cpa_commit();

    float i2t_wsum = 0.0f;
    float acc[2][8][4];

    #pragma unroll
    for (int c = 0; c < 4; ++c) {
        const int pass = c >> 1, kc = c & 1;
        const int v0 = pass * 128;
        const bool active = (v0 + vb) < VV;
        const bool rgok0 = (v0 + vb) < VV;
        const bool rgok1 = (v0 + vb + 16) < VV;

        if (kc == 0) {
            #pragma unroll
            for (int rg = 0; rg < 2; rg++)
                #pragma unroll
                for (int ng = 0; ng < 8; ng++)
                    #pragma unroll
                    for (int j = 0; j < 4; j++) acc[rg][ng][j] = 0.0f;
        }

        cpa_wait0();
        __syncthreads();

        if (active) {
            #pragma unroll
            for (int ks = 0; ks < 8; ks++) {
                unsigned b0[8], b1[8];
                #pragma unroll
                for (int ng = 0; ng < 8; ng++) {
                    const __half* p = sT + (tb + 8 * ng + lq) * STS + kc * 128 + ks * 16 + 2 * lr;
                    b0[ng] = *(const unsigned*)p;
                    b1[ng] = *(const unsigned*)(p + 8);
                }
                #pragma unroll
                for (int rg = 0; rg < 2; rg++) {
                    if (rg == 0 ? rgok0 : rgok1) {
                        const __half* p = sV + (vb + 16 * rg + lq) * SVS + ks * 16 + 2 * lr;
                        unsigned a0 = *(const unsigned*)p;
                        unsigned a1 = *(const unsigned*)(p + 8 * SVS);
                        unsigned a2 = *(const unsigned*)(p + 8);
                        unsigned a3 = *(const unsigned*)(p + 8 * SVS + 8);
                        #pragma unroll
                        for (int ng = 0; ng < 8; ng++)
                            mma16(acc[rg][ng], a0, a1, a2, a3, b0[ng], b1[ng]);
                    }
                }
            }
        }
        __syncthreads();   // MMAs done block-wide -> sV free for next chunk

        // lookahead: issue next chunk's sV loads
        if (c < 3) {
            const int nc = c + 1;
            const int np = nc >> 1, nkc = nc & 1;
            const int nv0 = np * 128;
            const int itmax = (np == 0) ? 8 : 5;
            for (int it = 0; it < itmax; it++) {
                int idx = tid + it * 256;
                int r = idx >> 4;
                int c8 = idx & 15;
                int vr = min(nv0 + r, VV - 1);
                cpa16(sVu + (unsigned)(r * SVS + c8 * 8) * 2,
                      vbase + (size_t)vr * EE + nkc * 128 + c8 * 8);
            }
            cpa_commit();
        }

        if (kc == 1) {
            // ---- i2t: per-v-row max over this warp's 64 t cols ----
            float rsum = 0.0f;
            #pragma unroll
            for (int rg = 0; rg < 2; rg++) {
                float m0 = -1e30f, m1 = -1e30f;
                #pragma unroll
                for (int ng = 0; ng < 8; ng++) {
                    m0 = fmaxf(m0, fmaxf(acc[rg][ng][0], acc[rg][ng][1]));
                    m1 = fmaxf(m1, fmaxf(acc[rg][ng][2], acc[rg][ng][3]));
                }
                m0 = fmaxf(m0, __shfl_xor_sync(0xffffffffu, m0, 1));
                m0 = fmaxf(m0, __shfl_xor_sync(0xffffffffu, m0, 2));
                m1 = fmaxf(m1, __shfl_xor_sync(0xffffffffu, m1, 1));
                m1 = fmaxf(m1, __shfl_xor_sync(0xffffffffu, m1, 2));
                int r0 = v0 + vb + 16 * rg + lq;
                if (lr == 0) {
                    if (r0 < VV) rsum += m0;
                    if (r0 + 8 < VV) rsum += m1;
                }
            }
            #pragma unroll
            for (int off = 16; off > 0; off >>= 1)
                rsum += __shfl_xor_sync(0xffffffffu, rsum, off);
            i2t_wsum += rsum;

            // ---- t2i: per-t-col max over this warp's 32 v rows (masked) ----
            #pragma unroll
            for (int ng = 0; ng < 8; ng++) {
                float m0 = -1e30f, m1 = -1e30f;
                #pragma unroll
                for (int rg = 0; rg < 2; rg++) {
                    int r0 = v0 + vb + 16 * rg + lq;
                    if (r0 < VV) {
                        m0 = fmaxf(m0, acc[rg][ng][0]);
                        m1 = fmaxf(m1, acc[rg][ng][1]);
                    }
                    if (r0 + 8 < VV) {
                        m0 = fmaxf(m0, acc[rg][ng][2]);
                        m1 = fmaxf(m1, acc[rg][ng][3]);
                    }
                }
                m0 = fmaxf(m0, __shfl_xor_sync(0xffffffffu, m0, 4));
                m0 = fmaxf(m0, __shfl_xor_sync(0xffffffffu, m0, 8));
                m0 = fmaxf(m0, __shfl_xor_sync(0xffffffffu, m0, 16));
                m1 = fmaxf(m1, __shfl_xor_sync(0xffffffffu, m1, 4));
                m1 = fmaxf(m1, __shfl_xor_sync(0xffffffffu, m1, 8));
                m1 = fmaxf(m1, __shfl_xor_sync(0xffffffffu, m1, 16));
                if (lane < 4) {
                    t2i_part[w >> 1][tb + 8 * ng + 2 * lane] = m0;
                    t2i_part[w >> 1][tb + 8 * ng + 2 * lane + 1] = m1;
                }
            }
            __syncthreads();
            if (tid < 128) {
                float m = fmaxf(fmaxf(t2i_part[0][tid], t2i_part[1][tid]),
                                fmaxf(t2i_part[2][tid], t2i_part[3][tid]));
                t2i_run[tid] = (v0 == 0) ? m : fmaxf(t2i_run[tid], m);
            }
            __syncthreads();
        }
    }

    if (lane == 0) wsum[w] = i2t_wsum;
    __syncthreads();

    // t2i outputs: warp 0 -> q0, warp 1 -> q1
    if (tid < 64) {
        int w2 = tid >> 5;
        int l2 = tid & 31;
        int len = text_length[b];   // reference quirk: indexed by b
        float s = 0.0f;
        if (l2 < len) s += t2i_run[w2 * 64 + l2];
        if (l2 + 32 < len) s += t2i_run[w2 * 64 + l2 + 32];
        #pragma unroll
        for (int off = 16; off > 0; off >>= 1)
            s += __shfl_xor_sync(0xffffffffu, s, off);
        if (l2 == 0)
            out[36864 + b * 64 + qp * 2 + w2] = s / fmaxf((float)len, 1e-6f);
    }
    // i2t outputs
    if (tid == 128 || tid == 129) {
        int j = tid - 128;
        float s = wsum[j] + wsum[j + 2] + wsum[j + 4] + wsum[j + 6];
        out[32768 + b * 64 + qp * 2 + j] = s / (float)VV;
    }
}

// ---------------------------------------------------------------------------
extern "C" void kernel_launch(void* const* d_in, const int* in_sizes, int n_in,
                              void* d_out, int out_size)
{
    const float* visual_cls     = (const float*)d_in[0];
    const float* textual_cls    = (const float*)d_in[1];
    const float* visual_tokens  = (const float*)d_in[2];
    const float* textual_tokens = (const float*)d_in[3];
    const int*   text_length    = (const int*)  d_in[4];
    const float* Wv  = (const float*)d_in[5];
    const float* bv  = (const float*)d_in[6];
    const float* Wt  = (const float*)d_in[7];
    const float* bt  = (const float*)d_in[8];
    const float* Wvt = (const float*)d_in[9];
    const float* bvt = (const float*)d_in[10];
    const float* Wtt = (const float*)d_in[11];
    const float* btt = (const float*)d_in[12];
    float* out = (float*)d_out;

    __half *vtok, *ttok, *wvtT, *wttT, *wvT, *wtT;
    cudaGetSymbolAddress((void**)&vtok, g_vtok);
    cudaGetSymbolAddress((void**)&ttok, g_ttok);
    cudaGetSymbolAddress((void**)&wvtT, g_wvtT);
    cudaGetSymbolAddress((void**)&wttT, g_wttT);
    cudaGetSymbolAddress((void**)&wvT, g_wvT);
    cudaGetSymbolAddress((void**)&wtT, g_wtT);

    const int proj_smem = (64 * 136 + 256 * 136) * sizeof(__half);        // 87040
    const int sim_smem  = (128 * SVS + 128 * STS) * sizeof(__half);       // 102400
    cudaFuncSetAttribute(proj_kernel, cudaFuncAttributeMaxDynamicSharedMemorySize, proj_smem);
    cudaFuncSetAttribute(sim_kernel,  cudaFuncAttributeMaxDynamicSharedMemorySize, sim_smem);

    wprep_kernel<<<dim3(24, 8, 4), dim3(32, 8)>>>(Wvt, Wtt, Wv, Wt, wvtT, wttT, wvT, wtT);

    proj_kernel<<<263, 256, proj_smem>>>(
        visual_cls, textual_cls, visual_tokens, textual_tokens,
        bv, bt, bvt, btt, wvtT, wttT, wvT, wtT,
        out, vtok, ttok);

    sim_kernel<<<dim3(32, 64), 256, sim_smem>>>(vtok, ttok, text_length, out);
}

// round 14
// speedup vs baseline: 9.5835x; 1.0043x over previous
#include <cuda_runtime.h>
#include <cuda_fp16.h>
#include <math.h>
#include <stdint.h>

#define BB 64
#define VV 197
#define LL 64
#define DD 768
#define EE 256

// Scratch: projected + normalized tokens in fp16, transposed half weights
__device__ __align__(16) __half g_vtok[(size_t)BB * VV * EE]; // 6.45 MB
__device__ __align__(16) __half g_ttok[(size_t)BB * LL * EE]; // 2.1 MB
__device__ __align__(16) __half g_wvtT[(size_t)EE * DD];      // [n][k]
__device__ __align__(16) __half g_wttT[(size_t)EE * DD];
__device__ __align__(16) __half g_wvT[(size_t)EE * DD];
__device__ __align__(16) __half g_wtT[(size_t)EE * DD];

// ---------------------------------------------------------------------------
// helpers
// ---------------------------------------------------------------------------
__device__ __forceinline__ void mma16(float* c, unsigned a0, unsigned a1, unsigned a2,
                                      unsigned a3, unsigned b0, unsigned b1) {
    asm volatile(
        "mma.sync.aligned.m16n8k16.row.col.f32.f16.f16.f32 "
        "{%0,%1,%2,%3},{%4,%5,%6,%7},{%8,%9},{%0,%1,%2,%3};\n"
        : "+f"(c[0]), "+f"(c[1]), "+f"(c[2]), "+f"(c[3])
        : "r"(a0), "r"(a1), "r"(a2), "r"(a3), "r"(b0), "r"(b1));
}

__device__ __forceinline__ void cpa16(unsigned s, const void* g) {
    asm volatile("cp.async.cg.shared.global [%0], [%1], 16;" :: "r"(s), "l"(g) : "memory");
}
__device__ __forceinline__ void cpa_commit() {
    asm volatile("cp.async.commit_group;" ::: "memory");
}
__device__ __forceinline__ void cpa_wait0() {
    asm volatile("cp.async.wait_group 0;" ::: "memory");
}
__device__ __forceinline__ unsigned s2u(const void* p) {
    return (unsigned)__cvta_generic_to_shared(p);
}

// ---------------------------------------------------------------------------
// W transpose + fp32->fp16 prepass: W[768][256] -> WT[256][768] half.
// grid (24, 8, 4), block (32, 8). z: 0=Wvt 1=Wtt 2=Wv 3=Wt.
// Triggers PDL early so proj can launch and run its prologue concurrently.
// ---------------------------------------------------------------------------
__global__ void wprep_kernel(const float* __restrict__ Wvt, const float* __restrict__ Wtt,
                             const float* __restrict__ Wv, const float* __restrict__ Wt,
                             __half* __restrict__ WvtT, __half* __restrict__ WttT,
                             __half* __restrict__ WvT, __half* __restrict__ WtT)
{
    cudaTriggerProgrammaticLaunchCompletion();

    __shared__ float t[32][33];
    const float* W;
    __half* WT;
    switch (blockIdx.z) {
        case 0: W = Wvt; WT = WvtT; break;
        case 1: W = Wtt; WT = WttT; break;
        case 2: W = Wv;  WT = WvT;  break;
        default: W = Wt; WT = WtT;  break;
    }
    int kb = blockIdx.x * 32, nb = blockIdx.y * 32;
    int tx = threadIdx.x, ty = threadIdx.y;
    #pragma unroll
    for (int j = 0; j < 4; j++)
        t[ty + 8 * j][tx] = W[(size_t)(kb + ty + 8 * j) * EE + nb + tx];
    __syncthreads();
    #pragma unroll
    for (int j = 0; j < 4; j++)
        WT[(size_t)(nb + ty + 8 * j) * DD + kb + tx] = __float2half(t[tx][ty + 8 * j]);
}

// ---------------------------------------------------------------------------
// Unified projection (fp16 MMA m16n8k16, fp32 accum), 2 blocks/SM.
// One block = 64 rows x 256 cols, K=768 in chunks of 128.
// PDL: prefills A chunk 0 (input tokens only), then grid-dep-syncs on wprep
// before the first W cp.async. Triggers early so sim can get resident.
// Grid: [0,197) vtok (+bias+l2norm, half out), [197,261) ttok (same),
//       261 vcls (+bias, fp32 out), 262 tcls (+bias, fp32 out).
// ---------------------------------------------------------------------------
__global__ __launch_bounds__(256, 2) void proj_kernel(
    const float* __restrict__ visual_cls, const float* __restrict__ textual_cls,
    const float* __restrict__ vtokA, const float* __restrict__ ttokA,
    const float* __restrict__ bv, const float* __restrict__ bt,
    const float* __restrict__ bvt, const float* __restrict__ btt,
    const __half* __restrict__ WvtT, const __half* __restrict__ WttT,
    const __half* __restrict__ WvT, const __half* __restrict__ WtT,
    float* __restrict__ out, __half* __restrict__ vtokC, __half* __restrict__ ttokC)
{
    cudaTriggerProgrammaticLaunchCompletion();

    extern __shared__ float sm[];
    __shared__ float sbias[256];
    __shared__ float rowsq[64 * 5];
    __shared__ float sinv[64];

    __half* sAh = (__half*)sm;               // 64 x 136
    __half* sWh = (__half*)sm + 64 * 136;    // 256 x 136

    const int bid = blockIdx.x;

    const float* A;
    const __half* WT;
    const float* bias;
    __half* C = nullptr;
    float* Cf = nullptr;
    int mbase = 0;
    bool do_norm;
    if (bid < 197)      { A = vtokA;       WT = WvtT; bias = bvt; C = vtokC; mbase = bid * 64;        do_norm = true;  }
    else if (bid < 261) { A = ttokA;       WT = WttT; bias = btt; C = ttokC; mbase = (bid - 197) * 64; do_norm = true;  }
    else if (bid == 261){ A = visual_cls;  WT = WvT;  bias = bv;  Cf = out;              do_norm = false; }
    else                { A = textual_cls; WT = WtT;  bias = bt;  Cf = out + 16384;      do_norm = false; }

    const int tid = threadIdx.x;
    const int lane = tid & 31, w = tid >> 5;
    const int lq = lane >> 2, lr = lane & 3;
    const int vg = w >> 2, nw = w & 3;
    const int rbase = vg * 32;
    const int nb = nw * 64;

    sbias[tid] = bias[tid];

    const unsigned sWu = s2u(sWh);

    // Prefill A chunk 0 (reads only input tokens — independent of wprep)
    #pragma unroll
    for (int it = 0; it < 8; it++) {
        int idx = tid + it * 256;        // 0..2047
        int r = idx >> 5;                // 0..63
        int c4 = idx & 31;               // float4 unit along k
        float4 v = *(const float4*)(A + (size_t)(mbase + r) * DD + c4 * 4);
        __half2 h0 = __floats2half2_rn(v.x, v.y);
        __half2 h1 = __floats2half2_rn(v.z, v.w);
        uint2 pk = make_uint2(*(unsigned*)&h0, *(unsigned*)&h1);
        *(uint2*)(sAh + r * 136 + c4 * 4) = pk;
    }

    // Wait for wprep's WT to be complete + visible
    cudaGridDependencySynchronize();

    float acc[2][8][4] = {};

    for (int k0 = 0; k0 < DD; k0 += 128) {
        // W chunk: 256 n-rows x 128 k halves via cp.async (16 x 16B per row)
        #pragma unroll
        for (int it = 0; it < 16; it++) {
            int idx = tid + it * 256;        // 0..4095
            int r = idx >> 4;                // 0..255
            int c16 = idx & 15;              // 16-byte chunk (8 halves)
            cpa16(sWu + (unsigned)(r * 136 + c16 * 8) * 2,
                  WT + (size_t)r * DD + k0 + c16 * 8);
        }
        cpa_commit();
        // A chunk: 64 rows x 128 k, fp32 -> half in-register (chunk 0 prefilled)
        if (k0 > 0) {
            #pragma unroll
            for (int it = 0; it < 8; it++) {
                int idx = tid + it * 256;        // 0..2047
                int r = idx >> 5;                // 0..63
                int c4 = idx & 31;               // float4 unit along k
                float4 v = *(const float4*)(A + (size_t)(mbase + r) * DD + k0 + c4 * 4);
                __half2 h0 = __floats2half2_rn(v.x, v.y);
                __half2 h1 = __floats2half2_rn(v.z, v.w);
                uint2 pk = make_uint2(*(unsigned*)&h0, *(unsigned*)&h1);
                *(uint2*)(sAh + r * 136 + c4 * 4) = pk;
            }
        }
        cpa_wait0();
        __syncthreads();

        #pragma unroll
        for (int ks = 0; ks < 8; ks++) {
            unsigned b0[8], b1[8];
            #pragma unroll
            for (int ng = 0; ng < 8; ng++) {
                const __half* p = sWh + (nb + 8 * ng + lq) * 136 + ks * 16 + 2 * lr;
                b0[ng] = *(const unsigned*)p;
                b1[ng] = *(const unsigned*)(p + 8);
            }
            #pragma unroll
            for (int rg = 0; rg < 2; rg++) {
                const __half* p = sAh + (rbase + 16 * rg + lq) * 136 + ks * 16 + 2 * lr;
                unsigned a0 = *(const unsigned*)p;
                unsigned a1 = *(const unsigned*)(p + 8 * 136);
                unsigned a2 = *(const unsigned*)(p + 8);
                unsigned a3 = *(const unsigned*)(p + 8 * 136 + 8);
                #pragma unroll
                for (int ng = 0; ng < 8; ng++)
                    mma16(acc[rg][ng], a0, a1, a2, a3, b0[ng], b1[ng]);
            }
        }
        __syncthreads();
    }

    // bias
    #pragma unroll
    for (int rg = 0; rg < 2; rg++)
        #pragma unroll
        for (int ng = 0; ng < 8; ng++) {
            int col = nb + 8 * ng + 2 * lr;
            float c0 = sbias[col], c1 = sbias[col + 1];
            acc[rg][ng][0] += c0; acc[rg][ng][1] += c1;
            acc[rg][ng][2] += c0; acc[rg][ng][3] += c1;
        }

    if (!do_norm) {
        #pragma unroll
        for (int rg = 0; rg < 2; rg++) {
            int r0 = rbase + 16 * rg + lq;
            #pragma unroll
            for (int ng = 0; ng < 8; ng++) {
                int col = nb + 8 * ng + 2 * lr;
                *(float2*)(Cf + (size_t)r0 * EE + col) =
                    make_float2(acc[rg][ng][0], acc[rg][ng][1]);
                *(float2*)(Cf + (size_t)(r0 + 8) * EE + col) =
                    make_float2(acc[rg][ng][2], acc[rg][ng][3]);
            }
        }
        return;
    }

    // l2norm: per-row sum of squares
    #pragma unroll
    for (int rg = 0; rg < 2; rg++) {
        float s0 = 0.f, s1 = 0.f;
        #pragma unroll
        for (int ng = 0; ng < 8; ng++) {
            s0 += acc[rg][ng][0] * acc[rg][ng][0] + acc[rg][ng][1] * acc[rg][ng][1];
            s1 += acc[rg][ng][2] * acc[rg][ng][2] + acc[rg][ng][3] * acc[rg][ng][3];
        }
        s0 += __shfl_xor_sync(0xffffffffu, s0, 1);
        s0 += __shfl_xor_sync(0xffffffffu, s0, 2);
        s1 += __shfl_xor_sync(0xffffffffu, s1, 1);
        s1 += __shfl_xor_sync(0xffffffffu, s1, 2);
        if (lr == 0) {
            rowsq[(rbase + 16 * rg + lq) * 5 + nw] = s0;
            rowsq[(rbase + 16 * rg + lq + 8) * 5 + nw] = s1;
        }
    }
    __syncthreads();
    if (tid < 64) {
        float s = rowsq[tid * 5] + rowsq[tid * 5 + 1] + rowsq[tid * 5 + 2] + rowsq[tid * 5 + 3];
        sinv[tid] = 1.0f / fmaxf(sqrtf(s), 1e-12f);
    }
    __syncthreads();

    #pragma unroll
    for (int rg = 0; rg < 2; rg++) {
        int r0 = rbase + 16 * rg + lq;
        float inv0 = sinv[r0], inv1 = sinv[r0 + 8];
        #pragma unroll
        for (int ng = 0; ng < 8; ng++) {
            int col = nb + 8 * ng + 2 * lr;
            __half2 h0 = __floats2half2_rn(acc[rg][ng][0] * inv0, acc[rg][ng][1] * inv0);
            __half2 h1 = __floats2half2_rn(acc[rg][ng][2] * inv1, acc[rg][ng][3] * inv1);
            *(__half2*)(C + (size_t)(mbase + r0) * EE + col) = h0;
            *(__half2*)(C + (size_t)(mbase + r0 + 8) * EE + col) = h1;
        }
    }
}

// ---------------------------------------------------------------------------
// Fused sim kernel (fp16 MMA m16n8k16, f32 accum).
// grid = (qpair=32, b=64), 256 threads (8 warps = 4 v-groups x 2 t-groups).
// PDL: grid-dep-syncs on proj before touching vtok/ttok; blocks get
// resident during proj's tail. Block tile 128v x 128t; sT resident for
// K=256; sV streamed as 4 chunks with lookahead cp.async; m16 padding
// elision (rows issued 208 of 197 valid).
// ---------------------------------------------------------------------------
#define SVS 136
#define STS 264

__global__ __launch_bounds__(256, 2) void sim_kernel(
    const __half* __restrict__ vtok, const __half* __restrict__ ttok,
    const int* __restrict__ text_length, float* __restrict__ out)
{
    extern __shared__ __half smh[];
    __half* sV = smh;                  // 128 x SVS
    __half* sT = smh + 128 * SVS;      // 128 x STS (full K)

    __shared__ float t2i_part[4][128];
    __shared__ float t2i_run[128];
    __shared__ float wsum[8];

    const int tid = threadIdx.x;
    const int lane = tid & 31, w = tid >> 5;
    const int lq = lane >> 2, lr = lane & 3;
    const int vb = (w >> 1) * 32;
    const int tb = (w & 1) * 64;
    const int qp = blockIdx.x, b = blockIdx.y;

    const __half* vbase = vtok + (size_t)b * VV * EE;
    const __half* tbase = ttok + (size_t)(qp * 2) * LL * EE;

    unsigned sVu = (unsigned)__cvta_generic_to_shared(sV);
    unsigned sTu = (unsigned)__cvta_generic_to_shared(sT);

    // Wait for proj's vtok/ttok to be complete + visible
    cudaGridDependencySynchronize();

    // sT: full 128 t-rows x 256 k (once per block) + sV chunk 0
    #pragma unroll
    for (int it = 0; it < 16; it++) {
        int idx = tid + it * 256;
        int r = idx >> 5;
        int c8 = idx & 31;
        cpa16(sTu + (unsigned)(r * STS + c8 * 8) * 2, tbase + (size_t)r * EE + c8 * 8);
    }
    #pragma unroll
    for (int it = 0; it < 8; it++) {
        int idx = tid + it * 256;
        int r = idx >> 4;
        int c8 = idx & 15;
        int vr = min(r, VV - 1);
        cpa16(sVu + (unsigned)(r * SVS + c8 * 8) * 2,
              vbase + (size_t)vr * EE + c8 * 8);
    }
    cpa_commit();

    float i2t_wsum = 0.0f;
    float acc[2][8][4];

    #pragma unroll
    for (int c = 0; c < 4; ++c) {
        const int pass = c >> 1, kc = c & 1;
        const int v0 = pass * 128;
        const bool active = (v0 + vb) < VV;
        const bool rgok0 = (v0 + vb) < VV;
        const bool rgok1 = (v0 + vb + 16) < VV;

        if (kc == 0) {
            #pragma unroll
            for (int rg = 0; rg < 2; rg++)
                #pragma unroll
                for (int ng = 0; ng < 8; ng++)
                    #pragma unroll
                    for (int j = 0; j < 4; j++) acc[rg][ng][j] = 0.0f;
        }

        cpa_wait0();
        __syncthreads();

        if (active) {
            #pragma unroll
            for (int ks = 0; ks < 8; ks++) {
                unsigned b0[8], b1[8];
                #pragma unroll
                for (int ng = 0; ng < 8; ng++) {
                    const __half* p = sT + (tb + 8 * ng + lq) * STS + kc * 128 + ks * 16 + 2 * lr;
                    b0[ng] = *(const unsigned*)p;
                    b1[ng] = *(const unsigned*)(p + 8);
                }
                #pragma unroll
                for (int rg = 0; rg < 2; rg++) {
                    if (rg == 0 ? rgok0 : rgok1) {
                        const __half* p = sV + (vb + 16 * rg + lq) * SVS + ks * 16 + 2 * lr;
                        unsigned a0 = *(const unsigned*)p;
                        unsigned a1 = *(const unsigned*)(p + 8 * SVS);
                        unsigned a2 = *(const unsigned*)(p + 8);
                        unsigned a3 = *(const unsigned*)(p + 8 * SVS + 8);
                        #pragma unroll
                        for (int ng = 0; ng < 8; ng++)
                            mma16(acc[rg][ng], a0, a1, a2, a3, b0[ng], b1[ng]);
                    }
                }
            }
        }
        __syncthreads();   // MMAs done block-wide -> sV free for next chunk

        // lookahead: issue next chunk's sV loads
        if (c < 3) {
            const int nc = c + 1;
            const int np = nc >> 1, nkc = nc & 1;
            const int nv0 = np * 128;
            const int itmax = (np == 0) ? 8 : 5;
            for (int it = 0; it < itmax; it++) {
                int idx = tid + it * 256;
                int r = idx >> 4;
                int c8 = idx & 15;
                int vr = min(nv0 + r, VV - 1);
                cpa16(sVu + (unsigned)(r * SVS + c8 * 8) * 2,
                      vbase + (size_t)vr * EE + nkc * 128 + c8 * 8);
            }
            cpa_commit();
        }

        if (kc == 1) {
            // ---- i2t: per-v-row max over this warp's 64 t cols ----
            float rsum = 0.0f;
            #pragma unroll
            for (int rg = 0; rg < 2; rg++) {
                float m0 = -1e30f, m1 = -1e30f;
                #pragma unroll
                for (int ng = 0; ng < 8; ng++) {
                    m0 = fmaxf(m0, fmaxf(acc[rg][ng][0], acc[rg][ng][1]));
                    m1 = fmaxf(m1, fmaxf(acc[rg][ng][2], acc[rg][ng][3]));
                }
                m0 = fmaxf(m0, __shfl_xor_sync(0xffffffffu, m0, 1));
                m0 = fmaxf(m0, __shfl_xor_sync(0xffffffffu, m0, 2));
                m1 = fmaxf(m1, __shfl_xor_sync(0xffffffffu, m1, 1));
                m1 = fmaxf(m1, __shfl_xor_sync(0xffffffffu, m1, 2));
                int r0 = v0 + vb + 16 * rg + lq;
                if (lr == 0) {
                    if (r0 < VV) rsum += m0;
                    if (r0 + 8 < VV) rsum += m1;
                }
            }
            #pragma unroll
            for (int off = 16; off > 0; off >>= 1)
                rsum += __shfl_xor_sync(0xffffffffu, rsum, off);
            i2t_wsum += rsum;

            // ---- t2i: per-t-col max over this warp's 32 v rows (masked) ----
            #pragma unroll
            for (int ng = 0; ng < 8; ng++) {
                float m0 = -1e30f, m1 = -1e30f;
                #pragma unroll
                for (int rg = 0; rg < 2; rg++) {
                    int r0 = v0 + vb + 16 * rg + lq;
                    if (r0 < VV) {
                        m0 = fmaxf(m0, acc[rg][ng][0]);
                        m1 = fmaxf(m1, acc[rg][ng][1]);
                    }
                    if (r0 + 8 < VV) {
                        m0 = fmaxf(m0, acc[rg][ng][2]);
                        m1 = fmaxf(m1, acc[rg][ng][3]);
                    }
                }
                m0 = fmaxf(m0, __shfl_xor_sync(0xffffffffu, m0, 4));
                m0 = fmaxf(m0, __shfl_xor_sync(0xffffffffu, m0, 8));
                m0 = fmaxf(m0, __shfl_xor_sync(0xffffffffu, m0, 16));
                m1 = fmaxf(m1, __shfl_xor_sync(0xffffffffu, m1, 4));
                m1 = fmaxf(m1, __shfl_xor_sync(0xffffffffu, m1, 8));
                m1 = fmaxf(m1, __shfl_xor_sync(0xffffffffu, m1, 16));
                if (lane < 4) {
                    t2i_part[w >> 1][tb + 8 * ng + 2 * lane] = m0;
                    t2i_part[w >> 1][tb + 8 * ng + 2 * lane + 1] = m1;
                }
            }
            __syncthreads();
            if (tid < 128) {
                float m = fmaxf(fmaxf(t2i_part[0][tid], t2i_part[1][tid]),
                                fmaxf(t2i_part[2][tid], t2i_part[3][tid]));
                t2i_run[tid] = (v0 == 0) ? m : fmaxf(t2i_run[tid], m);
            }
            __syncthreads();
        }
    }

    if (lane == 0) wsum[w] = i2t_wsum;
    __syncthreads();

    // t2i outputs: warp 0 -> q0, warp 1 -> q1
    if (tid < 64) {
        int w2 = tid >> 5;
        int l2 = tid & 31;
        int len = text_length[b];   // reference quirk: indexed by b
        float s = 0.0f;
        if (l2 < len) s += t2i_run[w2 * 64 + l2];
        if (l2 + 32 < len) s += t2i_run[w2 * 64 + l2 + 32];
        #pragma unroll
        for (int off = 16; off > 0; off >>= 1)
            s += __shfl_xor_sync(0xffffffffu, s, off);
        if (l2 == 0)
            out[36864 + b * 64 + qp * 2 + w2] = s / fmaxf((float)len, 1e-6f);
    }
    // i2t outputs
    if (tid == 128 || tid == 129) {
        int j = tid - 128;
        float s = wsum[j] + wsum[j + 2] + wsum[j + 4] + wsum[j + 6];
        out[32768 + b * 64 + qp * 2 + j] = s / (float)VV;
    }
}

// ---------------------------------------------------------------------------
extern "C" void kernel_launch(void* const* d_in, const int* in_sizes, int n_in,
                              void* d_out, int out_size)
{
    const float* visual_cls     = (const float*)d_in[0];
    const float* textual_cls    = (const float*)d_in[1];
    const float* visual_tokens  = (const float*)d_in[2];
    const float* textual_tokens = (const float*)d_in[3];
    const int*   text_length    = (const int*)  d_in[4];
    const float* Wv  = (const float*)d_in[5];
    const float* bv  = (const float*)d_in[6];
    const float* Wt  = (const float*)d_in[7];
    const float* bt  = (const float*)d_in[8];
    const float* Wvt = (const float*)d_in[9];
    const float* bvt = (const float*)d_in[10];
    const float* Wtt = (const float*)d_in[11];
    const float* btt = (const float*)d_in[12];
    float* out = (float*)d_out;

    __half *vtok, *ttok, *wvtT, *wttT, *wvT, *wtT;
    cudaGetSymbolAddress((void**)&vtok, g_vtok);
    cudaGetSymbolAddress((void**)&ttok, g_ttok);
    cudaGetSymbolAddress((void**)&wvtT, g_wvtT);
    cudaGetSymbolAddress((void**)&wttT, g_wttT);
    cudaGetSymbolAddress((void**)&wvT, g_wvT);
    cudaGetSymbolAddress((void**)&wtT, g_wtT);

    const int proj_smem = (64 * 136 + 256 * 136) * sizeof(__half);        // 87040
    const int sim_smem  = (128 * SVS + 128 * STS) * sizeof(__half);       // 102400
    cudaFuncSetAttribute(proj_kernel, cudaFuncAttributeMaxDynamicSharedMemorySize, proj_smem);
    cudaFuncSetAttribute(sim_kernel,  cudaFuncAttributeMaxDynamicSharedMemorySize, sim_smem);

    wprep_kernel<<<dim3(24, 8, 4), dim3(32, 8)>>>(Wvt, Wtt, Wv, Wt, wvtT, wttT, wvT, wtT);

    // proj: programmatic dependent launch on wprep
    {
        cudaLaunchAttribute attr[1];
        attr[0].id = cudaLaunchAttributeProgrammaticStreamSerialization;
        attr[0].val.programmaticStreamSerializationAllowed = 1;
        cudaLaunchConfig_t cfg = {};
        cfg.gridDim = dim3(263, 1, 1);
        cfg.blockDim = dim3(256, 1, 1);
        cfg.dynamicSmemBytes = proj_smem;
        cfg.stream = 0;
        cfg.attrs = attr;
        cfg.numAttrs = 1;
        cudaLaunchKernelEx(&cfg, proj_kernel,
            visual_cls, textual_cls, visual_tokens, textual_tokens,
            bv, bt, bvt, btt,
            (const __half*)wvtT, (const __half*)wttT,
            (const __half*)wvT, (const __half*)wtT,
            out, vtok, ttok);
    }

    // sim: programmatic dependent launch on proj
    {
        cudaLaunchAttribute attr[1];
        attr[0].id = cudaLaunchAttributeProgrammaticStreamSerialization;
        attr[0].val.programmaticStreamSerializationAllowed = 1;
        cudaLaunchConfig_t cfg = {};
        cfg.gridDim = dim3(32, 64, 1);
        cfg.blockDim = dim3(256, 1, 1);
        cfg.dynamicSmemBytes = sim_smem;
        cfg.stream = 0;
        cfg.attrs = attr;
        cfg.numAttrs = 1;
        cudaLaunchKernelEx(&cfg, sim_kernel,
            (const __half*)vtok, (const __half*)ttok, text_length, out);
    }
}

// round 15
// speedup vs baseline: 9.6228x; 1.0041x over previous
#include <cuda_runtime.h>
#include <cuda_fp16.h>
#include <math.h>
#include <stdint.h>

#define BB 64
#define VV 197
#define LL 64
#define DD 768
#define EE 256

// Scratch: projected + normalized tokens in fp16, transposed half weights
__device__ __align__(16) __half g_vtok[(size_t)BB * VV * EE]; // 6.45 MB
__device__ __align__(16) __half g_ttok[(size_t)BB * LL * EE]; // 2.1 MB
__device__ __align__(16) __half g_wvtT[(size_t)EE * DD];      // [n][k]
__device__ __align__(16) __half g_wttT[(size_t)EE * DD];
__device__ __align__(16) __half g_wvT[(size_t)EE * DD];
__device__ __align__(16) __half g_wtT[(size_t)EE * DD];

// ---------------------------------------------------------------------------
// helpers
// ---------------------------------------------------------------------------
__device__ __forceinline__ void mma16(float* c, unsigned a0, unsigned a1, unsigned a2,
                                      unsigned a3, unsigned b0, unsigned b1) {
    asm volatile(
        "mma.sync.aligned.m16n8k16.row.col.f32.f16.f16.f32 "
        "{%0,%1,%2,%3},{%4,%5,%6,%7},{%8,%9},{%0,%1,%2,%3};\n"
        : "+f"(c[0]), "+f"(c[1]), "+f"(c[2]), "+f"(c[3])
        : "r"(a0), "r"(a1), "r"(a2), "r"(a3), "r"(b0), "r"(b1));
}

__device__ __forceinline__ void cpa16(unsigned s, const void* g) {
    asm volatile("cp.async.cg.shared.global [%0], [%1], 16;" :: "r"(s), "l"(g) : "memory");
}
__device__ __forceinline__ void cpa_commit() {
    asm volatile("cp.async.commit_group;" ::: "memory");
}
__device__ __forceinline__ void cpa_wait0() {
    asm volatile("cp.async.wait_group 0;" ::: "memory");
}
__device__ __forceinline__ unsigned s2u(const void* p) {
    return (unsigned)__cvta_generic_to_shared(p);
}

// ---------------------------------------------------------------------------
// W transpose + fp32->fp16 prepass: W[768][256] -> WT[256][768] half.
// grid (24, 8, 4), block (32, 8). z: 0=Wvt 1=Wtt 2=Wv 3=Wt.
// Triggers PDL early so proj can launch and run its prologue concurrently.
// ---------------------------------------------------------------------------
__global__ void wprep_kernel(const float* __restrict__ Wvt, const float* __restrict__ Wtt,
                             const float* __restrict__ Wv, const float* __restrict__ Wt,
                             __half* __restrict__ WvtT, __half* __restrict__ WttT,
                             __half* __restrict__ WvT, __half* __restrict__ WtT)
{
    cudaTriggerProgrammaticLaunchCompletion();

    __shared__ float t[32][33];
    const float* W;
    __half* WT;
    switch (blockIdx.z) {
        case 0: W = Wvt; WT = WvtT; break;
        case 1: W = Wtt; WT = WttT; break;
        case 2: W = Wv;  WT = WvT;  break;
        default: W = Wt; WT = WtT;  break;
    }
    int kb = blockIdx.x * 32, nb = blockIdx.y * 32;
    int tx = threadIdx.x, ty = threadIdx.y;
    #pragma unroll
    for (int j = 0; j < 4; j++)
        t[ty + 8 * j][tx] = W[(size_t)(kb + ty + 8 * j) * EE + nb + tx];
    __syncthreads();
    #pragma unroll
    for (int j = 0; j < 4; j++)
        WT[(size_t)(nb + ty + 8 * j) * DD + kb + tx] = __float2half(t[tx][ty + 8 * j]);
}

// ---------------------------------------------------------------------------
// Unified projection (fp16 MMA m16n8k16, fp32 accum), 2 blocks/SM.
// One block = 64 rows x 256 cols, K=768 in chunks of 128.
// PDL: prefills A chunk 0 (input tokens only), then grid-dep-syncs on wprep
// before the first W cp.async. Triggers early so sim can get resident.
// Grid: [0,197) vtok (+bias+l2norm, half out), [197,261) ttok (same),
//       261 vcls (+bias, fp32 out), 262 tcls (+bias, fp32 out).
// ---------------------------------------------------------------------------
__global__ __launch_bounds__(256, 2) void proj_kernel(
    const float* __restrict__ visual_cls, const float* __restrict__ textual_cls,
    const float* __restrict__ vtokA, const float* __restrict__ ttokA,
    const float* __restrict__ bv, const float* __restrict__ bt,
    const float* __restrict__ bvt, const float* __restrict__ btt,
    const __half* __restrict__ WvtT, const __half* __restrict__ WttT,
    const __half* __restrict__ WvT, const __half* __restrict__ WtT,
    float* __restrict__ out, __half* __restrict__ vtokC, __half* __restrict__ ttokC)
{
    cudaTriggerProgrammaticLaunchCompletion();

    extern __shared__ float sm[];
    __shared__ float sbias[256];
    __shared__ float rowsq[64 * 5];
    __shared__ float sinv[64];

    __half* sAh = (__half*)sm;               // 64 x 136
    __half* sWh = (__half*)sm + 64 * 136;    // 256 x 136

    const int bid = blockIdx.x;

    const float* A;
    const __half* WT;
    const float* bias;
    __half* C = nullptr;
    float* Cf = nullptr;
    int mbase = 0;
    bool do_norm;
    if (bid < 197)      { A = vtokA;       WT = WvtT; bias = bvt; C = vtokC; mbase = bid * 64;        do_norm = true;  }
    else if (bid < 261) { A = ttokA;       WT = WttT; bias = btt; C = ttokC; mbase = (bid - 197) * 64; do_norm = true;  }
    else if (bid == 261){ A = visual_cls;  WT = WvT;  bias = bv;  Cf = out;              do_norm = false; }
    else                { A = textual_cls; WT = WtT;  bias = bt;  Cf = out + 16384;      do_norm = false; }

    const int tid = threadIdx.x;
    const int lane = tid & 31, w = tid >> 5;
    const int lq = lane >> 2, lr = lane & 3;
    const int vg = w >> 2, nw = w & 3;
    const int rbase = vg * 32;
    const int nb = nw * 64;

    sbias[tid] = bias[tid];

    const unsigned sWu = s2u(sWh);

    // Prefill A chunk 0 (reads only input tokens — independent of wprep)
    #pragma unroll
    for (int it = 0; it < 8; it++) {
        int idx = tid + it * 256;        // 0..2047
        int r = idx >> 5;                // 0..63
        int c4 = idx & 31;               // float4 unit along k
        float4 v = *(const float4*)(A + (size_t)(mbase + r) * DD + c4 * 4);
        __half2 h0 = __floats2half2_rn(v.x, v.y);
        __half2 h1 = __floats2half2_rn(v.z, v.w);
        uint2 pk = make_uint2(*(unsigned*)&h0, *(unsigned*)&h1);
        *(uint2*)(sAh + r * 136 + c4 * 4) = pk;
    }

    // Wait for wprep's WT to be complete + visible
    cudaGridDependencySynchronize();

    float acc[2][8][4] = {};

    for (int k0 = 0; k0 < DD; k0 += 128) {
        // W chunk: 256 n-rows x 128 k halves via cp.async (16 x 16B per row)
        #pragma unroll
        for (int it = 0; it < 16; it++) {
            int idx = tid + it * 256;        // 0..4095
            int r = idx >> 4;                // 0..255
            int c16 = idx & 15;              // 16-byte chunk (8 halves)
            cpa16(sWu + (unsigned)(r * 136 + c16 * 8) * 2,
                  WT + (size_t)r * DD + k0 + c16 * 8);
        }
        cpa_commit();
        // A chunk: 64 rows x 128 k, fp32 -> half in-register (chunk 0 prefilled)
        if (k0 > 0) {
            #pragma unroll
            for (int it = 0; it < 8; it++) {
                int idx = tid + it * 256;        // 0..2047
                int r = idx >> 5;                // 0..63
                int c4 = idx & 31;               // float4 unit along k
                float4 v = *(const float4*)(A + (size_t)(mbase + r) * DD + k0 + c4 * 4);
                __half2 h0 = __floats2half2_rn(v.x, v.y);
                __half2 h1 = __floats2half2_rn(v.z, v.w);
                uint2 pk = make_uint2(*(unsigned*)&h0, *(unsigned*)&h1);
                *(uint2*)(sAh + r * 136 + c4 * 4) = pk;
            }
        }
        cpa_wait0();
        __syncthreads();

        #pragma unroll
        for (int ks = 0; ks < 8; ks++) {
            unsigned b0[8], b1[8];
            #pragma unroll
            for (int ng = 0; ng < 8; ng++) {
                const __half* p = sWh + (nb + 8 * ng + lq) * 136 + ks * 16 + 2 * lr;
                b0[ng] = *(const unsigned*)p;
                b1[ng] = *(const unsigned*)(p + 8);
            }
            #pragma unroll
            for (int rg = 0; rg < 2; rg++) {
                const __half* p = sAh + (rbase + 16 * rg + lq) * 136 + ks * 16 + 2 * lr;
                unsigned a0 = *(const unsigned*)p;
                unsigned a1 = *(const unsigned*)(p + 8 * 136);
                unsigned a2 = *(const unsigned*)(p + 8);
                unsigned a3 = *(const unsigned*)(p + 8 * 136 + 8);
                #pragma unroll
                for (int ng = 0; ng < 8; ng++)
                    mma16(acc[rg][ng], a0, a1, a2, a3, b0[ng], b1[ng]);
            }
        }
        __syncthreads();
    }

    // bias
    #pragma unroll
    for (int rg = 0; rg < 2; rg++)
        #pragma unroll
        for (int ng = 0; ng < 8; ng++) {
            int col = nb + 8 * ng + 2 * lr;
            float c0 = sbias[col], c1 = sbias[col + 1];
            acc[rg][ng][0] += c0; acc[rg][ng][1] += c1;
            acc[rg][ng][2] += c0; acc[rg][ng][3] += c1;
        }

    if (!do_norm) {
        #pragma unroll
        for (int rg = 0; rg < 2; rg++) {
            int r0 = rbase + 16 * rg + lq;
            #pragma unroll
            for (int ng = 0; ng < 8; ng++) {
                int col = nb + 8 * ng + 2 * lr;
                *(float2*)(Cf + (size_t)r0 * EE + col) =
                    make_float2(acc[rg][ng][0], acc[rg][ng][1]);
                *(float2*)(Cf + (size_t)(r0 + 8) * EE + col) =
                    make_float2(acc[rg][ng][2], acc[rg][ng][3]);
            }
        }
        return;
    }

    // l2norm: per-row sum of squares
    #pragma unroll
    for (int rg = 0; rg < 2; rg++) {
        float s0 = 0.f, s1 = 0.f;
        #pragma unroll
        for (int ng = 0; ng < 8; ng++) {
            s0 += acc[rg][ng][0] * acc[rg][ng][0] + acc[rg][ng][1] * acc[rg][ng][1];
            s1 += acc[rg][ng][2] * acc[rg][ng][2] + acc[rg][ng][3] * acc[rg][ng][3];
        }
        s0 += __shfl_xor_sync(0xffffffffu, s0, 1);
        s0 += __shfl_xor_sync(0xffffffffu, s0, 2);
        s1 += __shfl_xor_sync(0xffffffffu, s1, 1);
        s1 += __shfl_xor_sync(0xffffffffu, s1, 2);
        if (lr == 0) {
            rowsq[(rbase + 16 * rg + lq) * 5 + nw] = s0;
            rowsq[(rbase + 16 * rg + lq + 8) * 5 + nw] = s1;
        }
    }
    __syncthreads();
    if (tid < 64) {
        float s = rowsq[tid * 5] + rowsq[tid * 5 + 1] + rowsq[tid * 5 + 2] + rowsq[tid * 5 + 3];
        sinv[tid] = 1.0f / fmaxf(sqrtf(s), 1e-12f);
    }
    __syncthreads();

    #pragma unroll
    for (int rg = 0; rg < 2; rg++) {
        int r0 = rbase + 16 * rg + lq;
        float inv0 = sinv[r0], inv1 = sinv[r0 + 8];
        #pragma unroll
        for (int ng = 0; ng < 8; ng++) {
            int col = nb + 8 * ng + 2 * lr;
            __half2 h0 = __floats2half2_rn(acc[rg][ng][0] * inv0, acc[rg][ng][1] * inv0);
            __half2 h1 = __floats2half2_rn(acc[rg][ng][2] * inv1, acc[rg][ng][3] * inv1);
            *(__half2*)(C + (size_t)(mbase + r0) * EE + col) = h0;
            *(__half2*)(C + (size_t)(mbase + r0 + 8) * EE + col) = h1;
        }
    }
}

// ---------------------------------------------------------------------------
// Fused sim kernel (fp16 MMA m16n8k16, f32 accum).
// grid = (qpair=32, b=64), 256 threads (8 warps = 4 v-groups x 2 t-groups).
// PDL: grid-dep-syncs on proj before touching vtok/ttok. Block tile
// 128v x 128t; sT resident for K=256; sV streamed as 4 chunks with
// lookahead cp.async; m16 padding elision (rows issued 208 of 197 valid).
// ---------------------------------------------------------------------------
#define SVS 136
#define STS 264

__global__ __launch_bounds__(256, 2) void sim_kernel(
    const __half* __restrict__ vtok, const __half* __restrict__ ttok,
    const int* __restrict__ text_length, float* __restrict__ out)
{
    extern __shared__ __half smh[];
    __half* sV = smh;                  // 128 x SVS
    __half* sT = smh + 128 * SVS;      // 128 x STS (full K)

    __shared__ float t2i_part[4][128];
    __shared__ float t2i_run[128];
    __shared__ float wsum[8];

    const int tid = threadIdx.x;
    const int lane = tid & 31, w = tid >> 5;
    const int lq = lane >> 2, lr = lane & 3;
    const int vb = (w >> 1) * 32;
    const int tb = (w & 1) * 64;
    const int qp = blockIdx.x, b = blockIdx.y;

    const __half* vbase = vtok + (size_t)b * VV * EE;
    const __half* tbase = ttok + (size_t)(qp * 2) * LL * EE;

    unsigned sVu = (unsigned)__cvta_generic_to_shared(sV);
    unsigned sTu = (unsigned)__cvta_generic_to_shared(sT);

    // Wait for proj's vtok/ttok to be complete + visible
    cudaGridDependencySynchronize();

    // sT: full 128 t-rows x 256 k (once per block) + sV chunk 0
    #pragma unroll
    for (int it = 0; it < 16; it++) {
        int idx = tid + it * 256;
        int r = idx >> 5;
        int c8 = idx & 31;
        cpa16(sTu + (unsigned)(r * STS + c8 * 8) * 2, tbase + (size_t)r * EE + c8 * 8);
    }
    #pragma unroll
    for (int it = 0; it < 8; it++) {
        int idx = tid + it * 256;
        int r = idx >> 4;
        int c8 = idx & 15;
        int vr = min(r, VV - 1);
        cpa16(sVu + (unsigned)(r * SVS + c8 * 8) * 2,
              vbase + (size_t)vr * EE + c8 * 8);
    }
    cpa_commit();

    float i2t_wsum = 0.0f;
    float acc[2][8][4];

    #pragma unroll
    for (int c = 0; c < 4; ++c) {
        const int pass = c >> 1, kc = c & 1;
        const int v0 = pass * 128;
        const bool active = (v0 + vb) < VV;
        const bool rgok0 = (v0 + vb) < VV;
        const bool rgok1 = (v0 + vb + 16) < VV;

        if (kc == 0) {
            #pragma unroll
            for (int rg = 0; rg < 2; rg++)
                #pragma unroll
                for (int ng = 0; ng < 8; ng++)
                    #pragma unroll
                    for (int j = 0; j < 4; j++) acc[rg][ng][j] = 0.0f;
        }

        cpa_wait0();
        __syncthreads();

        if (active) {
            #pragma unroll
            for (int ks = 0; ks < 8; ks++) {
                unsigned b0[8], b1[8];
                #pragma unroll
                for (int ng = 0; ng < 8; ng++) {
                    const __half* p = sT + (tb + 8 * ng + lq) * STS + kc * 128 + ks * 16 + 2 * lr;
                    b0[ng] = *(const unsigned*)p;
                    b1[ng] = *(const unsigned*)(p + 8);
                }
                #pragma unroll
                for (int rg = 0; rg < 2; rg++) {
                    if (rg == 0 ? rgok0 : rgok1) {
                        const __half* p = sV + (vb + 16 * rg + lq) * SVS + ks * 16 + 2 * lr;
                        unsigned a0 = *(const unsigned*)p;
                        unsigned a1 = *(const unsigned*)(p + 8 * SVS);
                        unsigned a2 = *(const unsigned*)(p + 8);
                        unsigned a3 = *(const unsigned*)(p + 8 * SVS + 8);
                        #pragma unroll
                        for (int ng = 0; ng < 8; ng++)
                            mma16(acc[rg][ng], a0, a1, a2, a3, b0[ng], b1[ng]);
                    }
                }
            }
        }
        __syncthreads();   // MMAs done block-wide -> sV free for next chunk

        // lookahead: issue next chunk's sV loads
        if (c < 3) {
            const int nc = c + 1;
            const int np = nc >> 1, nkc = nc & 1;
            const int nv0 = np * 128;
            const int itmax = (np == 0) ? 8 : 5;
            for (int it = 0; it < itmax; it++) {
                int idx = tid + it * 256;
                int r = idx >> 4;
                int c8 = idx & 15;
                int vr = min(nv0 + r, VV - 1);
                cpa16(sVu + (unsigned)(r * SVS + c8 * 8) * 2,
                      vbase + (size_t)vr * EE + nkc * 128 + c8 * 8);
            }
            cpa_commit();
        }

        if (kc == 1) {
            // ---- i2t: per-v-row max over this warp's 64 t cols ----
            float rsum = 0.0f;
            #pragma unroll
            for (int rg = 0; rg < 2; rg++) {
                float m0 = -1e30f, m1 = -1e30f;
                #pragma unroll
                for (int ng = 0; ng < 8; ng++) {
                    m0 = fmaxf(m0, fmaxf(acc[rg][ng][0], acc[rg][ng][1]));
                    m1 = fmaxf(m1, fmaxf(acc[rg][ng][2], acc[rg][ng][3]));
                }
                m0 = fmaxf(m0, __shfl_xor_sync(0xffffffffu, m0, 1));
                m0 = fmaxf(m0, __shfl_xor_sync(0xffffffffu, m0, 2));
                m1 = fmaxf(m1, __shfl_xor_sync(0xffffffffu, m1, 1));
                m1 = fmaxf(m1, __shfl_xor_sync(0xffffffffu, m1, 2));
                int r0 = v0 + vb + 16 * rg + lq;
                if (lr == 0) {
                    if (r0 < VV) rsum += m0;
                    if (r0 + 8 < VV) rsum += m1;
                }
            }
            #pragma unroll
            for (int off = 16; off > 0; off >>= 1)
                rsum += __shfl_xor_sync(0xffffffffu, rsum, off);
            i2t_wsum += rsum;

            // ---- t2i: per-t-col max over this warp's 32 v rows (masked) ----
            #pragma unroll
            for (int ng = 0; ng < 8; ng++) {
                float m0 = -1e30f, m1 = -1e30f;
                #pragma unroll
                for (int rg = 0; rg < 2; rg++) {
                    int r0 = v0 + vb + 16 * rg + lq;
                    if (r0 < VV) {
                        m0 = fmaxf(m0, acc[rg][ng][0]);
                        m1 = fmaxf(m1, acc[rg][ng][1]);
                    }
                    if (r0 + 8 < VV) {
                        m0 = fmaxf(m0, acc[rg][ng][2]);
                        m1 = fmaxf(m1, acc[rg][ng][3]);
                    }
                }
                m0 = fmaxf(m0, __shfl_xor_sync(0xffffffffu, m0, 4));
                m0 = fmaxf(m0, __shfl_xor_sync(0xffffffffu, m0, 8));
                m0 = fmaxf(m0, __shfl_xor_sync(0xffffffffu, m0, 16));
                m1 = fmaxf(m1, __shfl_xor_sync(0xffffffffu, m1, 4));
                m1 = fmaxf(m1, __shfl_xor_sync(0xffffffffu, m1, 8));
                m1 = fmaxf(m1, __shfl_xor_sync(0xffffffffu, m1, 16));
                if (lane < 4) {
                    t2i_part[w >> 1][tb + 8 * ng + 2 * lane] = m0;
                    t2i_part[w >> 1][tb + 8 * ng + 2 * lane + 1] = m1;
                }
            }
            __syncthreads();
            if (tid < 128) {
                float m = fmaxf(fmaxf(t2i_part[0][tid], t2i_part[1][tid]),
                                fmaxf(t2i_part[2][tid], t2i_part[3][tid]));
                t2i_run[tid] = (v0 == 0) ? m : fmaxf(t2i_run[tid], m);
            }
            __syncthreads();
        }
    }

    if (lane == 0) wsum[w] = i2t_wsum;
    __syncthreads();

    // t2i outputs: warp 0 -> q0, warp 1 -> q1
    if (tid < 64) {
        int w2 = tid >> 5;
        int l2 = tid & 31;
        int len = text_length[b];   // reference quirk: indexed by b
        float s = 0.0f;
        if (l2 < len) s += t2i_run[w2 * 64 + l2];
        if (l2 + 32 < len) s += t2i_run[w2 * 64 + l2 + 32];
        #pragma unroll
        for (int off = 16; off > 0; off >>= 1)
            s += __shfl_xor_sync(0xffffffffu, s, off);
        if (l2 == 0)
            out[36864 + b * 64 + qp * 2 + w2] = s / fmaxf((float)len, 1e-6f);
    }
    // i2t outputs
    if (tid == 128 || tid == 129) {
        int j = tid - 128;
        float s = wsum[j] + wsum[j + 2] + wsum[j + 4] + wsum[j + 6];
        out[32768 + b * 64 + qp * 2 + j] = s / (float)VV;
    }
}

// ---------------------------------------------------------------------------
extern "C" void kernel_launch(void* const* d_in, const int* in_sizes, int n_in,
                              void* d_out, int out_size)
{
    const float* visual_cls     = (const float*)d_in[0];
    const float* textual_cls    = (const float*)d_in[1];
    const float* visual_tokens  = (const float*)d_in[2];
    const float* textual_tokens = (const float*)d_in[3];
    const int*   text_length    = (const int*)  d_in[4];
    const float* Wv  = (const float*)d_in[5];
    const float* bv  = (const float*)d_in[6];
    const float* Wt  = (const float*)d_in[7];
    const float* bt  = (const float*)d_in[8];
    const float* Wvt = (const float*)d_in[9];
    const float* bvt = (const float*)d_in[10];
    const float* Wtt = (const float*)d_in[11];
    const float* btt = (const float*)d_in[12];
    float* out = (float*)d_out;

    __half *vtok, *ttok, *wvtT, *wttT, *wvT, *wtT;
    cudaGetSymbolAddress((void**)&vtok, g_vtok);
    cudaGetSymbolAddress((void**)&ttok, g_ttok);
    cudaGetSymbolAddress((void**)&wvtT, g_wvtT);
    cudaGetSymbolAddress((void**)&wttT, g_wttT);
    cudaGetSymbolAddress((void**)&wvT, g_wvT);
    cudaGetSymbolAddress((void**)&wtT, g_wtT);

    const int proj_smem = (64 * 136 + 256 * 136) * sizeof(__half);        // 87040
    const int sim_smem  = (128 * SVS + 128 * STS) * sizeof(__half);       // 102400
    cudaFuncSetAttribute(proj_kernel, cudaFuncAttributeMaxDynamicSharedMemorySize, proj_smem);
    cudaFuncSetAttribute(sim_kernel,  cudaFuncAttributeMaxDynamicSharedMemorySize, sim_smem);

    wprep_kernel<<<dim3(24, 8, 4), dim3(32, 8)>>>(Wvt, Wtt, Wv, Wt, wvtT, wttT, wvT, wtT);

    // proj: programmatic dependent launch on wprep
    {
        cudaLaunchAttribute attr[1];
        attr[0].id = cudaLaunchAttributeProgrammaticStreamSerialization;
        attr[0].val.programmaticStreamSerializationAllowed = 1;
        cudaLaunchConfig_t cfg = {};
        cfg.gridDim = dim3(263, 1, 1);
        cfg.blockDim = dim3(256, 1, 1);
        cfg.dynamicSmemBytes = proj_smem;
        cfg.stream = 0;
        cfg.attrs = attr;
        cfg.numAttrs = 1;
        cudaLaunchKernelEx(&cfg, proj_kernel,
            visual_cls, textual_cls, visual_tokens, textual_tokens,
            bv, bt, bvt, btt,
            (const __half*)wvtT, (const __half*)wttT,
            (const __half*)wvT, (const __half*)wtT,
            out, vtok, ttok);
    }

    // sim: programmatic dependent launch on proj
    {
        cudaLaunchAttribute attr[1];
        attr[0].id = cudaLaunchAttributeProgrammaticStreamSerialization;
        attr[0].val.programmaticStreamSerializationAllowed = 1;
        cudaLaunchConfig_t cfg = {};
        cfg.gridDim = dim3(32, 64, 1);
        cfg.blockDim = dim3(256, 1, 1);
        cfg.dynamicSmemBytes = sim_smem;
        cfg.stream = 0;
        cfg.attrs = attr;
        cfg.numAttrs = 1;
        cudaLaunchKernelEx(&cfg, sim_kernel,
            (const __half*)vtok, (const __half*)ttok, text_length, out);
    }
}